// round 2
// baseline (speedup 1.0000x reference)
#include <cuda_runtime.h>
#include <math.h>

#define Bsz  4
#define Nseq 1024
#define Dmod 768
#define Hh   12
#define DHd  64
#define HID  3072
#define ROWS (Bsz*Nseq)   // 4096

// ---- scratch (no cudaMalloc allowed) ----
__device__ float g_h   [ROWS*Dmod];
__device__ float g_qkv [ROWS*3*Dmod];
__device__ float g_attn[ROWS*Dmod];
__device__ float g_x1  [ROWS*Dmod];
__device__ float g_h2  [ROWS*Dmod];
__device__ float g_act [ROWS*HID];

// ---------------- LayerNorm: one block per row ----------------
__global__ __launch_bounds__(256) void ln_kernel(
    const float* __restrict__ x, const float* __restrict__ g,
    const float* __restrict__ b, float* __restrict__ out)
{
    int row = blockIdx.x;
    const float* xr = x + (size_t)row * Dmod;
    float v[3];
    float s = 0.f, s2 = 0.f;
#pragma unroll
    for (int it = 0; it < 3; it++) {
        v[it] = xr[threadIdx.x + it*256];
        s += v[it]; s2 += v[it]*v[it];
    }
#pragma unroll
    for (int off = 16; off; off >>= 1) {
        s  += __shfl_xor_sync(0xffffffffu, s,  off);
        s2 += __shfl_xor_sync(0xffffffffu, s2, off);
    }
    __shared__ float ws[8], ws2[8];
    __shared__ float mu_s, rs_s;
    int wid = threadIdx.x >> 5, lane = threadIdx.x & 31;
    if (lane == 0) { ws[wid] = s; ws2[wid] = s2; }
    __syncthreads();
    if (threadIdx.x == 0) {
        float S = 0.f, S2 = 0.f;
#pragma unroll
        for (int i = 0; i < 8; i++) { S += ws[i]; S2 += ws2[i]; }
        float mu  = S * (1.f/Dmod);
        float var = S2 * (1.f/Dmod) - mu*mu;
        mu_s = mu;
        rs_s = rsqrtf(var + 1e-6f);
    }
    __syncthreads();
    float mu = mu_s, rs = rs_s;
#pragma unroll
    for (int it = 0; it < 3; it++) {
        int i = threadIdx.x + it*256;
        out[(size_t)row*Dmod + i] = (v[it]-mu)*rs*g[i] + b[i];
    }
}

// ---------------- SGEMM 128x128x8, 8x8 microtile ----------------
// C[M,Nc] = A[M,K] @ W[K,Nc] + bias (+ optional GELU, + optional residual)
template<bool GELU, bool RES>
__global__ __launch_bounds__(256) void gemm128(
    const float* __restrict__ A, const float* __restrict__ W,
    const float* __restrict__ bias, const float* __restrict__ res,
    float* __restrict__ C, int M, int K, int Nc)
{
    __shared__ float As[8][128];
    __shared__ float Bs[8][128];
    const int tid = threadIdx.x;
    const int tx = tid & 15, ty = tid >> 4;
    const int bm = blockIdx.y * 128, bn = blockIdx.x * 128;

    const int arow = tid >> 1;          // 0..127
    const int akk  = (tid & 1) * 4;     // 0 or 4
    const int brow = tid >> 5;          // 0..7
    const int bcol = (tid & 31) * 4;    // 0..124

    const float* Aptr = A + (size_t)(bm + arow) * K + akk;
    const float* Wptr = W + (size_t)brow * Nc + bn + bcol;

    float acc[8][8] = {};

    for (int k0 = 0; k0 < K; k0 += 8) {
        float4 av = *(const float4*)(Aptr + k0);
        As[akk+0][arow] = av.x;
        As[akk+1][arow] = av.y;
        As[akk+2][arow] = av.z;
        As[akk+3][arow] = av.w;
        *(float4*)&Bs[brow][bcol] = *(const float4*)(Wptr + (size_t)k0 * Nc);
        __syncthreads();
#pragma unroll
        for (int kk = 0; kk < 8; kk++) {
            float a[8], b[8];
            *(float4*)(a  ) = *(const float4*)&As[kk][ty*8];
            *(float4*)(a+4) = *(const float4*)&As[kk][ty*8+4];
            *(float4*)(b  ) = *(const float4*)&Bs[kk][tx*8];
            *(float4*)(b+4) = *(const float4*)&Bs[kk][tx*8+4];
#pragma unroll
            for (int i = 0; i < 8; i++)
#pragma unroll
                for (int j = 0; j < 8; j++)
                    acc[i][j] = fmaf(a[i], b[j], acc[i][j]);
        }
        __syncthreads();
    }
#pragma unroll
    for (int i = 0; i < 8; i++) {
        int row = bm + ty*8 + i;
#pragma unroll
        for (int j = 0; j < 8; j++) {
            int col = bn + tx*8 + j;
            float v = acc[i][j] + bias[col];
            if (GELU) v = v * normcdff(v);          // exact gelu: x*Phi(x)
            if (RES)  v += res[(size_t)row*Nc + col];
            C[(size_t)row*Nc + col] = v;
        }
    }
}

// ---------------- Flash attention with additive adjacency bias ----------------
// grid: (Nseq/64, B*H), block 256. Q-tile 64 rows, K-tiles of 64, DH=64.
__global__ __launch_bounds__(256) void attn_kernel(
    const float* __restrict__ qkv, const float* __restrict__ adj,
    float* __restrict__ out)
{
    extern __shared__ float sm[];
    float* Qs = sm;              // [64][64]
    float* KP = sm + 64*64;      // [64][65]  K tile, reused as P tile
    float* Vs = KP + 64*65;      // [64][65]
    const int tid = threadIdx.x;
    const int tx = tid & 15, ty = tid >> 4;
    const int bh = blockIdx.y;
    const int b  = bh / Hh, h = bh % Hh;
    const int q0 = blockIdx.x * 64;
    const float scale = 0.125f;  // DH^-0.5

    // load Q tile
#pragma unroll
    for (int it = 0; it < 16; it++) {
        int idx = tid + it*256;
        int r = idx >> 6, d = idx & 63;
        Qs[r*64 + d] = qkv[(size_t)(b*Nseq + q0 + r) * (3*Dmod) + h*DHd + d];
    }
    float m_run[4], l_run[4], o[4][4];
#pragma unroll
    for (int i = 0; i < 4; i++) {
        m_run[i] = -1e30f; l_run[i] = 0.f;
#pragma unroll
        for (int j = 0; j < 4; j++) o[i][j] = 0.f;
    }
    __syncthreads();

    for (int kt = 0; kt < Nseq/64; kt++) {
        int k0 = kt*64;
        // load K and V tiles
#pragma unroll
        for (int it = 0; it < 16; it++) {
            int idx = tid + it*256;
            int r = idx >> 6, d = idx & 63;
            size_t base = (size_t)(b*Nseq + k0 + r) * (3*Dmod) + h*DHd + d;
            KP[r*65 + d] = qkv[base +   Dmod];
            Vs[r*65 + d] = qkv[base + 2*Dmod];
        }
        __syncthreads();
        // S = Q K^T
        float s[4][4] = {};
#pragma unroll
        for (int d = 0; d < 64; d++) {
            float a[4], bb[4];
#pragma unroll
            for (int i = 0; i < 4; i++) a[i]  = Qs[(ty*4+i)*64 + d];
#pragma unroll
            for (int j = 0; j < 4; j++) bb[j] = KP[(tx*4+j)*65 + d];
#pragma unroll
            for (int i = 0; i < 4; i++)
#pragma unroll
                for (int j = 0; j < 4; j++)
                    s[i][j] = fmaf(a[i], bb[j], s[i][j]);
        }
        // scale + adjacency bias
#pragma unroll
        for (int i = 0; i < 4; i++) {
            int qg = q0 + ty*4 + i;
#pragma unroll
            for (int j = 0; j < 4; j++)
                s[i][j] = s[i][j]*scale + adj[(size_t)qg*Nseq + k0 + tx*4 + j];
        }
        __syncthreads();   // done reading K tile; KP will hold P

        // online softmax (row stats shared by 16 lanes with same ty)
#pragma unroll
        for (int i = 0; i < 4; i++) {
            float mx = fmaxf(fmaxf(s[i][0], s[i][1]), fmaxf(s[i][2], s[i][3]));
#pragma unroll
            for (int off = 8; off; off >>= 1)
                mx = fmaxf(mx, __shfl_xor_sync(0xffffffffu, mx, off, 16));
            float mnew  = fmaxf(m_run[i], mx);
            float alpha = __expf(m_run[i] - mnew);
            float rs = 0.f;
#pragma unroll
            for (int j = 0; j < 4; j++) { s[i][j] = __expf(s[i][j] - mnew); rs += s[i][j]; }
#pragma unroll
            for (int off = 8; off; off >>= 1)
                rs += __shfl_xor_sync(0xffffffffu, rs, off, 16);
            l_run[i] = l_run[i]*alpha + rs;
            m_run[i] = mnew;
#pragma unroll
            for (int j = 0; j < 4; j++) o[i][j] *= alpha;
#pragma unroll
            for (int j = 0; j < 4; j++) KP[(ty*4+i)*65 + tx*4+j] = s[i][j];
        }
        __syncthreads();
        // O += P @ V
#pragma unroll
        for (int kk = 0; kk < 64; kk++) {
            float a[4], bb[4];
#pragma unroll
            for (int i = 0; i < 4; i++) a[i]  = KP[(ty*4+i)*65 + kk];
#pragma unroll
            for (int j = 0; j < 4; j++) bb[j] = Vs[kk*65 + tx*4+j];
#pragma unroll
            for (int i = 0; i < 4; i++)
#pragma unroll
                for (int j = 0; j < 4; j++)
                    o[i][j] = fmaf(a[i], bb[j], o[i][j]);
        }
        __syncthreads();
    }
    // write back: attn[b, q, h*64 + d]
#pragma unroll
    for (int i = 0; i < 4; i++) {
        int qg = q0 + ty*4 + i;
        float inv = 1.f / l_run[i];
#pragma unroll
        for (int j = 0; j < 4; j++)
            out[(size_t)(b*Nseq + qg)*Dmod + h*DHd + tx*4 + j] = o[i][j]*inv;
    }
}

// ---------------- launcher ----------------
extern "C" void kernel_launch(void* const* d_in, const int* in_sizes, int n_in,
                              void* d_out, int out_size)
{
    const float* x      = (const float*)d_in[0];
    const float* adj    = (const float*)d_in[1];
    const float* ln1_g  = (const float*)d_in[2];
    const float* ln1_b  = (const float*)d_in[3];
    const float* qkv_w  = (const float*)d_in[4];
    const float* qkv_b  = (const float*)d_in[5];
    const float* proj_w = (const float*)d_in[6];
    const float* proj_b = (const float*)d_in[7];
    const float* ln2_g  = (const float*)d_in[8];
    const float* ln2_b  = (const float*)d_in[9];
    const float* fc1_w  = (const float*)d_in[10];
    const float* fc1_b  = (const float*)d_in[11];
    const float* fc2_w  = (const float*)d_in[12];
    const float* fc2_b  = (const float*)d_in[13];
    float* out = (float*)d_out;

    float *h, *qkv, *attn, *x1, *h2, *act;
    cudaGetSymbolAddress((void**)&h,    g_h);
    cudaGetSymbolAddress((void**)&qkv,  g_qkv);
    cudaGetSymbolAddress((void**)&attn, g_attn);
    cudaGetSymbolAddress((void**)&x1,   g_x1);
    cudaGetSymbolAddress((void**)&h2,   g_h2);
    cudaGetSymbolAddress((void**)&act,  g_act);

    const int attn_smem = (64*64 + 2*64*65) * sizeof(float);  // 49664 B
    cudaFuncSetAttribute(attn_kernel,
                         cudaFuncAttributeMaxDynamicSharedMemorySize, attn_smem);

    // 1. LN1
    ln_kernel<<<ROWS, 256>>>(x, ln1_g, ln1_b, h);
    // 2. qkv = h @ qkv_w + qkv_b           [4096,768] x [768,2304]
    gemm128<false,false><<<dim3(3*Dmod/128, ROWS/128), 256>>>(
        h, qkv_w, qkv_b, nullptr, qkv, ROWS, Dmod, 3*Dmod);
    // 3. attention (flash, with adjacency bias)
    attn_kernel<<<dim3(Nseq/64, Bsz*Hh), 256, attn_smem>>>(qkv, adj, attn);
    // 4. x1 = x + attn @ proj_w + proj_b   [4096,768] x [768,768]
    gemm128<false,true><<<dim3(Dmod/128, ROWS/128), 256>>>(
        attn, proj_w, proj_b, x, x1, ROWS, Dmod, Dmod);
    // 5. LN2
    ln_kernel<<<ROWS, 256>>>(x1, ln2_g, ln2_b, h2);
    // 6. act = gelu(h2 @ fc1_w + fc1_b)    [4096,768] x [768,3072]
    gemm128<true,false><<<dim3(HID/128, ROWS/128), 256>>>(
        h2, fc1_w, fc1_b, nullptr, act, ROWS, Dmod, HID);
    // 7. out = x1 + act @ fc2_w + fc2_b    [4096,3072] x [3072,768]
    gemm128<false,true><<<dim3(Dmod/128, ROWS/128), 256>>>(
        act, fc2_w, fc2_b, x1, out, ROWS, HID, Dmod);
}

// round 3
// speedup vs baseline: 1.9644x; 1.9644x over previous
#include <cuda_runtime.h>
#include <math.h>

#define Bsz  4
#define Nseq 1024
#define Dmod 768
#define Hh   12
#define DHd  64
#define HID  3072
#define ROWS (Bsz*Nseq)   // 4096

// ---- scratch (no cudaMalloc allowed) ----
__device__ float g_h   [ROWS*Dmod];
__device__ float g_qkv [ROWS*3*Dmod];
__device__ float g_attn[ROWS*Dmod];
__device__ float g_x1  [ROWS*Dmod];
__device__ float g_h2  [ROWS*Dmod];
__device__ float g_act [ROWS*HID];

// ---------------- LayerNorm: one block per row ----------------
__global__ __launch_bounds__(256) void ln_kernel(
    const float* __restrict__ x, const float* __restrict__ g,
    const float* __restrict__ b, float* __restrict__ out)
{
    int row = blockIdx.x;
    const float* xr = x + (size_t)row * Dmod;
    float v[3];
    float s = 0.f, s2 = 0.f;
#pragma unroll
    for (int it = 0; it < 3; it++) {
        v[it] = xr[threadIdx.x + it*256];
        s += v[it]; s2 += v[it]*v[it];
    }
#pragma unroll
    for (int off = 16; off; off >>= 1) {
        s  += __shfl_xor_sync(0xffffffffu, s,  off);
        s2 += __shfl_xor_sync(0xffffffffu, s2, off);
    }
    __shared__ float ws[8], ws2[8];
    __shared__ float mu_s, rs_s;
    int wid = threadIdx.x >> 5, lane = threadIdx.x & 31;
    if (lane == 0) { ws[wid] = s; ws2[wid] = s2; }
    __syncthreads();
    if (threadIdx.x == 0) {
        float S = 0.f, S2 = 0.f;
#pragma unroll
        for (int i = 0; i < 8; i++) { S += ws[i]; S2 += ws2[i]; }
        float mu  = S * (1.f/Dmod);
        float var = S2 * (1.f/Dmod) - mu*mu;
        mu_s = mu;
        rs_s = rsqrtf(var + 1e-6f);
    }
    __syncthreads();
    float mu = mu_s, rs = rs_s;
#pragma unroll
    for (int it = 0; it < 3; it++) {
        int i = threadIdx.x + it*256;
        out[(size_t)row*Dmod + i] = (v[it]-mu)*rs*g[i] + b[i];
    }
}

// ---------------- tf32 tensor-core GEMM 128x128x32 ----------------
// C[M,Nc] = A[M,K] @ W[K,Nc] + bias (+ optional GELU, + optional residual)
// 8 warps in 2x4 layout, warp tile 64x32, mma.sync.m16n8k8.tf32.

#define AS_STRIDE 36   // 32 + 4 pad  -> conflict-free a-fragment LDS
#define BS_STRIDE 136  // 128 + 8 pad -> conflict-free b-fragment LDS
#define STAGE_FLOATS (128*AS_STRIDE + 32*BS_STRIDE)

__device__ __forceinline__ unsigned f2tf32(float x) {
    unsigned r;
    asm("cvt.rna.tf32.f32 %0, %1;" : "=r"(r) : "f"(x));
    return r;
}
__device__ __forceinline__ void cp16(unsigned dst, const void* src) {
    asm volatile("cp.async.cg.shared.global [%0], [%1], 16;" :: "r"(dst), "l"(src));
}

template<bool GELU, bool RES>
__global__ __launch_bounds__(256, 2) void gemm_tc(
    const float* __restrict__ A, const float* __restrict__ W,
    const float* __restrict__ bias, const float* __restrict__ res,
    float* __restrict__ C, int M, int K, int Nc)
{
    extern __shared__ float sm[];
    float* As[2] = { sm,                sm + STAGE_FLOATS };
    float* Bs[2] = { sm + 128*AS_STRIDE, sm + STAGE_FLOATS + 128*AS_STRIDE };

    const int tid  = threadIdx.x;
    const int lane = tid & 31;
    const int warp = tid >> 5;
    const int wm   = warp & 1;        // 0..1
    const int wn   = warp >> 1;       // 0..3
    const int bm   = blockIdx.y * 128;
    const int bn   = blockIdx.x * 128;

    // ---- load indexing (4 x 16B chunks each for A and B) ----
    const int a_row = tid >> 1;                 // base pattern: idx = tid + i*256
    // idx: 0..1023 ; row = idx>>3, kk = (idx&7)*4
    // B  : k = idx>>5, n = (idx&31)*4
    float acc[4][4][4];
#pragma unroll
    for (int i = 0; i < 4; i++)
#pragma unroll
        for (int j = 0; j < 4; j++)
#pragma unroll
            for (int r = 0; r < 4; r++) acc[i][j][r] = 0.f;

    const int kTiles = K >> 5;

    auto load_stage = [&](int kt, int buf) {
        const int k0 = kt * 32;
#pragma unroll
        for (int i = 0; i < 4; i++) {
            int idx = tid + i*256;
            int r = idx >> 3, kk = (idx & 7) * 4;
            cp16((unsigned)__cvta_generic_to_shared(&As[buf][r*AS_STRIDE + kk]),
                 A + (size_t)(bm + r) * K + k0 + kk);
        }
#pragma unroll
        for (int i = 0; i < 4; i++) {
            int idx = tid + i*256;
            int kr = idx >> 5, n = (idx & 31) * 4;
            cp16((unsigned)__cvta_generic_to_shared(&Bs[buf][kr*BS_STRIDE + n]),
                 W + (size_t)(k0 + kr) * Nc + bn + n);
        }
        asm volatile("cp.async.commit_group;");
    };

    load_stage(0, 0);

    const int r8 = lane >> 2;     // 0..7
    const int c4 = lane & 3;      // 0..3

    for (int kt = 0; kt < kTiles; kt++) {
        if (kt + 1 < kTiles) load_stage(kt + 1, (kt + 1) & 1);
        if (kt + 1 < kTiles) asm volatile("cp.async.wait_group 1;");
        else                 asm volatile("cp.async.wait_group 0;");
        __syncthreads();

        const float* as = As[kt & 1];
        const float* bs = Bs[kt & 1];
#pragma unroll
        for (int k8 = 0; k8 < 4; k8++) {
            const int kb = k8 * 8;
            unsigned af[4][4], bf[4][2];
#pragma unroll
            for (int mt = 0; mt < 4; mt++) {
                int row = wm*64 + mt*16 + r8;
                int col = kb + c4;
                af[mt][0] = f2tf32(as[ row     *AS_STRIDE + col    ]);
                af[mt][1] = f2tf32(as[(row + 8)*AS_STRIDE + col    ]);
                af[mt][2] = f2tf32(as[ row     *AS_STRIDE + col + 4]);
                af[mt][3] = f2tf32(as[(row + 8)*AS_STRIDE + col + 4]);
            }
#pragma unroll
            for (int nt = 0; nt < 4; nt++) {
                int col = wn*32 + nt*8 + r8;
                int krow = kb + c4;
                bf[nt][0] = f2tf32(bs[ krow     *BS_STRIDE + col]);
                bf[nt][1] = f2tf32(bs[(krow + 4)*BS_STRIDE + col]);
            }
#pragma unroll
            for (int mt = 0; mt < 4; mt++)
#pragma unroll
                for (int nt = 0; nt < 4; nt++) {
                    asm volatile(
                        "mma.sync.aligned.m16n8k8.row.col.f32.tf32.tf32.f32 "
                        "{%0,%1,%2,%3}, {%4,%5,%6,%7}, {%8,%9}, {%0,%1,%2,%3};"
                        : "+f"(acc[mt][nt][0]), "+f"(acc[mt][nt][1]),
                          "+f"(acc[mt][nt][2]), "+f"(acc[mt][nt][3])
                        : "r"(af[mt][0]), "r"(af[mt][1]),
                          "r"(af[mt][2]), "r"(af[mt][3]),
                          "r"(bf[nt][0]), "r"(bf[nt][1]));
                }
        }
        __syncthreads();
    }

    // ---- epilogue ----
#pragma unroll
    for (int mt = 0; mt < 4; mt++) {
        int row0 = bm + wm*64 + mt*16 + r8;
#pragma unroll
        for (int nt = 0; nt < 4; nt++) {
            int col0 = bn + wn*32 + nt*8 + c4*2;
            float b0 = bias[col0], b1 = bias[col0 + 1];
#pragma unroll
            for (int half = 0; half < 2; half++) {
                int row = row0 + half*8;
                float v0 = acc[mt][nt][half*2 + 0] + b0;
                float v1 = acc[mt][nt][half*2 + 1] + b1;
                if (GELU) { v0 = v0 * normcdff(v0); v1 = v1 * normcdff(v1); }
                if (RES) {
                    const float2 rr = *(const float2*)&res[(size_t)row*Nc + col0];
                    v0 += rr.x; v1 += rr.y;
                }
                *(float2*)&C[(size_t)row*Nc + col0] = make_float2(v0, v1);
            }
        }
    }
}

// ---------------- Flash attention with additive adjacency bias ----------------
__global__ __launch_bounds__(256) void attn_kernel(
    const float* __restrict__ qkv, const float* __restrict__ adj,
    float* __restrict__ out)
{
    extern __shared__ float smf[];
    float* Qs = smf;             // [64][64]
    float* KP = smf + 64*64;     // [64][65]
    float* Vs = KP + 64*65;      // [64][65]
    const int tid = threadIdx.x;
    const int tx = tid & 15, ty = tid >> 4;
    const int bh = blockIdx.y;
    const int b  = bh / Hh, h = bh % Hh;
    const int q0 = blockIdx.x * 64;
    const float scale = 0.125f;

#pragma unroll
    for (int it = 0; it < 16; it++) {
        int idx = tid + it*256;
        int r = idx >> 6, d = idx & 63;
        Qs[r*64 + d] = qkv[(size_t)(b*Nseq + q0 + r) * (3*Dmod) + h*DHd + d];
    }
    float m_run[4], l_run[4], o[4][4];
#pragma unroll
    for (int i = 0; i < 4; i++) {
        m_run[i] = -1e30f; l_run[i] = 0.f;
#pragma unroll
        for (int j = 0; j < 4; j++) o[i][j] = 0.f;
    }
    __syncthreads();

    for (int kt = 0; kt < Nseq/64; kt++) {
        int k0 = kt*64;
#pragma unroll
        for (int it = 0; it < 16; it++) {
            int idx = tid + it*256;
            int r = idx >> 6, d = idx & 63;
            size_t base = (size_t)(b*Nseq + k0 + r) * (3*Dmod) + h*DHd + d;
            KP[r*65 + d] = qkv[base +   Dmod];
            Vs[r*65 + d] = qkv[base + 2*Dmod];
        }
        __syncthreads();
        float s[4][4] = {};
#pragma unroll
        for (int d = 0; d < 64; d++) {
            float a[4], bb[4];
#pragma unroll
            for (int i = 0; i < 4; i++) a[i]  = Qs[(ty*4+i)*64 + d];
#pragma unroll
            for (int j = 0; j < 4; j++) bb[j] = KP[(tx*4+j)*65 + d];
#pragma unroll
            for (int i = 0; i < 4; i++)
#pragma unroll
                for (int j = 0; j < 4; j++)
                    s[i][j] = fmaf(a[i], bb[j], s[i][j]);
        }
#pragma unroll
        for (int i = 0; i < 4; i++) {
            int qg = q0 + ty*4 + i;
#pragma unroll
            for (int j = 0; j < 4; j++)
                s[i][j] = s[i][j]*scale + adj[(size_t)qg*Nseq + k0 + tx*4 + j];
        }
        __syncthreads();

#pragma unroll
        for (int i = 0; i < 4; i++) {
            float mx = fmaxf(fmaxf(s[i][0], s[i][1]), fmaxf(s[i][2], s[i][3]));
#pragma unroll
            for (int off = 8; off; off >>= 1)
                mx = fmaxf(mx, __shfl_xor_sync(0xffffffffu, mx, off, 16));
            float mnew  = fmaxf(m_run[i], mx);
            float alpha = __expf(m_run[i] - mnew);
            float rs = 0.f;
#pragma unroll
            for (int j = 0; j < 4; j++) { s[i][j] = __expf(s[i][j] - mnew); rs += s[i][j]; }
#pragma unroll
            for (int off = 8; off; off >>= 1)
                rs += __shfl_xor_sync(0xffffffffu, rs, off, 16);
            l_run[i] = l_run[i]*alpha + rs;
            m_run[i] = mnew;
#pragma unroll
            for (int j = 0; j < 4; j++) o[i][j] *= alpha;
#pragma unroll
            for (int j = 0; j < 4; j++) KP[(ty*4+i)*65 + tx*4+j] = s[i][j];
        }
        __syncthreads();
#pragma unroll
        for (int kk = 0; kk < 64; kk++) {
            float a[4], bb[4];
#pragma unroll
            for (int i = 0; i < 4; i++) a[i]  = KP[(ty*4+i)*65 + kk];
#pragma unroll
            for (int j = 0; j < 4; j++) bb[j] = Vs[kk*65 + tx*4+j];
#pragma unroll
            for (int i = 0; i < 4; i++)
#pragma unroll
                for (int j = 0; j < 4; j++)
                    o[i][j] = fmaf(a[i], bb[j], o[i][j]);
        }
        __syncthreads();
    }
#pragma unroll
    for (int i = 0; i < 4; i++) {
        int qg = q0 + ty*4 + i;
        float inv = 1.f / l_run[i];
#pragma unroll
        for (int j = 0; j < 4; j++)
            out[(size_t)(b*Nseq + qg)*Dmod + h*DHd + tx*4 + j] = o[i][j]*inv;
    }
}

// ---------------- launcher ----------------
extern "C" void kernel_launch(void* const* d_in, const int* in_sizes, int n_in,
                              void* d_out, int out_size)
{
    const float* x      = (const float*)d_in[0];
    const float* adj    = (const float*)d_in[1];
    const float* ln1_g  = (const float*)d_in[2];
    const float* ln1_b  = (const float*)d_in[3];
    const float* qkv_w  = (const float*)d_in[4];
    const float* qkv_b  = (const float*)d_in[5];
    const float* proj_w = (const float*)d_in[6];
    const float* proj_b = (const float*)d_in[7];
    const float* ln2_g  = (const float*)d_in[8];
    const float* ln2_b  = (const float*)d_in[9];
    const float* fc1_w  = (const float*)d_in[10];
    const float* fc1_b  = (const float*)d_in[11];
    const float* fc2_w  = (const float*)d_in[12];
    const float* fc2_b  = (const float*)d_in[13];
    float* out = (float*)d_out;

    float *h, *qkv, *attn, *x1, *h2, *act;
    cudaGetSymbolAddress((void**)&h,    g_h);
    cudaGetSymbolAddress((void**)&qkv,  g_qkv);
    cudaGetSymbolAddress((void**)&attn, g_attn);
    cudaGetSymbolAddress((void**)&x1,   g_x1);
    cudaGetSymbolAddress((void**)&h2,   g_h2);
    cudaGetSymbolAddress((void**)&act,  g_act);

    const int gemm_smem = 2 * STAGE_FLOATS * sizeof(float);  // ~71.7 KB
    static int init = 0;
    if (!init) {
        cudaFuncSetAttribute(gemm_tc<false,false>,
            cudaFuncAttributeMaxDynamicSharedMemorySize, gemm_smem);
        cudaFuncSetAttribute(gemm_tc<false,true>,
            cudaFuncAttributeMaxDynamicSharedMemorySize, gemm_smem);
        cudaFuncSetAttribute(gemm_tc<true,false>,
            cudaFuncAttributeMaxDynamicSharedMemorySize, gemm_smem);
        const int attn_smem = (64*64 + 2*64*65) * sizeof(float);
        cudaFuncSetAttribute(attn_kernel,
            cudaFuncAttributeMaxDynamicSharedMemorySize, attn_smem);
        init = 1;
    }
    const int attn_smem = (64*64 + 2*64*65) * sizeof(float);

    // 1. LN1
    ln_kernel<<<ROWS, 256>>>(x, ln1_g, ln1_b, h);
    // 2. qkv = h @ qkv_w + qkv_b
    gemm_tc<false,false><<<dim3(3*Dmod/128, ROWS/128), 256, gemm_smem>>>(
        h, qkv_w, qkv_b, nullptr, qkv, ROWS, Dmod, 3*Dmod);
    // 3. attention
    attn_kernel<<<dim3(Nseq/64, Bsz*Hh), 256, attn_smem>>>(qkv, adj, attn);
    // 4. x1 = x + attn @ proj_w + proj_b
    gemm_tc<false,true><<<dim3(Dmod/128, ROWS/128), 256, gemm_smem>>>(
        attn, proj_w, proj_b, x, x1, ROWS, Dmod, Dmod);
    // 5. LN2
    ln_kernel<<<ROWS, 256>>>(x1, ln2_g, ln2_b, h2);
    // 6. act = gelu(h2 @ fc1_w + fc1_b)
    gemm_tc<true,false><<<dim3(HID/128, ROWS/128), 256, gemm_smem>>>(
        h2, fc1_w, fc1_b, nullptr, act, ROWS, Dmod, HID);
    // 7. out = x1 + act @ fc2_w + fc2_b
    gemm_tc<false,true><<<dim3(Dmod/128, ROWS/128), 256, gemm_smem>>>(
        act, fc2_w, fc2_b, x1, out, ROWS, HID, Dmod);
}

// round 4
// speedup vs baseline: 2.1312x; 1.0849x over previous
#include <cuda_runtime.h>
#include <math.h>

#define Bsz  4
#define Nseq 1024
#define Dmod 768
#define Hh   12
#define DHd  64
#define HID  3072
#define ROWS (Bsz*Nseq)   // 4096

// ---- scratch (no cudaMalloc allowed) ----
__device__ float g_h   [ROWS*Dmod];
__device__ float g_qkv [ROWS*3*Dmod];
__device__ float g_attn[ROWS*Dmod];
__device__ float g_x1  [ROWS*Dmod];
__device__ float g_h2  [ROWS*Dmod];
__device__ float g_act [ROWS*HID];
// tf32-rounded weight copies
__device__ float g_wqkv[Dmod*3*Dmod];
__device__ float g_wproj[Dmod*Dmod];
__device__ float g_wfc1[Dmod*HID];
__device__ float g_wfc2[HID*Dmod];

__device__ __forceinline__ float round_tf32(float x) {
    unsigned r;
    asm("cvt.rna.tf32.f32 %0, %1;" : "=r"(r) : "f"(x));
    return __uint_as_float(r);
}

// ---------------- weight rounding (elementwise, vectorized) ----------------
__global__ __launch_bounds__(256) void round_kernel(
    const float* __restrict__ in, float* __restrict__ out, int n4)
{
    int i = blockIdx.x * 256 + threadIdx.x;
    if (i < n4) {
        float4 v = ((const float4*)in)[i];
        v.x = round_tf32(v.x); v.y = round_tf32(v.y);
        v.z = round_tf32(v.z); v.w = round_tf32(v.w);
        ((float4*)out)[i] = v;
    }
}

// ---------------- LayerNorm: one block per row (tf32-rounded output) -------
__global__ __launch_bounds__(256) void ln_kernel(
    const float* __restrict__ x, const float* __restrict__ g,
    const float* __restrict__ b, float* __restrict__ out)
{
    int row = blockIdx.x;
    const float* xr = x + (size_t)row * Dmod;
    float v[3];
    float s = 0.f, s2 = 0.f;
#pragma unroll
    for (int it = 0; it < 3; it++) {
        v[it] = xr[threadIdx.x + it*256];
        s += v[it]; s2 += v[it]*v[it];
    }
#pragma unroll
    for (int off = 16; off; off >>= 1) {
        s  += __shfl_xor_sync(0xffffffffu, s,  off);
        s2 += __shfl_xor_sync(0xffffffffu, s2, off);
    }
    __shared__ float ws[8], ws2[8];
    __shared__ float mu_s, rs_s;
    int wid = threadIdx.x >> 5, lane = threadIdx.x & 31;
    if (lane == 0) { ws[wid] = s; ws2[wid] = s2; }
    __syncthreads();
    if (threadIdx.x == 0) {
        float S = 0.f, S2 = 0.f;
#pragma unroll
        for (int i = 0; i < 8; i++) { S += ws[i]; S2 += ws2[i]; }
        float mu  = S * (1.f/Dmod);
        float var = S2 * (1.f/Dmod) - mu*mu;
        mu_s = mu;
        rs_s = rsqrtf(var + 1e-6f);
    }
    __syncthreads();
    float mu = mu_s, rs = rs_s;
#pragma unroll
    for (int it = 0; it < 3; it++) {
        int i = threadIdx.x + it*256;
        out[(size_t)row*Dmod + i] = round_tf32((v[it]-mu)*rs*g[i] + b[i]);
    }
}

// ---------------- tf32 tensor-core GEMM 128x128x32 ----------------
// Inputs are PRE-ROUNDED to tf32; fragments load raw bits, no cvt in loop.
#define AS_STRIDE 36   // 32 + 4 pad
#define BS_STRIDE 136  // 128 + 8 pad
#define STAGE_FLOATS (128*AS_STRIDE + 32*BS_STRIDE)

__device__ __forceinline__ void cp16(unsigned dst, const void* src) {
    asm volatile("cp.async.cg.shared.global [%0], [%1], 16;" :: "r"(dst), "l"(src));
}

template<bool GELU, bool RES, bool ROUND>
__global__ __launch_bounds__(256, 2) void gemm_tc(
    const float* __restrict__ A, const float* __restrict__ W,
    const float* __restrict__ bias, const float* __restrict__ res,
    float* __restrict__ C, int M, int K, int Nc)
{
    extern __shared__ float sm[];
    float* As[2] = { sm,                 sm + STAGE_FLOATS };
    float* Bs[2] = { sm + 128*AS_STRIDE, sm + STAGE_FLOATS + 128*AS_STRIDE };

    const int tid  = threadIdx.x;
    const int lane = tid & 31;
    const int warp = tid >> 5;
    const int wm   = warp & 1;
    const int wn   = warp >> 1;
    const int bm   = blockIdx.y * 128;
    const int bn   = blockIdx.x * 128;

    float acc[4][4][4];
#pragma unroll
    for (int i = 0; i < 4; i++)
#pragma unroll
        for (int j = 0; j < 4; j++)
#pragma unroll
            for (int r = 0; r < 4; r++) acc[i][j][r] = 0.f;

    const int kTiles = K >> 5;

    auto load_stage = [&](int kt, int buf) {
        const int k0 = kt * 32;
#pragma unroll
        for (int i = 0; i < 4; i++) {
            int idx = tid + i*256;
            int r = idx >> 3, kk = (idx & 7) * 4;
            cp16((unsigned)__cvta_generic_to_shared(&As[buf][r*AS_STRIDE + kk]),
                 A + (size_t)(bm + r) * K + k0 + kk);
        }
#pragma unroll
        for (int i = 0; i < 4; i++) {
            int idx = tid + i*256;
            int kr = idx >> 5, n = (idx & 31) * 4;
            cp16((unsigned)__cvta_generic_to_shared(&Bs[buf][kr*BS_STRIDE + n]),
                 W + (size_t)(k0 + kr) * Nc + bn + n);
        }
        asm volatile("cp.async.commit_group;");
    };

    load_stage(0, 0);

    const int r8 = lane >> 2;
    const int c4 = lane & 3;

    for (int kt = 0; kt < kTiles; kt++) {
        asm volatile("cp.async.wait_group 0;");
        __syncthreads();
        if (kt + 1 < kTiles) load_stage(kt + 1, (kt + 1) & 1);

        const float* as = As[kt & 1];
        const float* bs = Bs[kt & 1];
#pragma unroll
        for (int k8 = 0; k8 < 4; k8++) {
            const int kb = k8 * 8;
            unsigned af[4][4], bf[4][2];
#pragma unroll
            for (int mt = 0; mt < 4; mt++) {
                int row = wm*64 + mt*16 + r8;
                int col = kb + c4;
                af[mt][0] = __float_as_uint(as[ row     *AS_STRIDE + col    ]);
                af[mt][1] = __float_as_uint(as[(row + 8)*AS_STRIDE + col    ]);
                af[mt][2] = __float_as_uint(as[ row     *AS_STRIDE + col + 4]);
                af[mt][3] = __float_as_uint(as[(row + 8)*AS_STRIDE + col + 4]);
            }
#pragma unroll
            for (int nt = 0; nt < 4; nt++) {
                int col = wn*32 + nt*8 + r8;
                int krow = kb + c4;
                bf[nt][0] = __float_as_uint(bs[ krow     *BS_STRIDE + col]);
                bf[nt][1] = __float_as_uint(bs[(krow + 4)*BS_STRIDE + col]);
            }
#pragma unroll
            for (int mt = 0; mt < 4; mt++)
#pragma unroll
                for (int nt = 0; nt < 4; nt++) {
                    asm volatile(
                        "mma.sync.aligned.m16n8k8.row.col.f32.tf32.tf32.f32 "
                        "{%0,%1,%2,%3}, {%4,%5,%6,%7}, {%8,%9}, {%0,%1,%2,%3};"
                        : "+f"(acc[mt][nt][0]), "+f"(acc[mt][nt][1]),
                          "+f"(acc[mt][nt][2]), "+f"(acc[mt][nt][3])
                        : "r"(af[mt][0]), "r"(af[mt][1]),
                          "r"(af[mt][2]), "r"(af[mt][3]),
                          "r"(bf[nt][0]), "r"(bf[nt][1]));
                }
        }
        __syncthreads();
    }

    // ---- epilogue ----
#pragma unroll
    for (int mt = 0; mt < 4; mt++) {
        int row0 = bm + wm*64 + mt*16 + r8;
#pragma unroll
        for (int nt = 0; nt < 4; nt++) {
            int col0 = bn + wn*32 + nt*8 + c4*2;
            float b0 = __ldg(&bias[col0]), b1 = __ldg(&bias[col0 + 1]);
#pragma unroll
            for (int half = 0; half < 2; half++) {
                int row = row0 + half*8;
                float v0 = acc[mt][nt][half*2 + 0] + b0;
                float v1 = acc[mt][nt][half*2 + 1] + b1;
                if (GELU) { v0 = v0 * normcdff(v0); v1 = v1 * normcdff(v1); }
                if (RES) {
                    const float2 rr = *(const float2*)&res[(size_t)row*Nc + col0];
                    v0 += rr.x; v1 += rr.y;
                }
                if (ROUND) { v0 = round_tf32(v0); v1 = round_tf32(v1); }
                *(float2*)&C[(size_t)row*Nc + col0] = make_float2(v0, v1);
            }
        }
    }
}

// ---------------- Flash attention with additive adjacency bias ----------------
__global__ __launch_bounds__(256) void attn_kernel(
    const float* __restrict__ qkv, const float* __restrict__ adj,
    float* __restrict__ out)
{
    extern __shared__ float smf[];
    float* Qs = smf;             // [64][64]
    float* KP = smf + 64*64;     // [64][65]
    float* Vs = KP + 64*65;      // [64][65]
    const int tid = threadIdx.x;
    const int tx = tid & 15, ty = tid >> 4;
    const int bh = blockIdx.y;
    const int b  = bh / Hh, h = bh % Hh;
    const int q0 = blockIdx.x * 64;
    const float scale = 0.125f;

#pragma unroll
    for (int it = 0; it < 16; it++) {
        int idx = tid + it*256;
        int r = idx >> 6, d = idx & 63;
        Qs[r*64 + d] = qkv[(size_t)(b*Nseq + q0 + r) * (3*Dmod) + h*DHd + d];
    }
    float m_run[4], l_run[4], o[4][4];
#pragma unroll
    for (int i = 0; i < 4; i++) {
        m_run[i] = -1e30f; l_run[i] = 0.f;
#pragma unroll
        for (int j = 0; j < 4; j++) o[i][j] = 0.f;
    }
    __syncthreads();

    for (int kt = 0; kt < Nseq/64; kt++) {
        int k0 = kt*64;
#pragma unroll
        for (int it = 0; it < 16; it++) {
            int idx = tid + it*256;
            int r = idx >> 6, d = idx & 63;
            size_t base = (size_t)(b*Nseq + k0 + r) * (3*Dmod) + h*DHd + d;
            KP[r*65 + d] = qkv[base +   Dmod];
            Vs[r*65 + d] = qkv[base + 2*Dmod];
        }
        __syncthreads();
        float s[4][4] = {};
#pragma unroll
        for (int d = 0; d < 64; d++) {
            float a[4], bb[4];
#pragma unroll
            for (int i = 0; i < 4; i++) a[i]  = Qs[(ty*4+i)*64 + d];
#pragma unroll
            for (int j = 0; j < 4; j++) bb[j] = KP[(tx*4+j)*65 + d];
#pragma unroll
            for (int i = 0; i < 4; i++)
#pragma unroll
                for (int j = 0; j < 4; j++)
                    s[i][j] = fmaf(a[i], bb[j], s[i][j]);
        }
#pragma unroll
        for (int i = 0; i < 4; i++) {
            int qg = q0 + ty*4 + i;
#pragma unroll
            for (int j = 0; j < 4; j++)
                s[i][j] = s[i][j]*scale + adj[(size_t)qg*Nseq + k0 + tx*4 + j];
        }
        __syncthreads();

#pragma unroll
        for (int i = 0; i < 4; i++) {
            float mx = fmaxf(fmaxf(s[i][0], s[i][1]), fmaxf(s[i][2], s[i][3]));
#pragma unroll
            for (int off = 8; off; off >>= 1)
                mx = fmaxf(mx, __shfl_xor_sync(0xffffffffu, mx, off, 16));
            float mnew  = fmaxf(m_run[i], mx);
            float alpha = __expf(m_run[i] - mnew);
            float rs = 0.f;
#pragma unroll
            for (int j = 0; j < 4; j++) { s[i][j] = __expf(s[i][j] - mnew); rs += s[i][j]; }
#pragma unroll
            for (int off = 8; off; off >>= 1)
                rs += __shfl_xor_sync(0xffffffffu, rs, off, 16);
            l_run[i] = l_run[i]*alpha + rs;
            m_run[i] = mnew;
#pragma unroll
            for (int j = 0; j < 4; j++) o[i][j] *= alpha;
#pragma unroll
            for (int j = 0; j < 4; j++) KP[(ty*4+i)*65 + tx*4+j] = s[i][j];
        }
        __syncthreads();
#pragma unroll
        for (int kk = 0; kk < 64; kk++) {
            float a[4], bb[4];
#pragma unroll
            for (int i = 0; i < 4; i++) a[i]  = KP[(ty*4+i)*65 + kk];
#pragma unroll
            for (int j = 0; j < 4; j++) bb[j] = Vs[kk*65 + tx*4+j];
#pragma unroll
            for (int i = 0; i < 4; i++)
#pragma unroll
                for (int j = 0; j < 4; j++)
                    o[i][j] = fmaf(a[i], bb[j], o[i][j]);
        }
        __syncthreads();
    }
#pragma unroll
    for (int i = 0; i < 4; i++) {
        int qg = q0 + ty*4 + i;
        float inv = 1.f / l_run[i];
#pragma unroll
        for (int j = 0; j < 4; j++)
            out[(size_t)(b*Nseq + qg)*Dmod + h*DHd + tx*4 + j] =
                round_tf32(o[i][j]*inv);
    }
}

// ---------------- launcher ----------------
extern "C" void kernel_launch(void* const* d_in, const int* in_sizes, int n_in,
                              void* d_out, int out_size)
{
    const float* x      = (const float*)d_in[0];
    const float* adj    = (const float*)d_in[1];
    const float* ln1_g  = (const float*)d_in[2];
    const float* ln1_b  = (const float*)d_in[3];
    const float* qkv_w  = (const float*)d_in[4];
    const float* qkv_b  = (const float*)d_in[5];
    const float* proj_w = (const float*)d_in[6];
    const float* proj_b = (const float*)d_in[7];
    const float* ln2_g  = (const float*)d_in[8];
    const float* ln2_b  = (const float*)d_in[9];
    const float* fc1_w  = (const float*)d_in[10];
    const float* fc1_b  = (const float*)d_in[11];
    const float* fc2_w  = (const float*)d_in[12];
    const float* fc2_b  = (const float*)d_in[13];
    float* out = (float*)d_out;

    float *h, *qkv, *attn, *x1, *h2, *act, *wqkv, *wproj, *wfc1, *wfc2;
    cudaGetSymbolAddress((void**)&h,    g_h);
    cudaGetSymbolAddress((void**)&qkv,  g_qkv);
    cudaGetSymbolAddress((void**)&attn, g_attn);
    cudaGetSymbolAddress((void**)&x1,   g_x1);
    cudaGetSymbolAddress((void**)&h2,   g_h2);
    cudaGetSymbolAddress((void**)&act,  g_act);
    cudaGetSymbolAddress((void**)&wqkv, g_wqkv);
    cudaGetSymbolAddress((void**)&wproj,g_wproj);
    cudaGetSymbolAddress((void**)&wfc1, g_wfc1);
    cudaGetSymbolAddress((void**)&wfc2, g_wfc2);

    const int gemm_smem = 2 * STAGE_FLOATS * sizeof(float);  // ~71.7 KB
    static int init = 0;
    if (!init) {
        cudaFuncSetAttribute(gemm_tc<false,false,false>,
            cudaFuncAttributeMaxDynamicSharedMemorySize, gemm_smem);
        cudaFuncSetAttribute(gemm_tc<false,true,false>,
            cudaFuncAttributeMaxDynamicSharedMemorySize, gemm_smem);
        cudaFuncSetAttribute(gemm_tc<true,false,true>,
            cudaFuncAttributeMaxDynamicSharedMemorySize, gemm_smem);
        const int attn_smem = (64*64 + 2*64*65) * sizeof(float);
        cudaFuncSetAttribute(attn_kernel,
            cudaFuncAttributeMaxDynamicSharedMemorySize, attn_smem);
        init = 1;
    }
    const int attn_smem = (64*64 + 2*64*65) * sizeof(float);

    // 0. tf32-round weight copies
    round_kernel<<<(Dmod*3*Dmod/4 + 255)/256, 256>>>(qkv_w,  wqkv,  Dmod*3*Dmod/4);
    round_kernel<<<(Dmod*Dmod/4   + 255)/256, 256>>>(proj_w, wproj, Dmod*Dmod/4);
    round_kernel<<<(Dmod*HID/4    + 255)/256, 256>>>(fc1_w,  wfc1,  Dmod*HID/4);
    round_kernel<<<(HID*Dmod/4    + 255)/256, 256>>>(fc2_w,  wfc2,  HID*Dmod/4);

    // 1. LN1 (rounded output)
    ln_kernel<<<ROWS, 256>>>(x, ln1_g, ln1_b, h);
    // 2. qkv = h @ qkv_w + qkv_b
    gemm_tc<false,false,false><<<dim3(3*Dmod/128, ROWS/128), 256, gemm_smem>>>(
        h, wqkv, qkv_b, nullptr, qkv, ROWS, Dmod, 3*Dmod);
    // 3. attention (rounded output)
    attn_kernel<<<dim3(Nseq/64, Bsz*Hh), 256, attn_smem>>>(qkv, adj, attn);
    // 4. x1 = x + attn @ proj_w + proj_b
    gemm_tc<false,true,false><<<dim3(Dmod/128, ROWS/128), 256, gemm_smem>>>(
        attn, wproj, proj_b, x, x1, ROWS, Dmod, Dmod);
    // 5. LN2 (rounded output)
    ln_kernel<<<ROWS, 256>>>(x1, ln2_g, ln2_b, h2);
    // 6. act = gelu(h2 @ fc1_w + fc1_b)  (rounded output)
    gemm_tc<true,false,true><<<dim3(HID/128, ROWS/128), 256, gemm_smem>>>(
        h2, wfc1, fc1_b, nullptr, act, ROWS, Dmod, HID);
    // 7. out = x1 + act @ fc2_w + fc2_b
    gemm_tc<false,true,false><<<dim3(Dmod/128, ROWS/128), 256, gemm_smem>>>(
        act, wfc2, fc2_b, x1, out, ROWS, HID, Dmod);
}

// round 5
// speedup vs baseline: 2.7302x; 1.2811x over previous
#include <cuda_runtime.h>
#include <math.h>

#define Bsz  4
#define Nseq 1024
#define Dmod 768
#define Hh   12
#define DHd  64
#define HID  3072
#define ROWS (Bsz*Nseq)   // 4096

// ---- scratch (no cudaMalloc allowed) ----
__device__ float g_h   [ROWS*Dmod];
__device__ float g_qkv [ROWS*3*Dmod];
__device__ float g_attn[ROWS*Dmod];
__device__ float g_x1  [ROWS*Dmod];
__device__ float g_h2  [ROWS*Dmod];
__device__ float g_act [ROWS*HID];

__device__ __forceinline__ float round_tf32(float x) {
    unsigned r;
    asm("cvt.rna.tf32.f32 %0, %1;" : "=r"(r) : "f"(x));
    return __uint_as_float(r);
}

#define MMA_TF32(acc, a0,a1,a2,a3, b0,b1)                                   \
    asm volatile(                                                           \
        "mma.sync.aligned.m16n8k8.row.col.f32.tf32.tf32.f32 "               \
        "{%0,%1,%2,%3}, {%4,%5,%6,%7}, {%8,%9}, {%0,%1,%2,%3};"             \
        : "+f"(acc[0]), "+f"(acc[1]), "+f"(acc[2]), "+f"(acc[3])            \
        : "r"(a0), "r"(a1), "r"(a2), "r"(a3), "r"(b0), "r"(b1))

// ---------------- LayerNorm: one block per row (tf32-rounded output) -------
__global__ __launch_bounds__(256) void ln_kernel(
    const float* __restrict__ x, const float* __restrict__ g,
    const float* __restrict__ b, float* __restrict__ out)
{
    int row = blockIdx.x;
    const float* xr = x + (size_t)row * Dmod;
    float v[3];
    float s = 0.f, s2 = 0.f;
#pragma unroll
    for (int it = 0; it < 3; it++) {
        v[it] = xr[threadIdx.x + it*256];
        s += v[it]; s2 += v[it]*v[it];
    }
#pragma unroll
    for (int off = 16; off; off >>= 1) {
        s  += __shfl_xor_sync(0xffffffffu, s,  off);
        s2 += __shfl_xor_sync(0xffffffffu, s2, off);
    }
    __shared__ float ws[8], ws2[8];
    __shared__ float mu_s, rs_s;
    int wid = threadIdx.x >> 5, lane = threadIdx.x & 31;
    if (lane == 0) { ws[wid] = s; ws2[wid] = s2; }
    __syncthreads();
    if (threadIdx.x == 0) {
        float S = 0.f, S2 = 0.f;
#pragma unroll
        for (int i = 0; i < 8; i++) { S += ws[i]; S2 += ws2[i]; }
        float mu  = S * (1.f/Dmod);
        float var = S2 * (1.f/Dmod) - mu*mu;
        mu_s = mu;
        rs_s = rsqrtf(var + 1e-6f);
    }
    __syncthreads();
    float mu = mu_s, rs = rs_s;
#pragma unroll
    for (int it = 0; it < 3; it++) {
        int i = threadIdx.x + it*256;
        out[(size_t)row*Dmod + i] = round_tf32((v[it]-mu)*rs*g[i] + b[i]);
    }
}

// ---------------- tf32 tensor-core GEMM 128x128x32 ----------------
#define AS_STRIDE 36   // 32 + 4 pad
#define BS_STRIDE 136  // 128 + 8 pad
#define STAGE_FLOATS (128*AS_STRIDE + 32*BS_STRIDE)

__device__ __forceinline__ void cp16(unsigned dst, const void* src) {
    asm volatile("cp.async.cg.shared.global [%0], [%1], 16;" :: "r"(dst), "l"(src));
}

template<bool GELU, bool RES, bool ROUND>
__global__ __launch_bounds__(256, 2) void gemm_tc(
    const float* __restrict__ A, const float* __restrict__ W,
    const float* __restrict__ bias, const float* __restrict__ res,
    float* __restrict__ C, int M, int K, int Nc)
{
    extern __shared__ float sm[];
    float* As[2] = { sm,                 sm + STAGE_FLOATS };
    float* Bs[2] = { sm + 128*AS_STRIDE, sm + STAGE_FLOATS + 128*AS_STRIDE };

    const int tid  = threadIdx.x;
    const int lane = tid & 31;
    const int warp = tid >> 5;
    const int wm   = warp & 1;
    const int wn   = warp >> 1;
    const int bm   = blockIdx.y * 128;
    const int bn   = blockIdx.x * 128;

    float acc[4][4][4];
#pragma unroll
    for (int i = 0; i < 4; i++)
#pragma unroll
        for (int j = 0; j < 4; j++)
#pragma unroll
            for (int r = 0; r < 4; r++) acc[i][j][r] = 0.f;

    const int kTiles = K >> 5;

    auto load_stage = [&](int kt, int buf) {
        const int k0 = kt * 32;
#pragma unroll
        for (int i = 0; i < 4; i++) {
            int idx = tid + i*256;
            int r = idx >> 3, kk = (idx & 7) * 4;
            cp16((unsigned)__cvta_generic_to_shared(&As[buf][r*AS_STRIDE + kk]),
                 A + (size_t)(bm + r) * K + k0 + kk);
        }
#pragma unroll
        for (int i = 0; i < 4; i++) {
            int idx = tid + i*256;
            int kr = idx >> 5, n = (idx & 31) * 4;
            cp16((unsigned)__cvta_generic_to_shared(&Bs[buf][kr*BS_STRIDE + n]),
                 W + (size_t)(k0 + kr) * Nc + bn + n);
        }
        asm volatile("cp.async.commit_group;");
    };

    load_stage(0, 0);

    const int r8 = lane >> 2;
    const int c4 = lane & 3;

    for (int kt = 0; kt < kTiles; kt++) {
        asm volatile("cp.async.wait_group 0;");
        __syncthreads();
        if (kt + 1 < kTiles) load_stage(kt + 1, (kt + 1) & 1);

        const float* as = As[kt & 1];
        const float* bs = Bs[kt & 1];
#pragma unroll
        for (int k8 = 0; k8 < 4; k8++) {
            const int kb = k8 * 8;
            unsigned af[4][4], bf[4][2];
#pragma unroll
            for (int mt = 0; mt < 4; mt++) {
                int row = wm*64 + mt*16 + r8;
                int col = kb + c4;
                af[mt][0] = __float_as_uint(as[ row     *AS_STRIDE + col    ]);
                af[mt][1] = __float_as_uint(as[(row + 8)*AS_STRIDE + col    ]);
                af[mt][2] = __float_as_uint(as[ row     *AS_STRIDE + col + 4]);
                af[mt][3] = __float_as_uint(as[(row + 8)*AS_STRIDE + col + 4]);
            }
#pragma unroll
            for (int nt = 0; nt < 4; nt++) {
                int col = wn*32 + nt*8 + r8;
                int krow = kb + c4;
                bf[nt][0] = __float_as_uint(bs[ krow     *BS_STRIDE + col]);
                bf[nt][1] = __float_as_uint(bs[(krow + 4)*BS_STRIDE + col]);
            }
#pragma unroll
            for (int mt = 0; mt < 4; mt++)
#pragma unroll
                for (int nt = 0; nt < 4; nt++)
                    MMA_TF32(acc[mt][nt], af[mt][0], af[mt][1], af[mt][2],
                             af[mt][3], bf[nt][0], bf[nt][1]);
        }
        if (kt + 1 < kTiles) __syncthreads();   // protect buf reuse via next top barrier
    }

    // ---- epilogue ----
#pragma unroll
    for (int mt = 0; mt < 4; mt++) {
        int row0 = bm + wm*64 + mt*16 + r8;
#pragma unroll
        for (int nt = 0; nt < 4; nt++) {
            int col0 = bn + wn*32 + nt*8 + c4*2;
            float b0 = __ldg(&bias[col0]), b1 = __ldg(&bias[col0 + 1]);
#pragma unroll
            for (int half = 0; half < 2; half++) {
                int row = row0 + half*8;
                float v0 = acc[mt][nt][half*2 + 0] + b0;
                float v1 = acc[mt][nt][half*2 + 1] + b1;
                if (GELU) { v0 = v0 * normcdff(v0); v1 = v1 * normcdff(v1); }
                if (RES) {
                    const float2 rr = *(const float2*)&res[(size_t)row*Nc + col0];
                    v0 += rr.x; v1 += rr.y;
                }
                if (ROUND) { v0 = round_tf32(v0); v1 = round_tf32(v1); }
                *(float2*)&C[(size_t)row*Nc + col0] = make_float2(v0, v1);
            }
        }
    }
}

// ---------------- Tensor-core flash attention ----------------
// 128 Q rows per block (two 64-row subtiles x 4 warps), K/V tiles of 64.
// QK^T and P@V via m16n8k8.tf32. P round-trips smem intra-warp only.
#define AT_STR 72   // 72 mod 32 == 8 -> conflict-free fragment access

__global__ __launch_bounds__(256) void attn_tc(
    const float* __restrict__ qkv, const float* __restrict__ adj,
    float* __restrict__ out)
{
    extern __shared__ float sm[];
    float* Qs = sm;                // [128][AT_STR]
    float* Ps = Qs + 128*AT_STR;   // [128][AT_STR]
    float* Ks = Ps + 128*AT_STR;   // [64][AT_STR]
    float* Vs = Ks + 64*AT_STR;    // [64][AT_STR]

    const int tid  = threadIdx.x;
    const int lane = tid & 31;
    const int warp = tid >> 5;
    const int r8   = lane >> 2;
    const int c4   = lane & 3;
    const int bh   = blockIdx.y;
    const int b    = bh / Hh, h = bh % Hh;
    const int q0   = blockIdx.x * 128;
    const int qrow = (warp >> 2)*64 + (warp & 3)*16;   // warp base row in tile
    const float scale = 0.125f;

    // load Q tile (128 x 64)
#pragma unroll
    for (int it = 0; it < 32; it++) {
        int idx = tid + it*256;
        int r = idx >> 6, d = idx & 63;
        Qs[r*AT_STR + d] = qkv[(size_t)(b*Nseq + q0 + r)*(3*Dmod) + h*DHd + d];
    }

    float m0 = -1e30f, m1 = -1e30f, l0 = 0.f, l1 = 0.f;
    float o[8][4];
#pragma unroll
    for (int nt = 0; nt < 8; nt++)
#pragma unroll
        for (int r = 0; r < 4; r++) o[nt][r] = 0.f;

    __syncthreads();

    for (int kt = 0; kt < Nseq/64; kt++) {
        const int k0 = kt*64;
        // load K,V tiles (64 x 64 each)
#pragma unroll
        for (int it = 0; it < 16; it++) {
            int idx = tid + it*256;
            int r = idx >> 6, d = idx & 63;
            size_t base = (size_t)(b*Nseq + k0 + r)*(3*Dmod) + h*DHd + d;
            Ks[r*AT_STR + d] = qkv[base +   Dmod];
            Vs[r*AT_STR + d] = qkv[base + 2*Dmod];
        }
        __syncthreads();

        // ---- S = Q @ K^T ----
        float s[8][4];
#pragma unroll
        for (int nt = 0; nt < 8; nt++)
#pragma unroll
            for (int r = 0; r < 4; r++) s[nt][r] = 0.f;

#pragma unroll
        for (int k8 = 0; k8 < 8; k8++) {
            const int kb = k8*8;
            unsigned a0 = __float_as_uint(Qs[(qrow + r8    )*AT_STR + kb + c4    ]);
            unsigned a1 = __float_as_uint(Qs[(qrow + r8 + 8)*AT_STR + kb + c4    ]);
            unsigned a2 = __float_as_uint(Qs[(qrow + r8    )*AT_STR + kb + c4 + 4]);
            unsigned a3 = __float_as_uint(Qs[(qrow + r8 + 8)*AT_STR + kb + c4 + 4]);
#pragma unroll
            for (int nt = 0; nt < 8; nt++) {
                unsigned b0 = __float_as_uint(Ks[(nt*8 + r8)*AT_STR + kb + c4    ]);
                unsigned b1 = __float_as_uint(Ks[(nt*8 + r8)*AT_STR + kb + c4 + 4]);
                MMA_TF32(s[nt], a0, a1, a2, a3, b0, b1);
            }
        }

        // ---- scale + adjacency bias ----
        const int qg0 = q0 + qrow + r8;
#pragma unroll
        for (int nt = 0; nt < 8; nt++) {
            int col = k0 + nt*8 + c4*2;
            float2 ad0 = *(const float2*)&adj[(size_t) qg0     *Nseq + col];
            float2 ad1 = *(const float2*)&adj[(size_t)(qg0 + 8)*Nseq + col];
            s[nt][0] = s[nt][0]*scale + ad0.x;
            s[nt][1] = s[nt][1]*scale + ad0.y;
            s[nt][2] = s[nt][2]*scale + ad1.x;
            s[nt][3] = s[nt][3]*scale + ad1.y;
        }

        // ---- online softmax (rows r8 and r8+8; 4 lanes per row share) ----
        float mx0 = -1e30f, mx1 = -1e30f;
#pragma unroll
        for (int nt = 0; nt < 8; nt++) {
            mx0 = fmaxf(mx0, fmaxf(s[nt][0], s[nt][1]));
            mx1 = fmaxf(mx1, fmaxf(s[nt][2], s[nt][3]));
        }
        mx0 = fmaxf(mx0, __shfl_xor_sync(0xffffffffu, mx0, 1));
        mx0 = fmaxf(mx0, __shfl_xor_sync(0xffffffffu, mx0, 2));
        mx1 = fmaxf(mx1, __shfl_xor_sync(0xffffffffu, mx1, 1));
        mx1 = fmaxf(mx1, __shfl_xor_sync(0xffffffffu, mx1, 2));
        float mn0 = fmaxf(m0, mx0), mn1 = fmaxf(m1, mx1);
        float al0 = __expf(m0 - mn0), al1 = __expf(m1 - mn1);
        float rs0 = 0.f, rs1 = 0.f;
#pragma unroll
        for (int nt = 0; nt < 8; nt++) {
            s[nt][0] = __expf(s[nt][0] - mn0);
            s[nt][1] = __expf(s[nt][1] - mn0);
            s[nt][2] = __expf(s[nt][2] - mn1);
            s[nt][3] = __expf(s[nt][3] - mn1);
            rs0 += s[nt][0] + s[nt][1];
            rs1 += s[nt][2] + s[nt][3];
        }
        rs0 += __shfl_xor_sync(0xffffffffu, rs0, 1);
        rs0 += __shfl_xor_sync(0xffffffffu, rs0, 2);
        rs1 += __shfl_xor_sync(0xffffffffu, rs1, 1);
        rs1 += __shfl_xor_sync(0xffffffffu, rs1, 2);
        l0 = l0*al0 + rs0;  l1 = l1*al1 + rs1;
        m0 = mn0;           m1 = mn1;
#pragma unroll
        for (int nt = 0; nt < 8; nt++) {
            o[nt][0] *= al0; o[nt][1] *= al0;
            o[nt][2] *= al1; o[nt][3] *= al1;
        }

        // ---- write P (own rows only) ----
#pragma unroll
        for (int nt = 0; nt < 8; nt++) {
            *(float2*)&Ps[(qrow + r8    )*AT_STR + nt*8 + c4*2] =
                make_float2(s[nt][0], s[nt][1]);
            *(float2*)&Ps[(qrow + r8 + 8)*AT_STR + nt*8 + c4*2] =
                make_float2(s[nt][2], s[nt][3]);
        }
        __syncwarp();

        // ---- O += P @ V ----
#pragma unroll
        for (int k8 = 0; k8 < 8; k8++) {
            const int kb = k8*8;
            unsigned a0 = __float_as_uint(Ps[(qrow + r8    )*AT_STR + kb + c4    ]);
            unsigned a1 = __float_as_uint(Ps[(qrow + r8 + 8)*AT_STR + kb + c4    ]);
            unsigned a2 = __float_as_uint(Ps[(qrow + r8    )*AT_STR + kb + c4 + 4]);
            unsigned a3 = __float_as_uint(Ps[(qrow + r8 + 8)*AT_STR + kb + c4 + 4]);
#pragma unroll
            for (int nt = 0; nt < 8; nt++) {
                unsigned b0 = __float_as_uint(Vs[(kb + c4    )*AT_STR + nt*8 + r8]);
                unsigned b1 = __float_as_uint(Vs[(kb + c4 + 4)*AT_STR + nt*8 + r8]);
                MMA_TF32(o[nt], a0, a1, a2, a3, b0, b1);
            }
        }
        __syncthreads();   // before K/V overwrite next iter
    }

    // ---- epilogue: normalize + write ----
    const int qg0 = q0 + qrow + r8;
    float i0 = 1.f / l0, i1 = 1.f / l1;
#pragma unroll
    for (int nt = 0; nt < 8; nt++) {
        int col = h*DHd + nt*8 + c4*2;
        *(float2*)&out[(size_t)(b*Nseq + qg0    )*Dmod + col] =
            make_float2(round_tf32(o[nt][0]*i0), round_tf32(o[nt][1]*i0));
        *(float2*)&out[(size_t)(b*Nseq + qg0 + 8)*Dmod + col] =
            make_float2(round_tf32(o[nt][2]*i1), round_tf32(o[nt][3]*i1));
    }
}

// ---------------- launcher ----------------
extern "C" void kernel_launch(void* const* d_in, const int* in_sizes, int n_in,
                              void* d_out, int out_size)
{
    const float* x      = (const float*)d_in[0];
    const float* adj    = (const float*)d_in[1];
    const float* ln1_g  = (const float*)d_in[2];
    const float* ln1_b  = (const float*)d_in[3];
    const float* qkv_w  = (const float*)d_in[4];
    const float* qkv_b  = (const float*)d_in[5];
    const float* proj_w = (const float*)d_in[6];
    const float* proj_b = (const float*)d_in[7];
    const float* ln2_g  = (const float*)d_in[8];
    const float* ln2_b  = (const float*)d_in[9];
    const float* fc1_w  = (const float*)d_in[10];
    const float* fc1_b  = (const float*)d_in[11];
    const float* fc2_w  = (const float*)d_in[12];
    const float* fc2_b  = (const float*)d_in[13];
    float* out = (float*)d_out;

    float *h, *qkv, *attn, *x1, *h2, *act;
    cudaGetSymbolAddress((void**)&h,    g_h);
    cudaGetSymbolAddress((void**)&qkv,  g_qkv);
    cudaGetSymbolAddress((void**)&attn, g_attn);
    cudaGetSymbolAddress((void**)&x1,   g_x1);
    cudaGetSymbolAddress((void**)&h2,   g_h2);
    cudaGetSymbolAddress((void**)&act,  g_act);

    const int gemm_smem = 2 * STAGE_FLOATS * sizeof(float);       // ~71.7 KB
    const int attn_smem = (128 + 128 + 64 + 64) * AT_STR * sizeof(float); // 108 KB
    static int init = 0;
    if (!init) {
        cudaFuncSetAttribute(gemm_tc<false,false,false>,
            cudaFuncAttributeMaxDynamicSharedMemorySize, gemm_smem);
        cudaFuncSetAttribute(gemm_tc<false,true,false>,
            cudaFuncAttributeMaxDynamicSharedMemorySize, gemm_smem);
        cudaFuncSetAttribute(gemm_tc<true,false,true>,
            cudaFuncAttributeMaxDynamicSharedMemorySize, gemm_smem);
        cudaFuncSetAttribute(attn_tc,
            cudaFuncAttributeMaxDynamicSharedMemorySize, attn_smem);
        init = 1;
    }

    // 1. LN1 (tf32-rounded output)
    ln_kernel<<<ROWS, 256>>>(x, ln1_g, ln1_b, h);
    // 2. qkv = h @ qkv_w + qkv_b   (W truncated to tf32 by HW)
    gemm_tc<false,false,false><<<dim3(3*Dmod/128, ROWS/128), 256, gemm_smem>>>(
        h, qkv_w, qkv_b, nullptr, qkv, ROWS, Dmod, 3*Dmod);
    // 3. tensor-core flash attention
    attn_tc<<<dim3(Nseq/128, Bsz*Hh), 256, attn_smem>>>(qkv, adj, attn);
    // 4. x1 = x + attn @ proj_w + proj_b
    gemm_tc<false,true,false><<<dim3(Dmod/128, ROWS/128), 256, gemm_smem>>>(
        attn, proj_w, proj_b, x, x1, ROWS, Dmod, Dmod);
    // 5. LN2
    ln_kernel<<<ROWS, 256>>>(x1, ln2_g, ln2_b, h2);
    // 6. act = gelu(h2 @ fc1_w + fc1_b)  (rounded output)
    gemm_tc<true,false,true><<<dim3(HID/128, ROWS/128), 256, gemm_smem>>>(
        h2, fc1_w, fc1_b, nullptr, act, ROWS, Dmod, HID);
    // 7. out = x1 + act @ fc2_w + fc2_b
    gemm_tc<false,true,false><<<dim3(Dmod/128, ROWS/128), 256, gemm_smem>>>(
        act, fc2_w, fc2_b, x1, out, ROWS, HID, Dmod);
}

// round 7
// speedup vs baseline: 2.9529x; 1.0816x over previous
#include <cuda_runtime.h>
#include <math.h>
#include <stdint.h>

#define Bsz  4
#define Nseq 1024
#define Dmod 768
#define Hh   12
#define DHd  64
#define HID  3072
#define ROWS (Bsz*Nseq)   // 4096

// ---- scratch (no cudaMalloc allowed) ----
__device__ float g_h   [ROWS*Dmod];
__device__ float g_qkv [ROWS*3*Dmod];
__device__ float g_attn[ROWS*Dmod];
__device__ float g_x1  [ROWS*Dmod];
__device__ float g_h2  [ROWS*Dmod];
__device__ float g_act [ROWS*HID];
__device__ float g_part[3*ROWS*Dmod];   // split-K partials

__device__ __forceinline__ float round_tf32(float x) {
    unsigned r;
    asm("cvt.rna.tf32.f32 %0, %1;" : "=r"(r) : "f"(x));
    return __uint_as_float(r);
}

#define MMA_TF32(acc, a0,a1,a2,a3, b0,b1)                                   \
    asm volatile(                                                           \
        "mma.sync.aligned.m16n8k8.row.col.f32.tf32.tf32.f32 "               \
        "{%0,%1,%2,%3}, {%4,%5,%6,%7}, {%8,%9}, {%0,%1,%2,%3};"             \
        : "+f"(acc[0]), "+f"(acc[1]), "+f"(acc[2]), "+f"(acc[3])            \
        : "r"(a0), "r"(a1), "r"(a2), "r"(a3), "r"(b0), "r"(b1))

__device__ __forceinline__ void cp16(unsigned dst, const void* src) {
    asm volatile("cp.async.cg.shared.global [%0], [%1], 16;" :: "r"(dst), "l"(src));
}

// ---------------- LayerNorm: one block per row (tf32-rounded output) -------
__global__ __launch_bounds__(256) void ln_kernel(
    const float* __restrict__ x, const float* __restrict__ g,
    const float* __restrict__ b, float* __restrict__ out)
{
    int row = blockIdx.x;
    const float* xr = x + (size_t)row * Dmod;
    float v[3];
    float s = 0.f, s2 = 0.f;
#pragma unroll
    for (int it = 0; it < 3; it++) {
        v[it] = xr[threadIdx.x + it*256];
        s += v[it]; s2 += v[it]*v[it];
    }
#pragma unroll
    for (int off = 16; off; off >>= 1) {
        s  += __shfl_xor_sync(0xffffffffu, s,  off);
        s2 += __shfl_xor_sync(0xffffffffu, s2, off);
    }
    __shared__ float ws[8], ws2[8];
    __shared__ float mu_s, rs_s;
    int wid = threadIdx.x >> 5, lane = threadIdx.x & 31;
    if (lane == 0) { ws[wid] = s; ws2[wid] = s2; }
    __syncthreads();
    if (threadIdx.x == 0) {
        float S = 0.f, S2 = 0.f;
#pragma unroll
        for (int i = 0; i < 8; i++) { S += ws[i]; S2 += ws2[i]; }
        float mu  = S * (1.f/Dmod);
        float var = S2 * (1.f/Dmod) - mu*mu;
        mu_s = mu;
        rs_s = rsqrtf(var + 1e-6f);
    }
    __syncthreads();
    float mu = mu_s, rs = rs_s;
#pragma unroll
    for (int it = 0; it < 3; it++) {
        int i = threadIdx.x + it*256;
        out[(size_t)row*Dmod + i] = round_tf32((v[it]-mu)*rs*g[i] + b[i]);
    }
}

// ---------------- tf32 tensor-core GEMM 128x128, 3-stage pipeline ----------
// PARTIAL: split-K over blockIdx.z; raw partial sums to C + z*M*Nc (no bias).
#define AS_STRIDE 36   // 32 + 4 pad
#define BS_STRIDE 136  // 128 + 8 pad
#define STAGE_FLOATS (128*AS_STRIDE + 32*BS_STRIDE)   // 8960 floats
#define GEMM_SMEM (3*STAGE_FLOATS*4)                  // 107520 B

template<bool GELU, bool RES, bool ROUND, bool PARTIAL>
__global__ __launch_bounds__(256, 2) void gemm_tc(
    const float* __restrict__ A, const float* __restrict__ W,
    const float* __restrict__ bias, const float* __restrict__ res,
    float* __restrict__ C, int M, int Kfull, int Nc, int Ks)
{
    extern __shared__ float sm[];
    float* As[3] = { sm,                 sm + STAGE_FLOATS,
                     sm + 2*STAGE_FLOATS };
    float* Bs[3] = { sm + 128*AS_STRIDE, sm + STAGE_FLOATS + 128*AS_STRIDE,
                     sm + 2*STAGE_FLOATS + 128*AS_STRIDE };

    const int tid  = threadIdx.x;
    const int lane = tid & 31;
    const int warp = tid >> 5;
    const int wm   = warp & 1;
    const int wn   = warp >> 1;
    const int bm   = blockIdx.y * 128;
    const int bn   = blockIdx.x * 128;
    const int z    = blockIdx.z;

    const float* Ab = A + (size_t)z * Ks;              // column offset, stride Kfull
    const float* Wb = W + (size_t)z * Ks * Nc;
    float* Cb = PARTIAL ? (C + (size_t)z * M * Nc) : C;

    float acc[4][4][4];
#pragma unroll
    for (int i = 0; i < 4; i++)
#pragma unroll
        for (int j = 0; j < 4; j++)
#pragma unroll
            for (int r = 0; r < 4; r++) acc[i][j][r] = 0.f;

    const int kTiles = Ks >> 5;

    auto load_stage = [&](int kt, int buf) {
        const int k0 = kt * 32;
#pragma unroll
        for (int i = 0; i < 4; i++) {
            int idx = tid + i*256;
            int r = idx >> 3, kk = (idx & 7) * 4;
            cp16((unsigned)__cvta_generic_to_shared(&As[buf][r*AS_STRIDE + kk]),
                 Ab + (size_t)(bm + r) * Kfull + k0 + kk);
        }
#pragma unroll
        for (int i = 0; i < 4; i++) {
            int idx = tid + i*256;
            int kr = idx >> 5, n = (idx & 31) * 4;
            cp16((unsigned)__cvta_generic_to_shared(&Bs[buf][kr*BS_STRIDE + n]),
                 Wb + (size_t)(k0 + kr) * Nc + bn + n);
        }
        asm volatile("cp.async.commit_group;");
    };

    load_stage(0, 0);
    load_stage(1, 1);

    const int r8 = lane >> 2;
    const int c4 = lane & 3;

    for (int kt = 0; kt < kTiles; kt++) {
        if (kt + 1 < kTiles) asm volatile("cp.async.wait_group 1;");
        else                 asm volatile("cp.async.wait_group 0;");
        __syncthreads();
        if (kt + 2 < kTiles) load_stage(kt + 2, (kt + 2) % 3);

        const float* as = As[kt % 3];
        const float* bs = Bs[kt % 3];
#pragma unroll
        for (int k8 = 0; k8 < 4; k8++) {
            const int kb = k8 * 8;
            unsigned af[4][4], bf[4][2];
#pragma unroll
            for (int mt = 0; mt < 4; mt++) {
                int row = wm*64 + mt*16 + r8;
                int col = kb + c4;
                af[mt][0] = __float_as_uint(as[ row     *AS_STRIDE + col    ]);
                af[mt][1] = __float_as_uint(as[(row + 8)*AS_STRIDE + col    ]);
                af[mt][2] = __float_as_uint(as[ row     *AS_STRIDE + col + 4]);
                af[mt][3] = __float_as_uint(as[(row + 8)*AS_STRIDE + col + 4]);
            }
#pragma unroll
            for (int nt = 0; nt < 4; nt++) {
                int col = wn*32 + nt*8 + r8;
                int krow = kb + c4;
                bf[nt][0] = __float_as_uint(bs[ krow     *BS_STRIDE + col]);
                bf[nt][1] = __float_as_uint(bs[(krow + 4)*BS_STRIDE + col]);
            }
#pragma unroll
            for (int mt = 0; mt < 4; mt++)
#pragma unroll
                for (int nt = 0; nt < 4; nt++)
                    MMA_TF32(acc[mt][nt], af[mt][0], af[mt][1], af[mt][2],
                             af[mt][3], bf[nt][0], bf[nt][1]);
        }
    }

    // ---- epilogue ----
#pragma unroll
    for (int mt = 0; mt < 4; mt++) {
        int row0 = bm + wm*64 + mt*16 + r8;
#pragma unroll
        for (int nt = 0; nt < 4; nt++) {
            int col0 = bn + wn*32 + nt*8 + c4*2;
            float b0 = 0.f, b1 = 0.f;
            if (!PARTIAL) { b0 = __ldg(&bias[col0]); b1 = __ldg(&bias[col0 + 1]); }
#pragma unroll
            for (int half = 0; half < 2; half++) {
                int row = row0 + half*8;
                float v0 = acc[mt][nt][half*2 + 0] + b0;
                float v1 = acc[mt][nt][half*2 + 1] + b1;
                if (GELU) { v0 = v0 * normcdff(v0); v1 = v1 * normcdff(v1); }
                if (RES) {
                    const float2 rr = *(const float2*)&res[(size_t)row*Nc + col0];
                    v0 += rr.x; v1 += rr.y;
                }
                if (ROUND) { v0 = round_tf32(v0); v1 = round_tf32(v1); }
                *(float2*)&Cb[(size_t)row*Nc + col0] = make_float2(v0, v1);
            }
        }
    }
}

// ---------------- split-K reduction: out = p0+p1+p2 + bias + res ----------
__global__ __launch_bounds__(256) void reduce3_kernel(
    const float* __restrict__ p, const float* __restrict__ bias,
    const float* __restrict__ res, float* __restrict__ out, int Nc)
{
    int i = blockIdx.x * 256 + threadIdx.x;   // float4 index
    const size_t tot = (size_t)ROWS * Nc;
    float4 a = ((const float4*)p)[i];
    float4 b = ((const float4*)(p + tot))[i];
    float4 c = ((const float4*)(p + 2*tot))[i];
    float4 r = ((const float4*)res)[i];
    int col = (i*4) % Nc;
    const float4 bi = *(const float4*)&bias[col];
    float4 o;
    o.x = a.x + b.x + c.x + bi.x + r.x;
    o.y = a.y + b.y + c.y + bi.y + r.y;
    o.z = a.z + b.z + c.z + bi.z + r.z;
    o.w = a.w + b.w + c.w + bi.w + r.w;
    ((float4*)out)[i] = o;
}

// ---------------- Tensor-core flash attention (mma.sync) ----------------
#define AT_STR 72

__global__ __launch_bounds__(256) void attn_tc(
    const float* __restrict__ qkv, const float* __restrict__ adj,
    float* __restrict__ out)
{
    extern __shared__ float sma[];
    float* Qs = sma;               // [128][AT_STR]
    float* Ps = Qs + 128*AT_STR;   // [128][AT_STR]
    float* Ks = Ps + 128*AT_STR;   // [64][AT_STR]
    float* Vs = Ks + 64*AT_STR;    // [64][AT_STR]

    const int tid  = threadIdx.x;
    const int lane = tid & 31;
    const int warp = tid >> 5;
    const int r8   = lane >> 2;
    const int c4   = lane & 3;
    const int bh   = blockIdx.y;
    const int b    = bh / Hh, h = bh % Hh;
    const int q0   = blockIdx.x * 128;
    const int qrow = (warp >> 2)*64 + (warp & 3)*16;
    const float scale = 0.125f;

#pragma unroll
    for (int it = 0; it < 32; it++) {
        int idx = tid + it*256;
        int r = idx >> 6, d = idx & 63;
        Qs[r*AT_STR + d] = qkv[(size_t)(b*Nseq + q0 + r)*(3*Dmod) + h*DHd + d];
    }

    float m0 = -1e30f, m1 = -1e30f, l0 = 0.f, l1 = 0.f;
    float o[8][4];
#pragma unroll
    for (int nt = 0; nt < 8; nt++)
#pragma unroll
        for (int r = 0; r < 4; r++) o[nt][r] = 0.f;

    __syncthreads();

    for (int kt = 0; kt < Nseq/64; kt++) {
        const int k0 = kt*64;
#pragma unroll
        for (int it = 0; it < 16; it++) {
            int idx = tid + it*256;
            int r = idx >> 6, d = idx & 63;
            size_t base = (size_t)(b*Nseq + k0 + r)*(3*Dmod) + h*DHd + d;
            Ks[r*AT_STR + d] = qkv[base +   Dmod];
            Vs[r*AT_STR + d] = qkv[base + 2*Dmod];
        }
        __syncthreads();

        float s[8][4];
#pragma unroll
        for (int nt = 0; nt < 8; nt++)
#pragma unroll
            for (int r = 0; r < 4; r++) s[nt][r] = 0.f;

#pragma unroll
        for (int k8 = 0; k8 < 8; k8++) {
            const int kb = k8*8;
            unsigned a0 = __float_as_uint(Qs[(qrow + r8    )*AT_STR + kb + c4    ]);
            unsigned a1 = __float_as_uint(Qs[(qrow + r8 + 8)*AT_STR + kb + c4    ]);
            unsigned a2 = __float_as_uint(Qs[(qrow + r8    )*AT_STR + kb + c4 + 4]);
            unsigned a3 = __float_as_uint(Qs[(qrow + r8 + 8)*AT_STR + kb + c4 + 4]);
#pragma unroll
            for (int nt = 0; nt < 8; nt++) {
                unsigned b0 = __float_as_uint(Ks[(nt*8 + r8)*AT_STR + kb + c4    ]);
                unsigned b1 = __float_as_uint(Ks[(nt*8 + r8)*AT_STR + kb + c4 + 4]);
                MMA_TF32(s[nt], a0, a1, a2, a3, b0, b1);
            }
        }

        const int qg0 = q0 + qrow + r8;
#pragma unroll
        for (int nt = 0; nt < 8; nt++) {
            int col = k0 + nt*8 + c4*2;
            float2 ad0 = *(const float2*)&adj[(size_t) qg0     *Nseq + col];
            float2 ad1 = *(const float2*)&adj[(size_t)(qg0 + 8)*Nseq + col];
            s[nt][0] = s[nt][0]*scale + ad0.x;
            s[nt][1] = s[nt][1]*scale + ad0.y;
            s[nt][2] = s[nt][2]*scale + ad1.x;
            s[nt][3] = s[nt][3]*scale + ad1.y;
        }

        float mx0 = -1e30f, mx1 = -1e30f;
#pragma unroll
        for (int nt = 0; nt < 8; nt++) {
            mx0 = fmaxf(mx0, fmaxf(s[nt][0], s[nt][1]));
            mx1 = fmaxf(mx1, fmaxf(s[nt][2], s[nt][3]));
        }
        mx0 = fmaxf(mx0, __shfl_xor_sync(0xffffffffu, mx0, 1));
        mx0 = fmaxf(mx0, __shfl_xor_sync(0xffffffffu, mx0, 2));
        mx1 = fmaxf(mx1, __shfl_xor_sync(0xffffffffu, mx1, 1));
        mx1 = fmaxf(mx1, __shfl_xor_sync(0xffffffffu, mx1, 2));
        float mn0 = fmaxf(m0, mx0), mn1 = fmaxf(m1, mx1);
        float al0 = __expf(m0 - mn0), al1 = __expf(m1 - mn1);
        float rs0 = 0.f, rs1 = 0.f;
#pragma unroll
        for (int nt = 0; nt < 8; nt++) {
            s[nt][0] = __expf(s[nt][0] - mn0);
            s[nt][1] = __expf(s[nt][1] - mn0);
            s[nt][2] = __expf(s[nt][2] - mn1);
            s[nt][3] = __expf(s[nt][3] - mn1);
            rs0 += s[nt][0] + s[nt][1];
            rs1 += s[nt][2] + s[nt][3];
        }
        rs0 += __shfl_xor_sync(0xffffffffu, rs0, 1);
        rs0 += __shfl_xor_sync(0xffffffffu, rs0, 2);
        rs1 += __shfl_xor_sync(0xffffffffu, rs1, 1);
        rs1 += __shfl_xor_sync(0xffffffffu, rs1, 2);
        l0 = l0*al0 + rs0;  l1 = l1*al1 + rs1;
        m0 = mn0;           m1 = mn1;
#pragma unroll
        for (int nt = 0; nt < 8; nt++) {
            o[nt][0] *= al0; o[nt][1] *= al0;
            o[nt][2] *= al1; o[nt][3] *= al1;
        }

#pragma unroll
        for (int nt = 0; nt < 8; nt++) {
            *(float2*)&Ps[(qrow + r8    )*AT_STR + nt*8 + c4*2] =
                make_float2(s[nt][0], s[nt][1]);
            *(float2*)&Ps[(qrow + r8 + 8)*AT_STR + nt*8 + c4*2] =
                make_float2(s[nt][2], s[nt][3]);
        }
        __syncwarp();

#pragma unroll
        for (int k8 = 0; k8 < 8; k8++) {
            const int kb = k8*8;
            unsigned a0 = __float_as_uint(Ps[(qrow + r8    )*AT_STR + kb + c4    ]);
            unsigned a1 = __float_as_uint(Ps[(qrow + r8 + 8)*AT_STR + kb + c4    ]);
            unsigned a2 = __float_as_uint(Ps[(qrow + r8    )*AT_STR + kb + c4 + 4]);
            unsigned a3 = __float_as_uint(Ps[(qrow + r8 + 8)*AT_STR + kb + c4 + 4]);
#pragma unroll
            for (int nt = 0; nt < 8; nt++) {
                unsigned b0 = __float_as_uint(Vs[(kb + c4    )*AT_STR + nt*8 + r8]);
                unsigned b1 = __float_as_uint(Vs[(kb + c4 + 4)*AT_STR + nt*8 + r8]);
                MMA_TF32(o[nt], a0, a1, a2, a3, b0, b1);
            }
        }
        __syncthreads();
    }

    const int qg0 = q0 + qrow + r8;
    float i0 = 1.f / l0, i1 = 1.f / l1;
#pragma unroll
    for (int nt = 0; nt < 8; nt++) {
        int col = h*DHd + nt*8 + c4*2;
        *(float2*)&out[(size_t)(b*Nseq + qg0    )*Dmod + col] =
            make_float2(round_tf32(o[nt][0]*i0), round_tf32(o[nt][1]*i0));
        *(float2*)&out[(size_t)(b*Nseq + qg0 + 8)*Dmod + col] =
            make_float2(round_tf32(o[nt][2]*i1), round_tf32(o[nt][3]*i1));
    }
}

// ---------------- launcher ----------------
extern "C" void kernel_launch(void* const* d_in, const int* in_sizes, int n_in,
                              void* d_out, int out_size)
{
    const float* x      = (const float*)d_in[0];
    const float* adj    = (const float*)d_in[1];
    const float* ln1_g  = (const float*)d_in[2];
    const float* ln1_b  = (const float*)d_in[3];
    const float* qkv_w  = (const float*)d_in[4];
    const float* qkv_b  = (const float*)d_in[5];
    const float* proj_w = (const float*)d_in[6];
    const float* proj_b = (const float*)d_in[7];
    const float* ln2_g  = (const float*)d_in[8];
    const float* ln2_b  = (const float*)d_in[9];
    const float* fc1_w  = (const float*)d_in[10];
    const float* fc1_b  = (const float*)d_in[11];
    const float* fc2_w  = (const float*)d_in[12];
    const float* fc2_b  = (const float*)d_in[13];
    float* out = (float*)d_out;

    float *h, *qkv, *attn, *x1, *h2, *act, *part;
    cudaGetSymbolAddress((void**)&h,    g_h);
    cudaGetSymbolAddress((void**)&qkv,  g_qkv);
    cudaGetSymbolAddress((void**)&attn, g_attn);
    cudaGetSymbolAddress((void**)&x1,   g_x1);
    cudaGetSymbolAddress((void**)&h2,   g_h2);
    cudaGetSymbolAddress((void**)&act,  g_act);
    cudaGetSymbolAddress((void**)&part, g_part);

    const int attn_smem = (128 + 128 + 64 + 64) * AT_STR * sizeof(float);
    static int init = 0;
    if (!init) {
        cudaFuncSetAttribute(gemm_tc<false,false,false,false>,
            cudaFuncAttributeMaxDynamicSharedMemorySize, GEMM_SMEM);
        cudaFuncSetAttribute(gemm_tc<true,false,true,false>,
            cudaFuncAttributeMaxDynamicSharedMemorySize, GEMM_SMEM);
        cudaFuncSetAttribute(gemm_tc<false,false,false,true>,
            cudaFuncAttributeMaxDynamicSharedMemorySize, GEMM_SMEM);
        cudaFuncSetAttribute(attn_tc,
            cudaFuncAttributeMaxDynamicSharedMemorySize, attn_smem);
        init = 1;
    }

    // 1. LN1
    ln_kernel<<<ROWS, 256>>>(x, ln1_g, ln1_b, h);
    // 2. qkv = h @ qkv_w + qkv_b
    gemm_tc<false,false,false,false><<<dim3(18, 32, 1), 256, GEMM_SMEM>>>(
        h, qkv_w, qkv_b, nullptr, qkv, ROWS, Dmod, 3*Dmod, Dmod);
    // 3. attention
    attn_tc<<<dim3(Nseq/128, Bsz*Hh), 256, attn_smem>>>(qkv, adj, attn);
    // 4. x1 = x + attn @ proj_w + proj_b   (split-K=3: 256 each)
    gemm_tc<false,false,false,true><<<dim3(6, 32, 3), 256, GEMM_SMEM>>>(
        attn, proj_w, proj_b, nullptr, part, ROWS, Dmod, Dmod, Dmod/3);
    reduce3_kernel<<<ROWS*Dmod/4/256, 256>>>(part, proj_b, x, x1, Dmod);
    // 5. LN2
    ln_kernel<<<ROWS, 256>>>(x1, ln2_g, ln2_b, h2);
    // 6. act = gelu(h2 @ fc1_w + fc1_b)
    gemm_tc<true,false,true,false><<<dim3(24, 32, 1), 256, GEMM_SMEM>>>(
        h2, fc1_w, fc1_b, nullptr, act, ROWS, Dmod, HID, Dmod);
    // 7. out = x1 + act @ fc2_w + fc2_b    (split-K=3: 1024 each)
    gemm_tc<false,false,false,true><<<dim3(6, 32, 3), 256, GEMM_SMEM>>>(
        act, fc2_w, fc2_b, nullptr, part, ROWS, HID, Dmod, HID/3);
    reduce3_kernel<<<ROWS*Dmod/4/256, 256>>>(part, fc2_b, x1, out, Dmod);
}

// round 8
// speedup vs baseline: 3.4775x; 1.1777x over previous
#include <cuda_runtime.h>
#include <math.h>
#include <stdint.h>

#define Bsz  4
#define Nseq 1024
#define Dmod 768
#define Hh   12
#define DHd  64
#define HID  3072
#define ROWS (Bsz*Nseq)   // 4096

// ---- scratch (no cudaMalloc allowed) ----
__device__ float g_h   [ROWS*Dmod];
__device__ float g_qkv [ROWS*3*Dmod];
__device__ float g_attn[ROWS*Dmod];
__device__ float g_x1  [ROWS*Dmod];
__device__ float g_h2  [ROWS*Dmod];
__device__ float g_act [ROWS*HID];
__device__ float g_part[3*ROWS*Dmod];   // split-K partials

__device__ __forceinline__ float round_tf32(float x) {
    unsigned r;
    asm("cvt.rna.tf32.f32 %0, %1;" : "=r"(r) : "f"(x));
    return __uint_as_float(r);
}

#define MMA_TF32(acc, a0,a1,a2,a3, b0,b1)                                   \
    asm volatile(                                                           \
        "mma.sync.aligned.m16n8k8.row.col.f32.tf32.tf32.f32 "               \
        "{%0,%1,%2,%3}, {%4,%5,%6,%7}, {%8,%9}, {%0,%1,%2,%3};"             \
        : "+f"(acc[0]), "+f"(acc[1]), "+f"(acc[2]), "+f"(acc[3])            \
        : "r"(a0), "r"(a1), "r"(a2), "r"(a3), "r"(b0), "r"(b1))

#define LDSM_X4(r, addr)                                                    \
    asm volatile("ldmatrix.sync.aligned.m8n8.x4.shared.b16 {%0,%1,%2,%3}, [%4];" \
        : "=r"((r)[0]), "=r"((r)[1]), "=r"((r)[2]), "=r"((r)[3]) : "r"(addr))

#define LDSM_X2(r0, r1, addr)                                               \
    asm volatile("ldmatrix.sync.aligned.m8n8.x2.shared.b16 {%0,%1}, [%2];"  \
        : "=r"(r0), "=r"(r1) : "r"(addr))

__device__ __forceinline__ void cp16(unsigned dst, const void* src) {
    asm volatile("cp.async.cg.shared.global [%0], [%1], 16;" :: "r"(dst), "l"(src));
}

// ---------------- LayerNorm: one block per row (tf32-rounded output) -------
__global__ __launch_bounds__(256) void ln_kernel(
    const float* __restrict__ x, const float* __restrict__ g,
    const float* __restrict__ b, float* __restrict__ out)
{
    int row = blockIdx.x;
    const float* xr = x + (size_t)row * Dmod;
    float v[3];
    float s = 0.f, s2 = 0.f;
#pragma unroll
    for (int it = 0; it < 3; it++) {
        v[it] = xr[threadIdx.x + it*256];
        s += v[it]; s2 += v[it]*v[it];
    }
#pragma unroll
    for (int off = 16; off; off >>= 1) {
        s  += __shfl_xor_sync(0xffffffffu, s,  off);
        s2 += __shfl_xor_sync(0xffffffffu, s2, off);
    }
    __shared__ float ws[8], ws2[8];
    __shared__ float mu_s, rs_s;
    int wid = threadIdx.x >> 5, lane = threadIdx.x & 31;
    if (lane == 0) { ws[wid] = s; ws2[wid] = s2; }
    __syncthreads();
    if (threadIdx.x == 0) {
        float S = 0.f, S2 = 0.f;
#pragma unroll
        for (int i = 0; i < 8; i++) { S += ws[i]; S2 += ws2[i]; }
        float mu  = S * (1.f/Dmod);
        float var = S2 * (1.f/Dmod) - mu*mu;
        mu_s = mu;
        rs_s = rsqrtf(var + 1e-6f);
    }
    __syncthreads();
    float mu = mu_s, rs = rs_s;
#pragma unroll
    for (int it = 0; it < 3; it++) {
        int i = threadIdx.x + it*256;
        out[(size_t)row*Dmod + i] = round_tf32((v[it]-mu)*rs*g[i] + b[i]);
    }
}

// ---------------- tf32 tensor-core GEMM 128x128, 3-stage, LDSM A-frags -----
#define AS_STRIDE 36   // 32 + 4 pad
#define BS_STRIDE 136  // 128 + 8 pad
#define STAGE_FLOATS (128*AS_STRIDE + 32*BS_STRIDE)   // 8960 floats
#define GEMM_SMEM (3*STAGE_FLOATS*4)                  // 107520 B

template<bool GELU, bool RES, bool ROUND, bool PARTIAL>
__global__ __launch_bounds__(256, 2) void gemm_tc(
    const float* __restrict__ A, const float* __restrict__ W,
    const float* __restrict__ bias, const float* __restrict__ res,
    float* __restrict__ C, int M, int Kfull, int Nc, int Ks)
{
    extern __shared__ float sm[];
    float* As[3] = { sm,                 sm + STAGE_FLOATS,
                     sm + 2*STAGE_FLOATS };
    float* Bs[3] = { sm + 128*AS_STRIDE, sm + STAGE_FLOATS + 128*AS_STRIDE,
                     sm + 2*STAGE_FLOATS + 128*AS_STRIDE };

    const int tid  = threadIdx.x;
    const int lane = tid & 31;
    const int warp = tid >> 5;
    const int wm   = warp & 1;
    const int wn   = warp >> 1;
    const int bm   = blockIdx.y * 128;
    const int bn   = blockIdx.x * 128;
    const int z    = blockIdx.z;

    const float* Ab = A + (size_t)z * Ks;
    const float* Wb = W + (size_t)z * Ks * Nc;
    float* Cb = PARTIAL ? (C + (size_t)z * M * Nc) : C;

    float acc[4][4][4];
#pragma unroll
    for (int i = 0; i < 4; i++)
#pragma unroll
        for (int j = 0; j < 4; j++)
#pragma unroll
            for (int r = 0; r < 4; r++) acc[i][j][r] = 0.f;

    const int kTiles = Ks >> 5;

    auto load_stage = [&](int kt, int buf) {
        const int k0 = kt * 32;
#pragma unroll
        for (int i = 0; i < 4; i++) {
            int idx = tid + i*256;
            int r = idx >> 3, kk = (idx & 7) * 4;
            cp16((unsigned)__cvta_generic_to_shared(&As[buf][r*AS_STRIDE + kk]),
                 Ab + (size_t)(bm + r) * Kfull + k0 + kk);
        }
#pragma unroll
        for (int i = 0; i < 4; i++) {
            int idx = tid + i*256;
            int kr = idx >> 5, n = (idx & 31) * 4;
            cp16((unsigned)__cvta_generic_to_shared(&Bs[buf][kr*BS_STRIDE + n]),
                 Wb + (size_t)(k0 + kr) * Nc + bn + n);
        }
        asm volatile("cp.async.commit_group;");
    };

    load_stage(0, 0);
    load_stage(1, 1);

    const int r8 = lane >> 2;
    const int c4 = lane & 3;
    // LDSM lane address components: matrix m = lane>>3 (x4)
    // row_add = (m&1)*8 + (lane&7); col_add = (m>>1)*4
    const int lrow = ((lane >> 3) & 1) * 8 + (lane & 7);
    const int lcol = (lane >> 4) * 4;
    // byte offsets of each mt's fragment base within an A stage
    uint32_t a_off[4];
#pragma unroll
    for (int mt = 0; mt < 4; mt++)
        a_off[mt] = ((wm*64 + mt*16 + lrow)*AS_STRIDE + lcol) * 4u;

    for (int kt = 0; kt < kTiles; kt++) {
        if (kt + 1 < kTiles) asm volatile("cp.async.wait_group 1;");
        else                 asm volatile("cp.async.wait_group 0;");
        __syncthreads();
        if (kt + 2 < kTiles) load_stage(kt + 2, (kt + 2) % 3);

        const float* as = As[kt % 3];
        const float* bs = Bs[kt % 3];
        const uint32_t as_u32 = (uint32_t)__cvta_generic_to_shared(as);
#pragma unroll
        for (int k8 = 0; k8 < 4; k8++) {
            const int kb = k8 * 8;
            unsigned af[4][4], bf[4][2];
#pragma unroll
            for (int mt = 0; mt < 4; mt++)
                LDSM_X4(af[mt], as_u32 + a_off[mt] + k8*32u);
#pragma unroll
            for (int nt = 0; nt < 4; nt++) {
                int col = wn*32 + nt*8 + r8;
                int krow = kb + c4;
                bf[nt][0] = __float_as_uint(bs[ krow     *BS_STRIDE + col]);
                bf[nt][1] = __float_as_uint(bs[(krow + 4)*BS_STRIDE + col]);
            }
#pragma unroll
            for (int mt = 0; mt < 4; mt++)
#pragma unroll
                for (int nt = 0; nt < 4; nt++)
                    MMA_TF32(acc[mt][nt], af[mt][0], af[mt][1], af[mt][2],
                             af[mt][3], bf[nt][0], bf[nt][1]);
        }
    }

    // ---- epilogue ----
#pragma unroll
    for (int mt = 0; mt < 4; mt++) {
        int row0 = bm + wm*64 + mt*16 + r8;
#pragma unroll
        for (int nt = 0; nt < 4; nt++) {
            int col0 = bn + wn*32 + nt*8 + c4*2;
            float b0 = 0.f, b1 = 0.f;
            if (!PARTIAL) { b0 = __ldg(&bias[col0]); b1 = __ldg(&bias[col0 + 1]); }
#pragma unroll
            for (int half = 0; half < 2; half++) {
                int row = row0 + half*8;
                float v0 = acc[mt][nt][half*2 + 0] + b0;
                float v1 = acc[mt][nt][half*2 + 1] + b1;
                if (GELU) { v0 = v0 * normcdff(v0); v1 = v1 * normcdff(v1); }
                if (RES) {
                    const float2 rr = *(const float2*)&res[(size_t)row*Nc + col0];
                    v0 += rr.x; v1 += rr.y;
                }
                if (ROUND) { v0 = round_tf32(v0); v1 = round_tf32(v1); }
                *(float2*)&Cb[(size_t)row*Nc + col0] = make_float2(v0, v1);
            }
        }
    }
}

// ---------------- split-K reduction: out = p0+p1+p2 + bias + res ----------
__global__ __launch_bounds__(256) void reduce3_kernel(
    const float* __restrict__ p, const float* __restrict__ bias,
    const float* __restrict__ res, float* __restrict__ out, int Nc)
{
    int i = blockIdx.x * 256 + threadIdx.x;   // float4 index
    const size_t tot = (size_t)ROWS * Nc;
    float4 a = ((const float4*)p)[i];
    float4 b = ((const float4*)(p + tot))[i];
    float4 c = ((const float4*)(p + 2*tot))[i];
    float4 r = ((const float4*)res)[i];
    int col = (i*4) % Nc;
    const float4 bi = *(const float4*)&bias[col];
    float4 o;
    o.x = a.x + b.x + c.x + bi.x + r.x;
    o.y = a.y + b.y + c.y + bi.y + r.y;
    o.z = a.z + b.z + c.z + bi.z + r.z;
    o.w = a.w + b.w + c.w + bi.w + r.w;
    ((float4*)out)[i] = o;
}

// ---------------- Tensor-core flash attention (LDSM, conflict-free) --------
#define QP_STR 68   // Q/P/K stride: 4-bank shift/row -> conflict-free
#define V_STR  72   // V stride: 8-bank shift/row -> conflict-free for [k][n] frag

__global__ __launch_bounds__(256) void attn_tc(
    const float* __restrict__ qkv, const float* __restrict__ adj,
    float* __restrict__ out)
{
    extern __shared__ float sma[];
    float* Qs = sma;               // [128][QP_STR]
    float* Ps = Qs + 128*QP_STR;   // [128][QP_STR]
    float* Ks = Ps + 128*QP_STR;   // [64][QP_STR]
    float* Vs = Ks + 64*QP_STR;    // [64][V_STR]

    const int tid  = threadIdx.x;
    const int lane = tid & 31;
    const int warp = tid >> 5;
    const int r8   = lane >> 2;
    const int c4   = lane & 3;
    const int bh   = blockIdx.y;
    const int b    = bh / Hh, h = bh % Hh;
    const int q0   = blockIdx.x * 128;
    const int qrow = (warp >> 2)*64 + (warp & 3)*16;
    const float scale = 0.125f;

    // LDSM address components
    const int lrow = ((lane >> 3) & 1) * 8 + (lane & 7);   // x4 row add
    const int lcol = (lane >> 4) * 4;                      // x4 col add
    const int krow2 = lane & 7;                            // x2 row add
    const int kcol2 = ((lane >> 3) & 1) * 4;               // x2 col add

    const uint32_t qs_u32 = (uint32_t)__cvta_generic_to_shared(Qs);
    const uint32_t ps_u32 = (uint32_t)__cvta_generic_to_shared(Ps);
    const uint32_t ks_u32 = (uint32_t)__cvta_generic_to_shared(Ks);
    const uint32_t q_off  = ((qrow + lrow)*QP_STR + lcol) * 4u;
    const uint32_t k_off  = (krow2*QP_STR + kcol2) * 4u;

#pragma unroll
    for (int it = 0; it < 32; it++) {
        int idx = tid + it*256;
        int r = idx >> 6, d = idx & 63;
        Qs[r*QP_STR + d] = qkv[(size_t)(b*Nseq + q0 + r)*(3*Dmod) + h*DHd + d];
    }

    float m0 = -1e30f, m1 = -1e30f, l0 = 0.f, l1 = 0.f;
    float o[8][4];
#pragma unroll
    for (int nt = 0; nt < 8; nt++)
#pragma unroll
        for (int r = 0; r < 4; r++) o[nt][r] = 0.f;

    __syncthreads();

    for (int kt = 0; kt < Nseq/64; kt++) {
        const int k0 = kt*64;
#pragma unroll
        for (int it = 0; it < 16; it++) {
            int idx = tid + it*256;
            int r = idx >> 6, d = idx & 63;
            size_t base = (size_t)(b*Nseq + k0 + r)*(3*Dmod) + h*DHd + d;
            Ks[r*QP_STR + d] = qkv[base +   Dmod];
            Vs[r*V_STR  + d] = qkv[base + 2*Dmod];
        }
        __syncthreads();

        // ---- S = Q @ K^T ----
        float s[8][4];
#pragma unroll
        for (int nt = 0; nt < 8; nt++)
#pragma unroll
            for (int r = 0; r < 4; r++) s[nt][r] = 0.f;

#pragma unroll
        for (int k8 = 0; k8 < 8; k8++) {
            unsigned aq[4];
            LDSM_X4(aq, qs_u32 + q_off + k8*32u);
#pragma unroll
            for (int nt = 0; nt < 8; nt++) {
                unsigned b0, b1;
                LDSM_X2(b0, b1, ks_u32 + k_off + nt*(8u*QP_STR*4u) + k8*32u);
                MMA_TF32(s[nt], aq[0], aq[1], aq[2], aq[3], b0, b1);
            }
        }

        // ---- scale + adjacency bias ----
        const int qg0 = q0 + qrow + r8;
#pragma unroll
        for (int nt = 0; nt < 8; nt++) {
            int col = k0 + nt*8 + c4*2;
            float2 ad0 = *(const float2*)&adj[(size_t) qg0     *Nseq + col];
            float2 ad1 = *(const float2*)&adj[(size_t)(qg0 + 8)*Nseq + col];
            s[nt][0] = s[nt][0]*scale + ad0.x;
            s[nt][1] = s[nt][1]*scale + ad0.y;
            s[nt][2] = s[nt][2]*scale + ad1.x;
            s[nt][3] = s[nt][3]*scale + ad1.y;
        }

        // ---- online softmax ----
        float mx0 = -1e30f, mx1 = -1e30f;
#pragma unroll
        for (int nt = 0; nt < 8; nt++) {
            mx0 = fmaxf(mx0, fmaxf(s[nt][0], s[nt][1]));
            mx1 = fmaxf(mx1, fmaxf(s[nt][2], s[nt][3]));
        }
        mx0 = fmaxf(mx0, __shfl_xor_sync(0xffffffffu, mx0, 1));
        mx0 = fmaxf(mx0, __shfl_xor_sync(0xffffffffu, mx0, 2));
        mx1 = fmaxf(mx1, __shfl_xor_sync(0xffffffffu, mx1, 1));
        mx1 = fmaxf(mx1, __shfl_xor_sync(0xffffffffu, mx1, 2));
        float mn0 = fmaxf(m0, mx0), mn1 = fmaxf(m1, mx1);
        float al0 = __expf(m0 - mn0), al1 = __expf(m1 - mn1);
        float rs0 = 0.f, rs1 = 0.f;
#pragma unroll
        for (int nt = 0; nt < 8; nt++) {
            s[nt][0] = __expf(s[nt][0] - mn0);
            s[nt][1] = __expf(s[nt][1] - mn0);
            s[nt][2] = __expf(s[nt][2] - mn1);
            s[nt][3] = __expf(s[nt][3] - mn1);
            rs0 += s[nt][0] + s[nt][1];
            rs1 += s[nt][2] + s[nt][3];
        }
        rs0 += __shfl_xor_sync(0xffffffffu, rs0, 1);
        rs0 += __shfl_xor_sync(0xffffffffu, rs0, 2);
        rs1 += __shfl_xor_sync(0xffffffffu, rs1, 1);
        rs1 += __shfl_xor_sync(0xffffffffu, rs1, 2);
        l0 = l0*al0 + rs0;  l1 = l1*al1 + rs1;
        m0 = mn0;           m1 = mn1;
#pragma unroll
        for (int nt = 0; nt < 8; nt++) {
            o[nt][0] *= al0; o[nt][1] *= al0;
            o[nt][2] *= al1; o[nt][3] *= al1;
        }

        // ---- write P (own rows only) ----
#pragma unroll
        for (int nt = 0; nt < 8; nt++) {
            *(float2*)&Ps[(qrow + r8    )*QP_STR + nt*8 + c4*2] =
                make_float2(s[nt][0], s[nt][1]);
            *(float2*)&Ps[(qrow + r8 + 8)*QP_STR + nt*8 + c4*2] =
                make_float2(s[nt][2], s[nt][3]);
        }
        __syncwarp();

        // ---- O += P @ V ----
#pragma unroll
        for (int k8 = 0; k8 < 8; k8++) {
            const int kb = k8*8;
            unsigned ap[4];
            LDSM_X4(ap, ps_u32 + q_off + k8*32u);
#pragma unroll
            for (int nt = 0; nt < 8; nt++) {
                unsigned b0 = __float_as_uint(Vs[(kb + c4    )*V_STR + nt*8 + r8]);
                unsigned b1 = __float_as_uint(Vs[(kb + c4 + 4)*V_STR + nt*8 + r8]);
                MMA_TF32(o[nt], ap[0], ap[1], ap[2], ap[3], b0, b1);
            }
        }
        __syncthreads();
    }

    // ---- epilogue: normalize + write ----
    const int qg0 = q0 + qrow + r8;
    float i0 = 1.f / l0, i1 = 1.f / l1;
#pragma unroll
    for (int nt = 0; nt < 8; nt++) {
        int col = h*DHd + nt*8 + c4*2;
        *(float2*)&out[(size_t)(b*Nseq + qg0    )*Dmod + col] =
            make_float2(round_tf32(o[nt][0]*i0), round_tf32(o[nt][1]*i0));
        *(float2*)&out[(size_t)(b*Nseq + qg0 + 8)*Dmod + col] =
            make_float2(round_tf32(o[nt][2]*i1), round_tf32(o[nt][3]*i1));
    }
}

// ---------------- launcher ----------------
extern "C" void kernel_launch(void* const* d_in, const int* in_sizes, int n_in,
                              void* d_out, int out_size)
{
    const float* x      = (const float*)d_in[0];
    const float* adj    = (const float*)d_in[1];
    const float* ln1_g  = (const float*)d_in[2];
    const float* ln1_b  = (const float*)d_in[3];
    const float* qkv_w  = (const float*)d_in[4];
    const float* qkv_b  = (const float*)d_in[5];
    const float* proj_w = (const float*)d_in[6];
    const float* proj_b = (const float*)d_in[7];
    const float* ln2_g  = (const float*)d_in[8];
    const float* ln2_b  = (const float*)d_in[9];
    const float* fc1_w  = (const float*)d_in[10];
    const float* fc1_b  = (const float*)d_in[11];
    const float* fc2_w  = (const float*)d_in[12];
    const float* fc2_b  = (const float*)d_in[13];
    float* out = (float*)d_out;

    float *h, *qkv, *attn, *x1, *h2, *act, *part;
    cudaGetSymbolAddress((void**)&h,    g_h);
    cudaGetSymbolAddress((void**)&qkv,  g_qkv);
    cudaGetSymbolAddress((void**)&attn, g_attn);
    cudaGetSymbolAddress((void**)&x1,   g_x1);
    cudaGetSymbolAddress((void**)&h2,   g_h2);
    cudaGetSymbolAddress((void**)&act,  g_act);
    cudaGetSymbolAddress((void**)&part, g_part);

    const int attn_smem = (128*QP_STR + 128*QP_STR + 64*QP_STR + 64*V_STR)
                          * sizeof(float);   // ~105.5 KB
    static int init = 0;
    if (!init) {
        cudaFuncSetAttribute(gemm_tc<false,false,false,false>,
            cudaFuncAttributeMaxDynamicSharedMemorySize, GEMM_SMEM);
        cudaFuncSetAttribute(gemm_tc<true,false,true,false>,
            cudaFuncAttributeMaxDynamicSharedMemorySize, GEMM_SMEM);
        cudaFuncSetAttribute(gemm_tc<false,false,false,true>,
            cudaFuncAttributeMaxDynamicSharedMemorySize, GEMM_SMEM);
        cudaFuncSetAttribute(attn_tc,
            cudaFuncAttributeMaxDynamicSharedMemorySize, attn_smem);
        init = 1;
    }

    // 1. LN1
    ln_kernel<<<ROWS, 256>>>(x, ln1_g, ln1_b, h);
    // 2. qkv = h @ qkv_w + qkv_b
    gemm_tc<false,false,false,false><<<dim3(18, 32, 1), 256, GEMM_SMEM>>>(
        h, qkv_w, qkv_b, nullptr, qkv, ROWS, Dmod, 3*Dmod, Dmod);
    // 3. attention
    attn_tc<<<dim3(Nseq/128, Bsz*Hh), 256, attn_smem>>>(qkv, adj, attn);
    // 4. x1 = x + attn @ proj_w + proj_b   (split-K=3)
    gemm_tc<false,false,false,true><<<dim3(6, 32, 3), 256, GEMM_SMEM>>>(
        attn, proj_w, proj_b, nullptr, part, ROWS, Dmod, Dmod, Dmod/3);
    reduce3_kernel<<<ROWS*Dmod/4/256, 256>>>(part, proj_b, x, x1, Dmod);
    // 5. LN2
    ln_kernel<<<ROWS, 256>>>(x1, ln2_g, ln2_b, h2);
    // 6. act = gelu(h2 @ fc1_w + fc1_b)
    gemm_tc<true,false,true,false><<<dim3(24, 32, 1), 256, GEMM_SMEM>>>(
        h2, fc1_w, fc1_b, nullptr, act, ROWS, Dmod, HID, Dmod);
    // 7. out = x1 + act @ fc2_w + fc2_b    (split-K=3)
    gemm_tc<false,false,false,true><<<dim3(6, 32, 3), 256, GEMM_SMEM>>>(
        act, fc2_w, fc2_b, nullptr, part, ROWS, HID, Dmod, HID/3);
    reduce3_kernel<<<ROWS*Dmod/4/256, 256>>>(part, fc2_b, x1, out, Dmod);
}

// round 9
// speedup vs baseline: 3.6497x; 1.0495x over previous
#include <cuda_runtime.h>
#include <math.h>
#include <stdint.h>

#define Bsz  4
#define Nseq 1024
#define Dmod 768
#define Hh   12
#define DHd  64
#define HID  3072
#define ROWS (Bsz*Nseq)   // 4096

// ---- scratch (no cudaMalloc allowed) ----
__device__ float g_h   [ROWS*Dmod];
__device__ float g_qkv [ROWS*3*Dmod];
__device__ float g_attn[ROWS*Dmod];
__device__ float g_x1  [ROWS*Dmod];
__device__ float g_h2  [ROWS*Dmod];
__device__ float g_act [ROWS*HID];
__device__ float g_part[3*ROWS*Dmod];   // split-K partials

__device__ __forceinline__ float round_tf32(float x) {
    unsigned r;
    asm("cvt.rna.tf32.f32 %0, %1;" : "=r"(r) : "f"(x));
    return __uint_as_float(r);
}

#define MMA_TF32(acc, a0,a1,a2,a3, b0,b1)                                   \
    asm volatile(                                                           \
        "mma.sync.aligned.m16n8k8.row.col.f32.tf32.tf32.f32 "               \
        "{%0,%1,%2,%3}, {%4,%5,%6,%7}, {%8,%9}, {%0,%1,%2,%3};"             \
        : "+f"(acc[0]), "+f"(acc[1]), "+f"(acc[2]), "+f"(acc[3])            \
        : "r"(a0), "r"(a1), "r"(a2), "r"(a3), "r"(b0), "r"(b1))

#define LDSM_X4(r, addr)                                                    \
    asm volatile("ldmatrix.sync.aligned.m8n8.x4.shared.b16 {%0,%1,%2,%3}, [%4];" \
        : "=r"((r)[0]), "=r"((r)[1]), "=r"((r)[2]), "=r"((r)[3]) : "r"(addr))

__device__ __forceinline__ void cp16(unsigned dst, const void* src) {
    asm volatile("cp.async.cg.shared.global [%0], [%1], 16;" :: "r"(dst), "l"(src));
}

// ---------------- warp-per-row LayerNorm (tf32-rounded output) -------------
__global__ __launch_bounds__(256) void ln_warp(
    const float* __restrict__ x, const float* __restrict__ g,
    const float* __restrict__ b, float* __restrict__ out)
{
    const int warp = threadIdx.x >> 5, lane = threadIdx.x & 31;
    const int row  = blockIdx.x * 8 + warp;
    const float4* xr = (const float4*)(x + (size_t)row * Dmod);
    float4 v[6];
    float s = 0.f, s2 = 0.f;
#pragma unroll
    for (int i = 0; i < 6; i++) {
        v[i] = xr[lane + i*32];
        s  += v[i].x + v[i].y + v[i].z + v[i].w;
        s2 += v[i].x*v[i].x + v[i].y*v[i].y + v[i].z*v[i].z + v[i].w*v[i].w;
    }
#pragma unroll
    for (int off = 16; off; off >>= 1) {
        s  += __shfl_xor_sync(0xffffffffu, s,  off);
        s2 += __shfl_xor_sync(0xffffffffu, s2, off);
    }
    const float mu = s * (1.f/Dmod);
    const float rs = rsqrtf(s2 * (1.f/Dmod) - mu*mu + 1e-6f);
    float4* orow = (float4*)(out + (size_t)row * Dmod);
#pragma unroll
    for (int i = 0; i < 6; i++) {
        int c = lane + i*32;
        float4 gg = __ldg(&((const float4*)g)[c]);
        float4 bb = __ldg(&((const float4*)b)[c]);
        float4 o;
        o.x = round_tf32((v[i].x - mu)*rs*gg.x + bb.x);
        o.y = round_tf32((v[i].y - mu)*rs*gg.y + bb.y);
        o.z = round_tf32((v[i].z - mu)*rs*gg.z + bb.z);
        o.w = round_tf32((v[i].w - mu)*rs*gg.w + bb.w);
        orow[c] = o;
    }
}

// ------- fused split-K reduce + residual + LN: x1 and h2 in one pass -------
__global__ __launch_bounds__(256) void reduce3_ln(
    const float* __restrict__ p, const float* __restrict__ bias,
    const float* __restrict__ res, float* __restrict__ x1,
    const float* __restrict__ g, const float* __restrict__ bv,
    float* __restrict__ h2)
{
    const int warp = threadIdx.x >> 5, lane = threadIdx.x & 31;
    const int row  = blockIdx.x * 8 + warp;
    const size_t tot4 = (size_t)ROWS * Dmod / 4;
    const size_t base4 = (size_t)row * (Dmod/4);
    float4 v[6];
    float s = 0.f, s2 = 0.f;
#pragma unroll
    for (int i = 0; i < 6; i++) {
        int c = lane + i*32;
        size_t idx = base4 + c;
        float4 a  = ((const float4*)p)[idx];
        float4 b2 = ((const float4*)p)[idx + tot4];
        float4 c2 = ((const float4*)p)[idx + 2*tot4];
        float4 r  = ((const float4*)res)[idx];
        float4 bi = __ldg(&((const float4*)bias)[c]);
        float4 o;
        o.x = a.x + b2.x + c2.x + bi.x + r.x;
        o.y = a.y + b2.y + c2.y + bi.y + r.y;
        o.z = a.z + b2.z + c2.z + bi.z + r.z;
        o.w = a.w + b2.w + c2.w + bi.w + r.w;
        ((float4*)x1)[idx] = o;
        v[i] = o;
        s  += o.x + o.y + o.z + o.w;
        s2 += o.x*o.x + o.y*o.y + o.z*o.z + o.w*o.w;
    }
#pragma unroll
    for (int off = 16; off; off >>= 1) {
        s  += __shfl_xor_sync(0xffffffffu, s,  off);
        s2 += __shfl_xor_sync(0xffffffffu, s2, off);
    }
    const float mu = s * (1.f/Dmod);
    const float rs = rsqrtf(s2 * (1.f/Dmod) - mu*mu + 1e-6f);
#pragma unroll
    for (int i = 0; i < 6; i++) {
        int c = lane + i*32;
        float4 gg = __ldg(&((const float4*)g)[c]);
        float4 bb = __ldg(&((const float4*)bv)[c]);
        float4 o;
        o.x = round_tf32((v[i].x - mu)*rs*gg.x + bb.x);
        o.y = round_tf32((v[i].y - mu)*rs*gg.y + bb.y);
        o.z = round_tf32((v[i].z - mu)*rs*gg.z + bb.z);
        o.w = round_tf32((v[i].w - mu)*rs*gg.w + bb.w);
        ((float4*)h2)[base4 + c] = o;
    }
}

// ---------------- split-K reduction: out = p0+p1+p2 + bias + res ----------
__global__ __launch_bounds__(256) void reduce3_kernel(
    const float* __restrict__ p, const float* __restrict__ bias,
    const float* __restrict__ res, float* __restrict__ out, int Nc)
{
    int i = blockIdx.x * 256 + threadIdx.x;
    const size_t tot = (size_t)ROWS * Nc;
    float4 a = ((const float4*)p)[i];
    float4 b = ((const float4*)(p + tot))[i];
    float4 c = ((const float4*)(p + 2*tot))[i];
    float4 r = ((const float4*)res)[i];
    int col = (i*4) % Nc;
    const float4 bi = *(const float4*)&bias[col];
    float4 o;
    o.x = a.x + b.x + c.x + bi.x + r.x;
    o.y = a.y + b.y + c.y + bi.y + r.y;
    o.z = a.z + b.z + c.z + bi.z + r.z;
    o.w = a.w + b.w + c.w + bi.w + r.w;
    ((float4*)out)[i] = o;
}

// ---------------- tf32 tensor-core GEMM 128x128, 3-stage, LDSM A-frags -----
#define AS_STRIDE 36
#define BS_STRIDE 136
#define STAGE_FLOATS (128*AS_STRIDE + 32*BS_STRIDE)
#define GEMM_SMEM (3*STAGE_FLOATS*4)

template<bool GELU, bool RES, bool ROUND, bool PARTIAL>
__global__ __launch_bounds__(256, 2) void gemm_tc(
    const float* __restrict__ A, const float* __restrict__ W,
    const float* __restrict__ bias, const float* __restrict__ res,
    float* __restrict__ C, int M, int Kfull, int Nc, int Ks)
{
    extern __shared__ float sm[];
    float* As[3] = { sm,                 sm + STAGE_FLOATS,
                     sm + 2*STAGE_FLOATS };
    float* Bs[3] = { sm + 128*AS_STRIDE, sm + STAGE_FLOATS + 128*AS_STRIDE,
                     sm + 2*STAGE_FLOATS + 128*AS_STRIDE };

    const int tid  = threadIdx.x;
    const int lane = tid & 31;
    const int warp = tid >> 5;
    const int wm   = warp & 1;
    const int wn   = warp >> 1;
    const int bm   = blockIdx.y * 128;
    const int bn   = blockIdx.x * 128;
    const int z    = blockIdx.z;

    const float* Ab = A + (size_t)z * Ks;
    const float* Wb = W + (size_t)z * Ks * Nc;
    float* Cb = PARTIAL ? (C + (size_t)z * M * Nc) : C;

    float acc[4][4][4];
#pragma unroll
    for (int i = 0; i < 4; i++)
#pragma unroll
        for (int j = 0; j < 4; j++)
#pragma unroll
            for (int r = 0; r < 4; r++) acc[i][j][r] = 0.f;

    const int kTiles = Ks >> 5;

    auto load_stage = [&](int kt, int buf) {
        const int k0 = kt * 32;
#pragma unroll
        for (int i = 0; i < 4; i++) {
            int idx = tid + i*256;
            int r = idx >> 3, kk = (idx & 7) * 4;
            cp16((unsigned)__cvta_generic_to_shared(&As[buf][r*AS_STRIDE + kk]),
                 Ab + (size_t)(bm + r) * Kfull + k0 + kk);
        }
#pragma unroll
        for (int i = 0; i < 4; i++) {
            int idx = tid + i*256;
            int kr = idx >> 5, n = (idx & 31) * 4;
            cp16((unsigned)__cvta_generic_to_shared(&Bs[buf][kr*BS_STRIDE + n]),
                 Wb + (size_t)(k0 + kr) * Nc + bn + n);
        }
        asm volatile("cp.async.commit_group;");
    };

    load_stage(0, 0);
    load_stage(1, 1);

    const int r8 = lane >> 2;
    const int c4 = lane & 3;
    const int lrow = ((lane >> 3) & 1) * 8 + (lane & 7);
    const int lcol = (lane >> 4) * 4;
    uint32_t a_off[4];
#pragma unroll
    for (int mt = 0; mt < 4; mt++)
        a_off[mt] = ((wm*64 + mt*16 + lrow)*AS_STRIDE + lcol) * 4u;

    for (int kt = 0; kt < kTiles; kt++) {
        if (kt + 1 < kTiles) asm volatile("cp.async.wait_group 1;");
        else                 asm volatile("cp.async.wait_group 0;");
        __syncthreads();
        if (kt + 2 < kTiles) load_stage(kt + 2, (kt + 2) % 3);

        const float* as = As[kt % 3];
        const float* bs = Bs[kt % 3];
        const uint32_t as_u32 = (uint32_t)__cvta_generic_to_shared(as);
#pragma unroll
        for (int k8 = 0; k8 < 4; k8++) {
            const int kb = k8 * 8;
            unsigned af[4][4], bf[4][2];
#pragma unroll
            for (int mt = 0; mt < 4; mt++)
                LDSM_X4(af[mt], as_u32 + a_off[mt] + k8*32u);
#pragma unroll
            for (int nt = 0; nt < 4; nt++) {
                int col = wn*32 + nt*8 + r8;
                int krow = kb + c4;
                bf[nt][0] = __float_as_uint(bs[ krow     *BS_STRIDE + col]);
                bf[nt][1] = __float_as_uint(bs[(krow + 4)*BS_STRIDE + col]);
            }
#pragma unroll
            for (int mt = 0; mt < 4; mt++)
#pragma unroll
                for (int nt = 0; nt < 4; nt++)
                    MMA_TF32(acc[mt][nt], af[mt][0], af[mt][1], af[mt][2],
                             af[mt][3], bf[nt][0], bf[nt][1]);
        }
    }

#pragma unroll
    for (int mt = 0; mt < 4; mt++) {
        int row0 = bm + wm*64 + mt*16 + r8;
#pragma unroll
        for (int nt = 0; nt < 4; nt++) {
            int col0 = bn + wn*32 + nt*8 + c4*2;
            float b0 = 0.f, b1 = 0.f;
            if (!PARTIAL) { b0 = __ldg(&bias[col0]); b1 = __ldg(&bias[col0 + 1]); }
#pragma unroll
            for (int half = 0; half < 2; half++) {
                int row = row0 + half*8;
                float v0 = acc[mt][nt][half*2 + 0] + b0;
                float v1 = acc[mt][nt][half*2 + 1] + b1;
                if (GELU) { v0 = v0 * normcdff(v0); v1 = v1 * normcdff(v1); }
                if (RES) {
                    const float2 rr = *(const float2*)&res[(size_t)row*Nc + col0];
                    v0 += rr.x; v1 += rr.y;
                }
                if (ROUND) { v0 = round_tf32(v0); v1 = round_tf32(v1); }
                *(float2*)&Cb[(size_t)row*Nc + col0] = make_float2(v0, v1);
            }
        }
    }
}

// ------- Tensor-core flash attention: cp.async double-buffer, no P smem ----
#define QP_STR 68   // Q/K stride (conflict-free LDSM)
#define V_STR  72   // V stride  (conflict-free scalar frag LDS)
// smem: Q[128*68] + K[2][64*68] + V[2][64*72] = 26624 floats = 106496 B

__global__ __launch_bounds__(256) void attn_tc(
    const float* __restrict__ qkv, const float* __restrict__ adj,
    float* __restrict__ out)
{
    extern __shared__ float sma[];
    float* Qs  = sma;
    float* Kb0 = Qs + 128*QP_STR;
    float* Vb0 = Kb0 + 2*64*QP_STR;

    const int tid  = threadIdx.x;
    const int lane = tid & 31;
    const int warp = tid >> 5;
    const int r8   = lane >> 2;
    const int c4   = lane & 3;
    const int bh   = blockIdx.y;
    const int b    = bh / Hh, h = bh % Hh;
    const int q0   = blockIdx.x * 128;
    const int qrow = (warp >> 2)*64 + (warp & 3)*16;
    const float scale = 0.125f;

    // LDSM lane offsets
    const int lrow  = ((lane >> 3) & 1) * 8 + (lane & 7);   // A-style x4
    const int lcol  = (lane >> 4) * 4;
    const int kprow = ((lane >> 4) & 1) * 8 + (lane & 7);   // K-pair x4
    const int kpcol = ((lane >> 3) & 1) * 4;

    const uint32_t qs_u32 = (uint32_t)__cvta_generic_to_shared(Qs);
    uint32_t ks_u32[2] = {
        (uint32_t)__cvta_generic_to_shared(Kb0),
        (uint32_t)__cvta_generic_to_shared(Kb0 + 64*QP_STR) };
    float* Vbuf[2] = { Vb0, Vb0 + 64*V_STR };
    const uint32_t q_off  = ((qrow + lrow)*QP_STR + lcol) * 4u;
    const uint32_t kp_off = (kprow*QP_STR + kpcol) * 4u;

    // load Q tile (plain stores; covered by first barrier)
#pragma unroll
    for (int it = 0; it < 32; it++) {
        int idx = tid + it*256;
        int r = idx >> 6, d = idx & 63;
        Qs[r*QP_STR + d] = qkv[(size_t)(b*Nseq + q0 + r)*(3*Dmod) + h*DHd + d];
    }

    auto load_kv = [&](int kt, int buf) {
        const int k0 = kt*64;
        float* kd = Kb0 + buf*64*QP_STR;
        float* vd = Vbuf[buf];
#pragma unroll
        for (int i = 0; i < 4; i++) {
            int idx = tid + i*256;
            int r = idx >> 4, d4 = (idx & 15) * 4;
            size_t base = (size_t)(b*Nseq + k0 + r)*(3*Dmod) + h*DHd + d4;
            cp16((unsigned)__cvta_generic_to_shared(&kd[r*QP_STR + d4]),
                 qkv + base + Dmod);
            cp16((unsigned)__cvta_generic_to_shared(&vd[r*V_STR + d4]),
                 qkv + base + 2*Dmod);
        }
        asm volatile("cp.async.commit_group;");
    };

    load_kv(0, 0);

    float m0 = -1e30f, m1 = -1e30f, l0 = 0.f, l1 = 0.f;
    float o[8][4];
#pragma unroll
    for (int nt = 0; nt < 8; nt++)
#pragma unroll
        for (int r = 0; r < 4; r++) o[nt][r] = 0.f;

    const int srcA = (lane & ~3) | (c4 >> 1);
    const int srcB = srcA + 2;
    const bool oddc = c4 & 1;

    for (int kt = 0; kt < Nseq/64; kt++) {
        const int buf = kt & 1;
        asm volatile("cp.async.wait_group 0;");
        __syncthreads();                    // load(kt) visible; all past kt-1
        if (kt + 1 < Nseq/64) load_kv(kt + 1, buf ^ 1);   // overlaps compute

        // ---- S = Q @ K^T ----
        float s[8][4];
#pragma unroll
        for (int nt = 0; nt < 8; nt++)
#pragma unroll
            for (int r = 0; r < 4; r++) s[nt][r] = 0.f;

#pragma unroll
        for (int k8 = 0; k8 < 8; k8++) {
            unsigned aq[4];
            LDSM_X4(aq, qs_u32 + q_off + k8*32u);
#pragma unroll
            for (int ntp = 0; ntp < 4; ntp++) {
                unsigned kb4[4];
                LDSM_X4(kb4, ks_u32[buf] + kp_off + ntp*(16u*QP_STR*4u) + k8*32u);
                MMA_TF32(s[2*ntp    ], aq[0], aq[1], aq[2], aq[3], kb4[0], kb4[1]);
                MMA_TF32(s[2*ntp + 1], aq[0], aq[1], aq[2], aq[3], kb4[2], kb4[3]);
            }
        }

        // ---- scale + adjacency bias ----
        const int k0 = kt*64;
        const int qg0 = q0 + qrow + r8;
#pragma unroll
        for (int nt = 0; nt < 8; nt++) {
            int col = k0 + nt*8 + c4*2;
            float2 ad0 = *(const float2*)&adj[(size_t) qg0     *Nseq + col];
            float2 ad1 = *(const float2*)&adj[(size_t)(qg0 + 8)*Nseq + col];
            s[nt][0] = s[nt][0]*scale + ad0.x;
            s[nt][1] = s[nt][1]*scale + ad0.y;
            s[nt][2] = s[nt][2]*scale + ad1.x;
            s[nt][3] = s[nt][3]*scale + ad1.y;
        }

        // ---- online softmax ----
        float mx0 = -1e30f, mx1 = -1e30f;
#pragma unroll
        for (int nt = 0; nt < 8; nt++) {
            mx0 = fmaxf(mx0, fmaxf(s[nt][0], s[nt][1]));
            mx1 = fmaxf(mx1, fmaxf(s[nt][2], s[nt][3]));
        }
        mx0 = fmaxf(mx0, __shfl_xor_sync(0xffffffffu, mx0, 1));
        mx0 = fmaxf(mx0, __shfl_xor_sync(0xffffffffu, mx0, 2));
        mx1 = fmaxf(mx1, __shfl_xor_sync(0xffffffffu, mx1, 1));
        mx1 = fmaxf(mx1, __shfl_xor_sync(0xffffffffu, mx1, 2));
        float mn0 = fmaxf(m0, mx0), mn1 = fmaxf(m1, mx1);
        float al0 = __expf(m0 - mn0), al1 = __expf(m1 - mn1);
        float rs0 = 0.f, rs1 = 0.f;
#pragma unroll
        for (int nt = 0; nt < 8; nt++) {
            s[nt][0] = __expf(s[nt][0] - mn0);
            s[nt][1] = __expf(s[nt][1] - mn0);
            s[nt][2] = __expf(s[nt][2] - mn1);
            s[nt][3] = __expf(s[nt][3] - mn1);
            rs0 += s[nt][0] + s[nt][1];
            rs1 += s[nt][2] + s[nt][3];
        }
        rs0 += __shfl_xor_sync(0xffffffffu, rs0, 1);
        rs0 += __shfl_xor_sync(0xffffffffu, rs0, 2);
        rs1 += __shfl_xor_sync(0xffffffffu, rs1, 1);
        rs1 += __shfl_xor_sync(0xffffffffu, rs1, 2);
        l0 = l0*al0 + rs0;  l1 = l1*al1 + rs1;
        m0 = mn0;           m1 = mn1;
#pragma unroll
        for (int nt = 0; nt < 8; nt++) {
            o[nt][0] *= al0; o[nt][1] *= al0;
            o[nt][2] *= al1; o[nt][3] *= al1;
        }

        // ---- O += P @ V : A-fragments built by intra-quad shuffles ----
        const float* vs = Vbuf[buf];
#pragma unroll
        for (int k8 = 0; k8 < 8; k8++) {
            const int kb = k8*8;
            float t0 = __shfl_sync(0xffffffffu, s[k8][0], srcA);
            float t1 = __shfl_sync(0xffffffffu, s[k8][1], srcA);
            float t2 = __shfl_sync(0xffffffffu, s[k8][2], srcA);
            float t3 = __shfl_sync(0xffffffffu, s[k8][3], srcA);
            float u0 = __shfl_sync(0xffffffffu, s[k8][0], srcB);
            float u1 = __shfl_sync(0xffffffffu, s[k8][1], srcB);
            float u2 = __shfl_sync(0xffffffffu, s[k8][2], srcB);
            float u3 = __shfl_sync(0xffffffffu, s[k8][3], srcB);
            unsigned ap0 = __float_as_uint(oddc ? t1 : t0);  // P[r8][kb+c4]
            unsigned ap1 = __float_as_uint(oddc ? t3 : t2);  // P[r8+8][kb+c4]
            unsigned ap2 = __float_as_uint(oddc ? u1 : u0);  // P[r8][kb+c4+4]
            unsigned ap3 = __float_as_uint(oddc ? u3 : u2);  // P[r8+8][kb+c4+4]
#pragma unroll
            for (int nt = 0; nt < 8; nt++) {
                unsigned b0 = __float_as_uint(vs[(kb + c4    )*V_STR + nt*8 + r8]);
                unsigned b1 = __float_as_uint(vs[(kb + c4 + 4)*V_STR + nt*8 + r8]);
                MMA_TF32(o[nt], ap0, ap1, ap2, ap3, b0, b1);
            }
        }
        __syncthreads();   // all warps done with K[buf]/V[buf] before reuse
    }

    const int qg0 = q0 + qrow + r8;
    float i0 = 1.f / l0, i1 = 1.f / l1;
#pragma unroll
    for (int nt = 0; nt < 8; nt++) {
        int col = h*DHd + nt*8 + c4*2;
        *(float2*)&out[(size_t)(b*Nseq + qg0    )*Dmod + col] =
            make_float2(round_tf32(o[nt][0]*i0), round_tf32(o[nt][1]*i0));
        *(float2*)&out[(size_t)(b*Nseq + qg0 + 8)*Dmod + col] =
            make_float2(round_tf32(o[nt][2]*i1), round_tf32(o[nt][3]*i1));
    }
}

// ---------------- launcher ----------------
extern "C" void kernel_launch(void* const* d_in, const int* in_sizes, int n_in,
                              void* d_out, int out_size)
{
    const float* x      = (const float*)d_in[0];
    const float* adj    = (const float*)d_in[1];
    const float* ln1_g  = (const float*)d_in[2];
    const float* ln1_b  = (const float*)d_in[3];
    const float* qkv_w  = (const float*)d_in[4];
    const float* qkv_b  = (const float*)d_in[5];
    const float* proj_w = (const float*)d_in[6];
    const float* proj_b = (const float*)d_in[7];
    const float* ln2_g  = (const float*)d_in[8];
    const float* ln2_b  = (const float*)d_in[9];
    const float* fc1_w  = (const float*)d_in[10];
    const float* fc1_b  = (const float*)d_in[11];
    const float* fc2_w  = (const float*)d_in[12];
    const float* fc2_b  = (const float*)d_in[13];
    float* out = (float*)d_out;

    float *h, *qkv, *attn, *x1, *h2, *act, *part;
    cudaGetSymbolAddress((void**)&h,    g_h);
    cudaGetSymbolAddress((void**)&qkv,  g_qkv);
    cudaGetSymbolAddress((void**)&attn, g_attn);
    cudaGetSymbolAddress((void**)&x1,   g_x1);
    cudaGetSymbolAddress((void**)&h2,   g_h2);
    cudaGetSymbolAddress((void**)&act,  g_act);
    cudaGetSymbolAddress((void**)&part, g_part);

    const int attn_smem = (128*QP_STR + 2*64*QP_STR + 2*64*V_STR)
                          * sizeof(float);   // 106496 B
    static int init = 0;
    if (!init) {
        cudaFuncSetAttribute(gemm_tc<false,false,false,false>,
            cudaFuncAttributeMaxDynamicSharedMemorySize, GEMM_SMEM);
        cudaFuncSetAttribute(gemm_tc<true,false,true,false>,
            cudaFuncAttributeMaxDynamicSharedMemorySize, GEMM_SMEM);
        cudaFuncSetAttribute(gemm_tc<false,false,false,true>,
            cudaFuncAttributeMaxDynamicSharedMemorySize, GEMM_SMEM);
        cudaFuncSetAttribute(attn_tc,
            cudaFuncAttributeMaxDynamicSharedMemorySize, attn_smem);
        init = 1;
    }

    // 1. LN1 (warp-per-row)
    ln_warp<<<ROWS/8, 256>>>(x, ln1_g, ln1_b, h);
    // 2. qkv = h @ qkv_w + qkv_b
    gemm_tc<false,false,false,false><<<dim3(18, 32, 1), 256, GEMM_SMEM>>>(
        h, qkv_w, qkv_b, nullptr, qkv, ROWS, Dmod, 3*Dmod, Dmod);
    // 3. attention
    attn_tc<<<dim3(Nseq/128, Bsz*Hh), 256, attn_smem>>>(qkv, adj, attn);
    // 4. proj (split-K=3) then fused reduce+residual+LN2
    gemm_tc<false,false,false,true><<<dim3(6, 32, 3), 256, GEMM_SMEM>>>(
        attn, proj_w, proj_b, nullptr, part, ROWS, Dmod, Dmod, Dmod/3);
    reduce3_ln<<<ROWS/8, 256>>>(part, proj_b, x, x1, ln2_g, ln2_b, h2);
    // 5. act = gelu(h2 @ fc1_w + fc1_b)
    gemm_tc<true,false,true,false><<<dim3(24, 32, 1), 256, GEMM_SMEM>>>(
        h2, fc1_w, fc1_b, nullptr, act, ROWS, Dmod, HID, Dmod);
    // 6. out = x1 + act @ fc2_w + fc2_b  (split-K=3)
    gemm_tc<false,false,false,true><<<dim3(6, 32, 3), 256, GEMM_SMEM>>>(
        act, fc2_w, fc2_b, nullptr, part, ROWS, HID, Dmod, HID/3);
    reduce3_kernel<<<ROWS*Dmod/4/256, 256>>>(part, fc2_b, x1, out, Dmod);
}

// round 10
// speedup vs baseline: 3.7704x; 1.0331x over previous
#include <cuda_runtime.h>
#include <math.h>
#include <stdint.h>

#define Bsz  4
#define Nseq 1024
#define Dmod 768
#define Hh   12
#define DHd  64
#define HID  3072
#define ROWS (Bsz*Nseq)   // 4096

// ---- scratch (no cudaMalloc allowed) ----
__device__ float g_h   [ROWS*Dmod];
__device__ float g_qkv [ROWS*3*Dmod];
__device__ float g_attn[ROWS*Dmod];
__device__ float g_x1  [ROWS*Dmod];
__device__ float g_h2  [ROWS*Dmod];
__device__ float g_act [ROWS*HID];
__device__ float g_part[3*ROWS*Dmod];   // split-K partials
// transposed weights [N][K]
__device__ float g_wqkvT[3*Dmod*Dmod];
__device__ float g_wprojT[Dmod*Dmod];
__device__ float g_wfc1T[HID*Dmod];
__device__ float g_wfc2T[Dmod*HID];

__device__ __forceinline__ float round_tf32(float x) {
    unsigned r;
    asm("cvt.rna.tf32.f32 %0, %1;" : "=r"(r) : "f"(x));
    return __uint_as_float(r);
}

#define MMA_TF32(acc, a0,a1,a2,a3, b0,b1)                                   \
    asm volatile(                                                           \
        "mma.sync.aligned.m16n8k8.row.col.f32.tf32.tf32.f32 "               \
        "{%0,%1,%2,%3}, {%4,%5,%6,%7}, {%8,%9}, {%0,%1,%2,%3};"             \
        : "+f"(acc[0]), "+f"(acc[1]), "+f"(acc[2]), "+f"(acc[3])            \
        : "r"(a0), "r"(a1), "r"(a2), "r"(a3), "r"(b0), "r"(b1))

#define LDSM_X4(r, addr)                                                    \
    asm volatile("ldmatrix.sync.aligned.m8n8.x4.shared.b16 {%0,%1,%2,%3}, [%4];" \
        : "=r"((r)[0]), "=r"((r)[1]), "=r"((r)[2]), "=r"((r)[3]) : "r"(addr))

__device__ __forceinline__ void cp16(unsigned dst, const void* src) {
    asm volatile("cp.async.cg.shared.global [%0], [%1], 16;" :: "r"(dst), "l"(src));
}

// ---------------- weight transpose: [K][N] -> [N][K] ----------------
__global__ __launch_bounds__(256) void transpose32(
    const float* __restrict__ in, float* __restrict__ out, int K, int N)
{
    __shared__ float t[32][33];
    int n0 = blockIdx.x*32, k0 = blockIdx.y*32;
    int tx = threadIdx.x, ty = threadIdx.y;
#pragma unroll
    for (int i = 0; i < 4; i++)
        t[ty + i*8][tx] = in[(size_t)(k0 + ty + i*8)*N + n0 + tx];
    __syncthreads();
#pragma unroll
    for (int i = 0; i < 4; i++)
        out[(size_t)(n0 + ty + i*8)*K + k0 + tx] = t[tx][ty + i*8];
}

// ---------------- warp-per-row LayerNorm (tf32-rounded output) -------------
__global__ __launch_bounds__(256) void ln_warp(
    const float* __restrict__ x, const float* __restrict__ g,
    const float* __restrict__ b, float* __restrict__ out)
{
    const int warp = threadIdx.x >> 5, lane = threadIdx.x & 31;
    const int row  = blockIdx.x * 8 + warp;
    const float4* xr = (const float4*)(x + (size_t)row * Dmod);
    float4 v[6];
    float s = 0.f, s2 = 0.f;
#pragma unroll
    for (int i = 0; i < 6; i++) {
        v[i] = xr[lane + i*32];
        s  += v[i].x + v[i].y + v[i].z + v[i].w;
        s2 += v[i].x*v[i].x + v[i].y*v[i].y + v[i].z*v[i].z + v[i].w*v[i].w;
    }
#pragma unroll
    for (int off = 16; off; off >>= 1) {
        s  += __shfl_xor_sync(0xffffffffu, s,  off);
        s2 += __shfl_xor_sync(0xffffffffu, s2, off);
    }
    const float mu = s * (1.f/Dmod);
    const float rs = rsqrtf(s2 * (1.f/Dmod) - mu*mu + 1e-6f);
    float4* orow = (float4*)(out + (size_t)row * Dmod);
#pragma unroll
    for (int i = 0; i < 6; i++) {
        int c = lane + i*32;
        float4 gg = __ldg(&((const float4*)g)[c]);
        float4 bb = __ldg(&((const float4*)b)[c]);
        float4 o;
        o.x = round_tf32((v[i].x - mu)*rs*gg.x + bb.x);
        o.y = round_tf32((v[i].y - mu)*rs*gg.y + bb.y);
        o.z = round_tf32((v[i].z - mu)*rs*gg.z + bb.z);
        o.w = round_tf32((v[i].w - mu)*rs*gg.w + bb.w);
        orow[c] = o;
    }
}

// ------- fused split-K reduce + residual + LN: x1 and h2 in one pass -------
__global__ __launch_bounds__(256) void reduce3_ln(
    const float* __restrict__ p, const float* __restrict__ bias,
    const float* __restrict__ res, float* __restrict__ x1,
    const float* __restrict__ g, const float* __restrict__ bv,
    float* __restrict__ h2)
{
    const int warp = threadIdx.x >> 5, lane = threadIdx.x & 31;
    const int row  = blockIdx.x * 8 + warp;
    const size_t tot4 = (size_t)ROWS * Dmod / 4;
    const size_t base4 = (size_t)row * (Dmod/4);
    float4 v[6];
    float s = 0.f, s2 = 0.f;
#pragma unroll
    for (int i = 0; i < 6; i++) {
        int c = lane + i*32;
        size_t idx = base4 + c;
        float4 a  = ((const float4*)p)[idx];
        float4 b2 = ((const float4*)p)[idx + tot4];
        float4 c2 = ((const float4*)p)[idx + 2*tot4];
        float4 r  = ((const float4*)res)[idx];
        float4 bi = __ldg(&((const float4*)bias)[c]);
        float4 o;
        o.x = a.x + b2.x + c2.x + bi.x + r.x;
        o.y = a.y + b2.y + c2.y + bi.y + r.y;
        o.z = a.z + b2.z + c2.z + bi.z + r.z;
        o.w = a.w + b2.w + c2.w + bi.w + r.w;
        ((float4*)x1)[idx] = o;
        v[i] = o;
        s  += o.x + o.y + o.z + o.w;
        s2 += o.x*o.x + o.y*o.y + o.z*o.z + o.w*o.w;
    }
#pragma unroll
    for (int off = 16; off; off >>= 1) {
        s  += __shfl_xor_sync(0xffffffffu, s,  off);
        s2 += __shfl_xor_sync(0xffffffffu, s2, off);
    }
    const float mu = s * (1.f/Dmod);
    const float rs = rsqrtf(s2 * (1.f/Dmod) - mu*mu + 1e-6f);
#pragma unroll
    for (int i = 0; i < 6; i++) {
        int c = lane + i*32;
        float4 gg = __ldg(&((const float4*)g)[c]);
        float4 bb = __ldg(&((const float4*)bv)[c]);
        float4 o;
        o.x = round_tf32((v[i].x - mu)*rs*gg.x + bb.x);
        o.y = round_tf32((v[i].y - mu)*rs*gg.y + bb.y);
        o.z = round_tf32((v[i].z - mu)*rs*gg.z + bb.z);
        o.w = round_tf32((v[i].w - mu)*rs*gg.w + bb.w);
        ((float4*)h2)[base4 + c] = o;
    }
}

// ---------------- split-K reduction: out = p0+p1+p2 + bias + res ----------
__global__ __launch_bounds__(256) void reduce3_kernel(
    const float* __restrict__ p, const float* __restrict__ bias,
    const float* __restrict__ res, float* __restrict__ out, int Nc)
{
    int i = blockIdx.x * 256 + threadIdx.x;
    const size_t tot = (size_t)ROWS * Nc;
    float4 a = ((const float4*)p)[i];
    float4 b = ((const float4*)(p + tot))[i];
    float4 c = ((const float4*)(p + 2*tot))[i];
    float4 r = ((const float4*)res)[i];
    int col = (i*4) % Nc;
    const float4 bi = *(const float4*)&bias[col];
    float4 o;
    o.x = a.x + b.x + c.x + bi.x + r.x;
    o.y = a.y + b.y + c.y + bi.y + r.y;
    o.z = a.z + b.z + c.z + bi.z + r.z;
    o.w = a.w + b.w + c.w + bi.w + r.w;
    ((float4*)out)[i] = o;
}

// --------- tf32 GEMM 128x128, 3-stage, full-LDSM (W pre-transposed) --------
// A [M][Kfull] row-major; WT [Nc][Kfull] row-major. Both tiles smem [128][36].
#define TS 36
#define STAGE_FLOATS (2*128*TS)                 // 9216 floats
#define GEMM_SMEM (3*STAGE_FLOATS*4)            // 110592 B

template<bool GELU, bool RES, bool ROUND, bool PARTIAL>
__global__ __launch_bounds__(256, 2) void gemm_tc(
    const float* __restrict__ A, const float* __restrict__ WT,
    const float* __restrict__ bias, const float* __restrict__ res,
    float* __restrict__ C, int M, int Kfull, int Nc, int Ks)
{
    extern __shared__ float sm[];

    const int tid  = threadIdx.x;
    const int lane = tid & 31;
    const int warp = tid >> 5;
    const int wm   = warp & 1;
    const int wn   = warp >> 1;
    const int bm   = blockIdx.y * 128;
    const int bn   = blockIdx.x * 128;
    const int z    = blockIdx.z;

    const float* Ab = A  + (size_t)z * Ks;
    const float* Wb = WT + (size_t)z * Ks;
    float* Cb = PARTIAL ? (C + (size_t)z * M * Nc) : C;

    float acc[4][4][4];
#pragma unroll
    for (int i = 0; i < 4; i++)
#pragma unroll
        for (int j = 0; j < 4; j++)
#pragma unroll
            for (int r = 0; r < 4; r++) acc[i][j][r] = 0.f;

    const int kTiles = Ks >> 5;

    auto load_stage = [&](int kt, int buf) {
        const int k0 = kt * 32;
        float* As = sm + buf*STAGE_FLOATS;
        float* Bs = As + 128*TS;
#pragma unroll
        for (int i = 0; i < 4; i++) {
            int idx = tid + i*256;
            int r = idx >> 3, kk = (idx & 7) * 4;
            cp16((unsigned)__cvta_generic_to_shared(&As[r*TS + kk]),
                 Ab + (size_t)(bm + r) * Kfull + k0 + kk);
        }
#pragma unroll
        for (int i = 0; i < 4; i++) {
            int idx = tid + i*256;
            int r = idx >> 3, kk = (idx & 7) * 4;
            cp16((unsigned)__cvta_generic_to_shared(&Bs[r*TS + kk]),
                 Wb + (size_t)(bn + r) * Kfull + k0 + kk);
        }
        asm volatile("cp.async.commit_group;");
    };

    load_stage(0, 0);
    load_stage(1, 1);

    const int r8 = lane >> 2;
    const int c4 = lane & 3;
    // A-frag LDSM lane offsets (x4: 16 rows x 8 cols)
    const int lrow = ((lane >> 3) & 1) * 8 + (lane & 7);
    const int lcol = (lane >> 4) * 4;
    // B-pair LDSM lane offsets (x4: two 8x8 frags over 16 rows)
    const int kprow = ((lane >> 4) & 1) * 8 + (lane & 7);
    const int kpcol = ((lane >> 3) & 1) * 4;

    const uint32_t a_base = ((wm*64 + lrow)*TS + lcol) * 4u;
    const uint32_t b_base = ((wn*32 + kprow)*TS + kpcol) * 4u;

    for (int kt = 0; kt < kTiles; kt++) {
        if (kt + 1 < kTiles) asm volatile("cp.async.wait_group 1;");
        else                 asm volatile("cp.async.wait_group 0;");
        __syncthreads();
        if (kt + 2 < kTiles) load_stage(kt + 2, (kt + 2) % 3);

        const int buf = kt % 3;
        const uint32_t as_u32 = (uint32_t)__cvta_generic_to_shared(sm)
                                + buf*STAGE_FLOATS*4u;
        const uint32_t bs_u32 = as_u32 + 128*TS*4u;
#pragma unroll
        for (int k8 = 0; k8 < 4; k8++) {
            unsigned af[4][4], bf[2][4];
#pragma unroll
            for (int mt = 0; mt < 4; mt++)
                LDSM_X4(af[mt], as_u32 + a_base + mt*(16u*TS*4u) + k8*32u);
#pragma unroll
            for (int p = 0; p < 2; p++)
                LDSM_X4(bf[p], bs_u32 + b_base + p*(16u*TS*4u) + k8*32u);
#pragma unroll
            for (int mt = 0; mt < 4; mt++) {
                MMA_TF32(acc[mt][0], af[mt][0], af[mt][1], af[mt][2], af[mt][3],
                         bf[0][0], bf[0][1]);
                MMA_TF32(acc[mt][1], af[mt][0], af[mt][1], af[mt][2], af[mt][3],
                         bf[0][2], bf[0][3]);
                MMA_TF32(acc[mt][2], af[mt][0], af[mt][1], af[mt][2], af[mt][3],
                         bf[1][0], bf[1][1]);
                MMA_TF32(acc[mt][3], af[mt][0], af[mt][1], af[mt][2], af[mt][3],
                         bf[1][2], bf[1][3]);
            }
        }
    }

#pragma unroll
    for (int mt = 0; mt < 4; mt++) {
        int row0 = bm + wm*64 + mt*16 + r8;
#pragma unroll
        for (int nt = 0; nt < 4; nt++) {
            int col0 = bn + wn*32 + nt*8 + c4*2;
            float b0 = 0.f, b1 = 0.f;
            if (!PARTIAL) { b0 = __ldg(&bias[col0]); b1 = __ldg(&bias[col0 + 1]); }
#pragma unroll
            for (int half = 0; half < 2; half++) {
                int row = row0 + half*8;
                float v0 = acc[mt][nt][half*2 + 0] + b0;
                float v1 = acc[mt][nt][half*2 + 1] + b1;
                if (GELU) { v0 = v0 * normcdff(v0); v1 = v1 * normcdff(v1); }
                if (RES) {
                    const float2 rr = *(const float2*)&res[(size_t)row*Nc + col0];
                    v0 += rr.x; v1 += rr.y;
                }
                if (ROUND) { v0 = round_tf32(v0); v1 = round_tf32(v1); }
                *(float2*)&Cb[(size_t)row*Nc + col0] = make_float2(v0, v1);
            }
        }
    }
}

// ------- Tensor-core flash attention: cp.async double-buffer, no P smem ----
#define QP_STR 68
#define V_STR  72

__global__ __launch_bounds__(256) void attn_tc(
    const float* __restrict__ qkv, const float* __restrict__ adj,
    float* __restrict__ out)
{
    extern __shared__ float sma[];
    float* Qs  = sma;
    float* Kb0 = Qs + 128*QP_STR;
    float* Vb0 = Kb0 + 2*64*QP_STR;

    const int tid  = threadIdx.x;
    const int lane = tid & 31;
    const int warp = tid >> 5;
    const int r8   = lane >> 2;
    const int c4   = lane & 3;
    const int bh   = blockIdx.y;
    const int b    = bh / Hh, h = bh % Hh;
    const int q0   = blockIdx.x * 128;
    const int qrow = (warp >> 2)*64 + (warp & 3)*16;
    const float scale = 0.125f;

    const int lrow  = ((lane >> 3) & 1) * 8 + (lane & 7);
    const int lcol  = (lane >> 4) * 4;
    const int kprow = ((lane >> 4) & 1) * 8 + (lane & 7);
    const int kpcol = ((lane >> 3) & 1) * 4;

    const uint32_t qs_u32 = (uint32_t)__cvta_generic_to_shared(Qs);
    uint32_t ks_u32[2] = {
        (uint32_t)__cvta_generic_to_shared(Kb0),
        (uint32_t)__cvta_generic_to_shared(Kb0 + 64*QP_STR) };
    float* Vbuf[2] = { Vb0, Vb0 + 64*V_STR };
    const uint32_t q_off  = ((qrow + lrow)*QP_STR + lcol) * 4u;
    const uint32_t kp_off = (kprow*QP_STR + kpcol) * 4u;

#pragma unroll
    for (int it = 0; it < 32; it++) {
        int idx = tid + it*256;
        int r = idx >> 6, d = idx & 63;
        Qs[r*QP_STR + d] = qkv[(size_t)(b*Nseq + q0 + r)*(3*Dmod) + h*DHd + d];
    }

    auto load_kv = [&](int kt, int buf) {
        const int k0 = kt*64;
        float* kd = Kb0 + buf*64*QP_STR;
        float* vd = Vbuf[buf];
#pragma unroll
        for (int i = 0; i < 4; i++) {
            int idx = tid + i*256;
            int r = idx >> 4, d4 = (idx & 15) * 4;
            size_t base = (size_t)(b*Nseq + k0 + r)*(3*Dmod) + h*DHd + d4;
            cp16((unsigned)__cvta_generic_to_shared(&kd[r*QP_STR + d4]),
                 qkv + base + Dmod);
            cp16((unsigned)__cvta_generic_to_shared(&vd[r*V_STR + d4]),
                 qkv + base + 2*Dmod);
        }
        asm volatile("cp.async.commit_group;");
    };

    load_kv(0, 0);

    float m0 = -1e30f, m1 = -1e30f, l0 = 0.f, l1 = 0.f;
    float o[8][4];
#pragma unroll
    for (int nt = 0; nt < 8; nt++)
#pragma unroll
        for (int r = 0; r < 4; r++) o[nt][r] = 0.f;

    const int srcA = (lane & ~3) | (c4 >> 1);
    const int srcB = srcA + 2;
    const bool oddc = c4 & 1;

    for (int kt = 0; kt < Nseq/64; kt++) {
        const int buf = kt & 1;
        asm volatile("cp.async.wait_group 0;");
        __syncthreads();
        if (kt + 1 < Nseq/64) load_kv(kt + 1, buf ^ 1);

        float s[8][4];
#pragma unroll
        for (int nt = 0; nt < 8; nt++)
#pragma unroll
            for (int r = 0; r < 4; r++) s[nt][r] = 0.f;

#pragma unroll
        for (int k8 = 0; k8 < 8; k8++) {
            unsigned aq[4];
            LDSM_X4(aq, qs_u32 + q_off + k8*32u);
#pragma unroll
            for (int ntp = 0; ntp < 4; ntp++) {
                unsigned kb4[4];
                LDSM_X4(kb4, ks_u32[buf] + kp_off + ntp*(16u*QP_STR*4u) + k8*32u);
                MMA_TF32(s[2*ntp    ], aq[0], aq[1], aq[2], aq[3], kb4[0], kb4[1]);
                MMA_TF32(s[2*ntp + 1], aq[0], aq[1], aq[2], aq[3], kb4[2], kb4[3]);
            }
        }

        const int k0 = kt*64;
        const int qg0 = q0 + qrow + r8;
#pragma unroll
        for (int nt = 0; nt < 8; nt++) {
            int col = k0 + nt*8 + c4*2;
            float2 ad0 = *(const float2*)&adj[(size_t) qg0     *Nseq + col];
            float2 ad1 = *(const float2*)&adj[(size_t)(qg0 + 8)*Nseq + col];
            s[nt][0] = s[nt][0]*scale + ad0.x;
            s[nt][1] = s[nt][1]*scale + ad0.y;
            s[nt][2] = s[nt][2]*scale + ad1.x;
            s[nt][3] = s[nt][3]*scale + ad1.y;
        }

        float mx0 = -1e30f, mx1 = -1e30f;
#pragma unroll
        for (int nt = 0; nt < 8; nt++) {
            mx0 = fmaxf(mx0, fmaxf(s[nt][0], s[nt][1]));
            mx1 = fmaxf(mx1, fmaxf(s[nt][2], s[nt][3]));
        }
        mx0 = fmaxf(mx0, __shfl_xor_sync(0xffffffffu, mx0, 1));
        mx0 = fmaxf(mx0, __shfl_xor_sync(0xffffffffu, mx0, 2));
        mx1 = fmaxf(mx1, __shfl_xor_sync(0xffffffffu, mx1, 1));
        mx1 = fmaxf(mx1, __shfl_xor_sync(0xffffffffu, mx1, 2));
        float mn0 = fmaxf(m0, mx0), mn1 = fmaxf(m1, mx1);
        float al0 = __expf(m0 - mn0), al1 = __expf(m1 - mn1);
        float rs0 = 0.f, rs1 = 0.f;
#pragma unroll
        for (int nt = 0; nt < 8; nt++) {
            s[nt][0] = __expf(s[nt][0] - mn0);
            s[nt][1] = __expf(s[nt][1] - mn0);
            s[nt][2] = __expf(s[nt][2] - mn1);
            s[nt][3] = __expf(s[nt][3] - mn1);
            rs0 += s[nt][0] + s[nt][1];
            rs1 += s[nt][2] + s[nt][3];
        }
        rs0 += __shfl_xor_sync(0xffffffffu, rs0, 1);
        rs0 += __shfl_xor_sync(0xffffffffu, rs0, 2);
        rs1 += __shfl_xor_sync(0xffffffffu, rs1, 1);
        rs1 += __shfl_xor_sync(0xffffffffu, rs1, 2);
        l0 = l0*al0 + rs0;  l1 = l1*al1 + rs1;
        m0 = mn0;           m1 = mn1;
#pragma unroll
        for (int nt = 0; nt < 8; nt++) {
            o[nt][0] *= al0; o[nt][1] *= al0;
            o[nt][2] *= al1; o[nt][3] *= al1;
        }

        const float* vs = Vbuf[buf];
#pragma unroll
        for (int k8 = 0; k8 < 8; k8++) {
            const int kb = k8*8;
            float t0 = __shfl_sync(0xffffffffu, s[k8][0], srcA);
            float t1 = __shfl_sync(0xffffffffu, s[k8][1], srcA);
            float t2 = __shfl_sync(0xffffffffu, s[k8][2], srcA);
            float t3 = __shfl_sync(0xffffffffu, s[k8][3], srcA);
            float u0 = __shfl_sync(0xffffffffu, s[k8][0], srcB);
            float u1 = __shfl_sync(0xffffffffu, s[k8][1], srcB);
            float u2 = __shfl_sync(0xffffffffu, s[k8][2], srcB);
            float u3 = __shfl_sync(0xffffffffu, s[k8][3], srcB);
            unsigned ap0 = __float_as_uint(oddc ? t1 : t0);
            unsigned ap1 = __float_as_uint(oddc ? t3 : t2);
            unsigned ap2 = __float_as_uint(oddc ? u1 : u0);
            unsigned ap3 = __float_as_uint(oddc ? u3 : u2);
#pragma unroll
            for (int nt = 0; nt < 8; nt++) {
                unsigned b0 = __float_as_uint(vs[(kb + c4    )*V_STR + nt*8 + r8]);
                unsigned b1 = __float_as_uint(vs[(kb + c4 + 4)*V_STR + nt*8 + r8]);
                MMA_TF32(o[nt], ap0, ap1, ap2, ap3, b0, b1);
            }
        }
        __syncthreads();
    }

    const int qg0 = q0 + qrow + r8;
    float i0 = 1.f / l0, i1 = 1.f / l1;
#pragma unroll
    for (int nt = 0; nt < 8; nt++) {
        int col = h*DHd + nt*8 + c4*2;
        *(float2*)&out[(size_t)(b*Nseq + qg0    )*Dmod + col] =
            make_float2(round_tf32(o[nt][0]*i0), round_tf32(o[nt][1]*i0));
        *(float2*)&out[(size_t)(b*Nseq + qg0 + 8)*Dmod + col] =
            make_float2(round_tf32(o[nt][2]*i1), round_tf32(o[nt][3]*i1));
    }
}

// ---------------- launcher ----------------
extern "C" void kernel_launch(void* const* d_in, const int* in_sizes, int n_in,
                              void* d_out, int out_size)
{
    const float* x      = (const float*)d_in[0];
    const float* adj    = (const float*)d_in[1];
    const float* ln1_g  = (const float*)d_in[2];
    const float* ln1_b  = (const float*)d_in[3];
    const float* qkv_w  = (const float*)d_in[4];
    const float* qkv_b  = (const float*)d_in[5];
    const float* proj_w = (const float*)d_in[6];
    const float* proj_b = (const float*)d_in[7];
    const float* ln2_g  = (const float*)d_in[8];
    const float* ln2_b  = (const float*)d_in[9];
    const float* fc1_w  = (const float*)d_in[10];
    const float* fc1_b  = (const float*)d_in[11];
    const float* fc2_w  = (const float*)d_in[12];
    const float* fc2_b  = (const float*)d_in[13];
    float* out = (float*)d_out;

    float *h, *qkv, *attn, *x1, *h2, *act, *part;
    float *wqkvT, *wprojT, *wfc1T, *wfc2T;
    cudaGetSymbolAddress((void**)&h,     g_h);
    cudaGetSymbolAddress((void**)&qkv,   g_qkv);
    cudaGetSymbolAddress((void**)&attn,  g_attn);
    cudaGetSymbolAddress((void**)&x1,    g_x1);
    cudaGetSymbolAddress((void**)&h2,    g_h2);
    cudaGetSymbolAddress((void**)&act,   g_act);
    cudaGetSymbolAddress((void**)&part,  g_part);
    cudaGetSymbolAddress((void**)&wqkvT, g_wqkvT);
    cudaGetSymbolAddress((void**)&wprojT,g_wprojT);
    cudaGetSymbolAddress((void**)&wfc1T, g_wfc1T);
    cudaGetSymbolAddress((void**)&wfc2T, g_wfc2T);

    const int attn_smem = (128*QP_STR + 2*64*QP_STR + 2*64*V_STR)
                          * sizeof(float);   // 106496 B
    static int init = 0;
    if (!init) {
        cudaFuncSetAttribute(gemm_tc<false,false,false,false>,
            cudaFuncAttributeMaxDynamicSharedMemorySize, GEMM_SMEM);
        cudaFuncSetAttribute(gemm_tc<true,false,true,false>,
            cudaFuncAttributeMaxDynamicSharedMemorySize, GEMM_SMEM);
        cudaFuncSetAttribute(gemm_tc<false,false,false,true>,
            cudaFuncAttributeMaxDynamicSharedMemorySize, GEMM_SMEM);
        cudaFuncSetAttribute(attn_tc,
            cudaFuncAttributeMaxDynamicSharedMemorySize, attn_smem);
        init = 1;
    }

    dim3 tb(32, 8);
    // 0. weight transposes [K][N] -> [N][K]
    transpose32<<<dim3(3*Dmod/32, Dmod/32), tb>>>(qkv_w,  wqkvT, Dmod, 3*Dmod);
    transpose32<<<dim3(Dmod/32,   Dmod/32), tb>>>(proj_w, wprojT, Dmod, Dmod);
    transpose32<<<dim3(HID/32,    Dmod/32), tb>>>(fc1_w,  wfc1T, Dmod, HID);
    transpose32<<<dim3(Dmod/32,   HID/32),  tb>>>(fc2_w,  wfc2T, HID, Dmod);

    // 1. LN1 (warp-per-row)
    ln_warp<<<ROWS/8, 256>>>(x, ln1_g, ln1_b, h);
    // 2. qkv = h @ qkv_w + qkv_b
    gemm_tc<false,false,false,false><<<dim3(18, 32, 1), 256, GEMM_SMEM>>>(
        h, wqkvT, qkv_b, nullptr, qkv, ROWS, Dmod, 3*Dmod, Dmod);
    // 3. attention
    attn_tc<<<dim3(Nseq/128, Bsz*Hh), 256, attn_smem>>>(qkv, adj, attn);
    // 4. proj (split-K=3) then fused reduce+residual+LN2
    gemm_tc<false,false,false,true><<<dim3(6, 32, 3), 256, GEMM_SMEM>>>(
        attn, wprojT, proj_b, nullptr, part, ROWS, Dmod, Dmod, Dmod/3);
    reduce3_ln<<<ROWS/8, 256>>>(part, proj_b, x, x1, ln2_g, ln2_b, h2);
    // 5. act = gelu(h2 @ fc1_w + fc1_b)
    gemm_tc<true,false,true,false><<<dim3(24, 32, 1), 256, GEMM_SMEM>>>(
        h2, wfc1T, fc1_b, nullptr, act, ROWS, Dmod, HID, Dmod);
    // 6. out = x1 + act @ fc2_w + fc2_b  (split-K=3)
    gemm_tc<false,false,false,true><<<dim3(6, 32, 3), 256, GEMM_SMEM>>>(
        act, wfc2T, fc2_b, nullptr, part, ROWS, HID, Dmod, HID/3);
    reduce3_kernel<<<ROWS*Dmod/4/256, 256>>>(part, fc2_b, x1, out, Dmod);
}

// round 11
// speedup vs baseline: 3.8141x; 1.0116x over previous
#include <cuda_runtime.h>
#include <math.h>
#include <stdint.h>

#define Bsz  4
#define Nseq 1024
#define Dmod 768
#define Hh   12
#define DHd  64
#define HID  3072
#define ROWS (Bsz*Nseq)   // 4096

// ---- scratch (no cudaMalloc allowed) ----
__device__ float g_h   [ROWS*Dmod];
__device__ float g_qkv [ROWS*3*Dmod];
__device__ float g_attn[ROWS*Dmod];
__device__ float g_x1  [ROWS*Dmod];
__device__ float g_h2  [ROWS*Dmod];
__device__ float g_act [ROWS*HID];
__device__ float g_part[3*ROWS*Dmod];   // split-K partials
// transposed weights [N][K]
__device__ float g_wqkvT[3*Dmod*Dmod];
__device__ float g_wprojT[Dmod*Dmod];
__device__ float g_wfc1T[HID*Dmod];
__device__ float g_wfc2T[Dmod*HID];

__device__ __forceinline__ float round_tf32(float x) {
    unsigned r;
    asm("cvt.rna.tf32.f32 %0, %1;" : "=r"(r) : "f"(x));
    return __uint_as_float(r);
}

#define MMA_TF32(acc, a0,a1,a2,a3, b0,b1)                                   \
    asm volatile(                                                           \
        "mma.sync.aligned.m16n8k8.row.col.f32.tf32.tf32.f32 "               \
        "{%0,%1,%2,%3}, {%4,%5,%6,%7}, {%8,%9}, {%0,%1,%2,%3};"             \
        : "+f"(acc[0]), "+f"(acc[1]), "+f"(acc[2]), "+f"(acc[3])            \
        : "r"(a0), "r"(a1), "r"(a2), "r"(a3), "r"(b0), "r"(b1))

#define LDSM_X4(r, addr)                                                    \
    asm volatile("ldmatrix.sync.aligned.m8n8.x4.shared.b16 {%0,%1,%2,%3}, [%4];" \
        : "=r"((r)[0]), "=r"((r)[1]), "=r"((r)[2]), "=r"((r)[3]) : "r"(addr))

__device__ __forceinline__ void cp16(unsigned dst, const void* src) {
    asm volatile("cp.async.cg.shared.global [%0], [%1], 16;" :: "r"(dst), "l"(src));
}

// ---------------- weight transpose: [K][N] -> [N][K] ----------------
__global__ __launch_bounds__(256) void transpose32(
    const float* __restrict__ in, float* __restrict__ out, int K, int N)
{
    __shared__ float t[32][33];
    int n0 = blockIdx.x*32, k0 = blockIdx.y*32;
    int tx = threadIdx.x, ty = threadIdx.y;
#pragma unroll
    for (int i = 0; i < 4; i++)
        t[ty + i*8][tx] = in[(size_t)(k0 + ty + i*8)*N + n0 + tx];
    __syncthreads();
#pragma unroll
    for (int i = 0; i < 4; i++)
        out[(size_t)(n0 + ty + i*8)*K + k0 + tx] = t[tx][ty + i*8];
}

// ---------------- warp-per-row LayerNorm (tf32-rounded output) -------------
__global__ __launch_bounds__(256) void ln_warp(
    const float* __restrict__ x, const float* __restrict__ g,
    const float* __restrict__ b, float* __restrict__ out)
{
    const int warp = threadIdx.x >> 5, lane = threadIdx.x & 31;
    const int row  = blockIdx.x * 8 + warp;
    const float4* xr = (const float4*)(x + (size_t)row * Dmod);
    float4 v[6];
    float s = 0.f, s2 = 0.f;
#pragma unroll
    for (int i = 0; i < 6; i++) {
        v[i] = xr[lane + i*32];
        s  += v[i].x + v[i].y + v[i].z + v[i].w;
        s2 += v[i].x*v[i].x + v[i].y*v[i].y + v[i].z*v[i].z + v[i].w*v[i].w;
    }
#pragma unroll
    for (int off = 16; off; off >>= 1) {
        s  += __shfl_xor_sync(0xffffffffu, s,  off);
        s2 += __shfl_xor_sync(0xffffffffu, s2, off);
    }
    const float mu = s * (1.f/Dmod);
    const float rs = rsqrtf(s2 * (1.f/Dmod) - mu*mu + 1e-6f);
    float4* orow = (float4*)(out + (size_t)row * Dmod);
#pragma unroll
    for (int i = 0; i < 6; i++) {
        int c = lane + i*32;
        float4 gg = __ldg(&((const float4*)g)[c]);
        float4 bb = __ldg(&((const float4*)b)[c]);
        float4 o;
        o.x = round_tf32((v[i].x - mu)*rs*gg.x + bb.x);
        o.y = round_tf32((v[i].y - mu)*rs*gg.y + bb.y);
        o.z = round_tf32((v[i].z - mu)*rs*gg.z + bb.z);
        o.w = round_tf32((v[i].w - mu)*rs*gg.w + bb.w);
        orow[c] = o;
    }
}

// ------- fused split-K reduce + residual + LN: x1 and h2 in one pass -------
__global__ __launch_bounds__(256) void reduce3_ln(
    const float* __restrict__ p, const float* __restrict__ bias,
    const float* __restrict__ res, float* __restrict__ x1,
    const float* __restrict__ g, const float* __restrict__ bv,
    float* __restrict__ h2)
{
    const int warp = threadIdx.x >> 5, lane = threadIdx.x & 31;
    const int row  = blockIdx.x * 8 + warp;
    const size_t tot4 = (size_t)ROWS * Dmod / 4;
    const size_t base4 = (size_t)row * (Dmod/4);
    float4 v[6];
    float s = 0.f, s2 = 0.f;
#pragma unroll
    for (int i = 0; i < 6; i++) {
        int c = lane + i*32;
        size_t idx = base4 + c;
        float4 a  = ((const float4*)p)[idx];
        float4 b2 = ((const float4*)p)[idx + tot4];
        float4 c2 = ((const float4*)p)[idx + 2*tot4];
        float4 r  = ((const float4*)res)[idx];
        float4 bi = __ldg(&((const float4*)bias)[c]);
        float4 o;
        o.x = a.x + b2.x + c2.x + bi.x + r.x;
        o.y = a.y + b2.y + c2.y + bi.y + r.y;
        o.z = a.z + b2.z + c2.z + bi.z + r.z;
        o.w = a.w + b2.w + c2.w + bi.w + r.w;
        ((float4*)x1)[idx] = o;
        v[i] = o;
        s  += o.x + o.y + o.z + o.w;
        s2 += o.x*o.x + o.y*o.y + o.z*o.z + o.w*o.w;
    }
#pragma unroll
    for (int off = 16; off; off >>= 1) {
        s  += __shfl_xor_sync(0xffffffffu, s,  off);
        s2 += __shfl_xor_sync(0xffffffffu, s2, off);
    }
    const float mu = s * (1.f/Dmod);
    const float rs = rsqrtf(s2 * (1.f/Dmod) - mu*mu + 1e-6f);
#pragma unroll
    for (int i = 0; i < 6; i++) {
        int c = lane + i*32;
        float4 gg = __ldg(&((const float4*)g)[c]);
        float4 bb = __ldg(&((const float4*)bv)[c]);
        float4 o;
        o.x = round_tf32((v[i].x - mu)*rs*gg.x + bb.x);
        o.y = round_tf32((v[i].y - mu)*rs*gg.y + bb.y);
        o.z = round_tf32((v[i].z - mu)*rs*gg.z + bb.z);
        o.w = round_tf32((v[i].w - mu)*rs*gg.w + bb.w);
        ((float4*)h2)[base4 + c] = o;
    }
}

// ---------------- split-K reduction: out = p0+p1+p2 + bias + res ----------
__global__ __launch_bounds__(256) void reduce3_kernel(
    const float* __restrict__ p, const float* __restrict__ bias,
    const float* __restrict__ res, float* __restrict__ out, int Nc)
{
    int i = blockIdx.x * 256 + threadIdx.x;
    const size_t tot = (size_t)ROWS * Nc;
    float4 a = ((const float4*)p)[i];
    float4 b = ((const float4*)(p + tot))[i];
    float4 c = ((const float4*)(p + 2*tot))[i];
    float4 r = ((const float4*)res)[i];
    int col = (i*4) % Nc;
    const float4 bi = *(const float4*)&bias[col];
    float4 o;
    o.x = a.x + b.x + c.x + bi.x + r.x;
    o.y = a.y + b.y + c.y + bi.y + r.y;
    o.z = a.z + b.z + c.z + bi.z + r.z;
    o.w = a.w + b.w + c.w + bi.w + r.w;
    ((float4*)out)[i] = o;
}

// --------- tf32 GEMM 128x128, 3-stage, full-LDSM (W pre-transposed) --------
#define TS 36
#define STAGE_FLOATS (2*128*TS)
#define GEMM_SMEM (3*STAGE_FLOATS*4)

template<bool GELU, bool RES, bool ROUND, bool PARTIAL>
__global__ __launch_bounds__(256, 2) void gemm_tc(
    const float* __restrict__ A, const float* __restrict__ WT,
    const float* __restrict__ bias, const float* __restrict__ res,
    float* __restrict__ C, int M, int Kfull, int Nc, int Ks)
{
    extern __shared__ float sm[];

    const int tid  = threadIdx.x;
    const int lane = tid & 31;
    const int warp = tid >> 5;
    const int wm   = warp & 1;
    const int wn   = warp >> 1;
    const int bm   = blockIdx.y * 128;
    const int bn   = blockIdx.x * 128;
    const int z    = blockIdx.z;

    const float* Ab = A  + (size_t)z * Ks;
    const float* Wb = WT + (size_t)z * Ks;
    float* Cb = PARTIAL ? (C + (size_t)z * M * Nc) : C;

    float acc[4][4][4];
#pragma unroll
    for (int i = 0; i < 4; i++)
#pragma unroll
        for (int j = 0; j < 4; j++)
#pragma unroll
            for (int r = 0; r < 4; r++) acc[i][j][r] = 0.f;

    const int kTiles = Ks >> 5;

    auto load_stage = [&](int kt, int buf) {
        const int k0 = kt * 32;
        float* As = sm + buf*STAGE_FLOATS;
        float* Bs = As + 128*TS;
#pragma unroll
        for (int i = 0; i < 4; i++) {
            int idx = tid + i*256;
            int r = idx >> 3, kk = (idx & 7) * 4;
            cp16((unsigned)__cvta_generic_to_shared(&As[r*TS + kk]),
                 Ab + (size_t)(bm + r) * Kfull + k0 + kk);
        }
#pragma unroll
        for (int i = 0; i < 4; i++) {
            int idx = tid + i*256;
            int r = idx >> 3, kk = (idx & 7) * 4;
            cp16((unsigned)__cvta_generic_to_shared(&Bs[r*TS + kk]),
                 Wb + (size_t)(bn + r) * Kfull + k0 + kk);
        }
        asm volatile("cp.async.commit_group;");
    };

    load_stage(0, 0);
    load_stage(1, 1);

    const int r8 = lane >> 2;
    const int c4 = lane & 3;
    const int lrow = ((lane >> 3) & 1) * 8 + (lane & 7);
    const int lcol = (lane >> 4) * 4;
    const int kprow = ((lane >> 4) & 1) * 8 + (lane & 7);
    const int kpcol = ((lane >> 3) & 1) * 4;

    const uint32_t a_base = ((wm*64 + lrow)*TS + lcol) * 4u;
    const uint32_t b_base = ((wn*32 + kprow)*TS + kpcol) * 4u;

    for (int kt = 0; kt < kTiles; kt++) {
        if (kt + 1 < kTiles) asm volatile("cp.async.wait_group 1;");
        else                 asm volatile("cp.async.wait_group 0;");
        __syncthreads();
        if (kt + 2 < kTiles) load_stage(kt + 2, (kt + 2) % 3);

        const int buf = kt % 3;
        const uint32_t as_u32 = (uint32_t)__cvta_generic_to_shared(sm)
                                + buf*STAGE_FLOATS*4u;
        const uint32_t bs_u32 = as_u32 + 128*TS*4u;
#pragma unroll
        for (int k8 = 0; k8 < 4; k8++) {
            unsigned af[4][4], bf[2][4];
#pragma unroll
            for (int mt = 0; mt < 4; mt++)
                LDSM_X4(af[mt], as_u32 + a_base + mt*(16u*TS*4u) + k8*32u);
#pragma unroll
            for (int p = 0; p < 2; p++)
                LDSM_X4(bf[p], bs_u32 + b_base + p*(16u*TS*4u) + k8*32u);
#pragma unroll
            for (int mt = 0; mt < 4; mt++) {
                MMA_TF32(acc[mt][0], af[mt][0], af[mt][1], af[mt][2], af[mt][3],
                         bf[0][0], bf[0][1]);
                MMA_TF32(acc[mt][1], af[mt][0], af[mt][1], af[mt][2], af[mt][3],
                         bf[0][2], bf[0][3]);
                MMA_TF32(acc[mt][2], af[mt][0], af[mt][1], af[mt][2], af[mt][3],
                         bf[1][0], bf[1][1]);
                MMA_TF32(acc[mt][3], af[mt][0], af[mt][1], af[mt][2], af[mt][3],
                         bf[1][2], bf[1][3]);
            }
        }
    }

#pragma unroll
    for (int mt = 0; mt < 4; mt++) {
        int row0 = bm + wm*64 + mt*16 + r8;
#pragma unroll
        for (int nt = 0; nt < 4; nt++) {
            int col0 = bn + wn*32 + nt*8 + c4*2;
            float b0 = 0.f, b1 = 0.f;
            if (!PARTIAL) { b0 = __ldg(&bias[col0]); b1 = __ldg(&bias[col0 + 1]); }
#pragma unroll
            for (int half = 0; half < 2; half++) {
                int row = row0 + half*8;
                float v0 = acc[mt][nt][half*2 + 0] + b0;
                float v1 = acc[mt][nt][half*2 + 1] + b1;
                if (GELU) { v0 = v0 * normcdff(v0); v1 = v1 * normcdff(v1); }
                if (RES) {
                    const float2 rr = *(const float2*)&res[(size_t)row*Nc + col0];
                    v0 += rr.x; v1 += rr.y;
                }
                if (ROUND) { v0 = round_tf32(v0); v1 = round_tf32(v1); }
                *(float2*)&Cb[(size_t)row*Nc + col0] = make_float2(v0, v1);
            }
        }
    }
}

// ------- Tensor-core flash attention: cp.async double-buffer, no P smem ----
#define QP_STR 68
#define V_STR  72

__global__ __launch_bounds__(256) void attn_tc(
    const float* __restrict__ qkv, const float* __restrict__ adj,
    float* __restrict__ out)
{
    extern __shared__ float sma[];
    float* Qs  = sma;
    float* Kb0 = Qs + 128*QP_STR;
    float* Vb0 = Kb0 + 2*64*QP_STR;

    const int tid  = threadIdx.x;
    const int lane = tid & 31;
    const int warp = tid >> 5;
    const int r8   = lane >> 2;
    const int c4   = lane & 3;
    const int bh   = blockIdx.y;
    const int b    = bh / Hh, h = bh % Hh;
    const int q0   = blockIdx.x * 128;
    const int qrow = (warp >> 2)*64 + (warp & 3)*16;
    const float scale = 0.125f;

    const int lrow  = ((lane >> 3) & 1) * 8 + (lane & 7);
    const int lcol  = (lane >> 4) * 4;
    const int kprow = ((lane >> 4) & 1) * 8 + (lane & 7);
    const int kpcol = ((lane >> 3) & 1) * 4;

    const uint32_t qs_u32 = (uint32_t)__cvta_generic_to_shared(Qs);
    uint32_t ks_u32[2] = {
        (uint32_t)__cvta_generic_to_shared(Kb0),
        (uint32_t)__cvta_generic_to_shared(Kb0 + 64*QP_STR) };
    float* Vbuf[2] = { Vb0, Vb0 + 64*V_STR };
    const uint32_t q_off  = ((qrow + lrow)*QP_STR + lcol) * 4u;
    const uint32_t kp_off = (kprow*QP_STR + kpcol) * 4u;

#pragma unroll
    for (int it = 0; it < 32; it++) {
        int idx = tid + it*256;
        int r = idx >> 6, d = idx & 63;
        Qs[r*QP_STR + d] = qkv[(size_t)(b*Nseq + q0 + r)*(3*Dmod) + h*DHd + d];
    }

    auto load_kv = [&](int kt, int buf) {
        const int k0 = kt*64;
        float* kd = Kb0 + buf*64*QP_STR;
        float* vd = Vbuf[buf];
#pragma unroll
        for (int i = 0; i < 4; i++) {
            int idx = tid + i*256;
            int r = idx >> 4, d4 = (idx & 15) * 4;
            size_t base = (size_t)(b*Nseq + k0 + r)*(3*Dmod) + h*DHd + d4;
            cp16((unsigned)__cvta_generic_to_shared(&kd[r*QP_STR + d4]),
                 qkv + base + Dmod);
            cp16((unsigned)__cvta_generic_to_shared(&vd[r*V_STR + d4]),
                 qkv + base + 2*Dmod);
        }
        asm volatile("cp.async.commit_group;");
    };

    load_kv(0, 0);

    float m0 = -1e30f, m1 = -1e30f, l0 = 0.f, l1 = 0.f;
    float o[8][4];
#pragma unroll
    for (int nt = 0; nt < 8; nt++)
#pragma unroll
        for (int r = 0; r < 4; r++) o[nt][r] = 0.f;

    const int srcA = (lane & ~3) | (c4 >> 1);
    const int srcB = srcA + 2;
    const bool oddc = c4 & 1;

    for (int kt = 0; kt < Nseq/64; kt++) {
        const int buf = kt & 1;
        asm volatile("cp.async.wait_group 0;");
        __syncthreads();
        if (kt + 1 < Nseq/64) load_kv(kt + 1, buf ^ 1);

        float s[8][4];
#pragma unroll
        for (int nt = 0; nt < 8; nt++)
#pragma unroll
            for (int r = 0; r < 4; r++) s[nt][r] = 0.f;

#pragma unroll
        for (int k8 = 0; k8 < 8; k8++) {
            unsigned aq[4];
            LDSM_X4(aq, qs_u32 + q_off + k8*32u);
#pragma unroll
            for (int ntp = 0; ntp < 4; ntp++) {
                unsigned kb4[4];
                LDSM_X4(kb4, ks_u32[buf] + kp_off + ntp*(16u*QP_STR*4u) + k8*32u);
                MMA_TF32(s[2*ntp    ], aq[0], aq[1], aq[2], aq[3], kb4[0], kb4[1]);
                MMA_TF32(s[2*ntp + 1], aq[0], aq[1], aq[2], aq[3], kb4[2], kb4[3]);
            }
        }

        const int k0 = kt*64;
        const int qg0 = q0 + qrow + r8;
#pragma unroll
        for (int nt = 0; nt < 8; nt++) {
            int col = k0 + nt*8 + c4*2;
            float2 ad0 = *(const float2*)&adj[(size_t) qg0     *Nseq + col];
            float2 ad1 = *(const float2*)&adj[(size_t)(qg0 + 8)*Nseq + col];
            s[nt][0] = s[nt][0]*scale + ad0.x;
            s[nt][1] = s[nt][1]*scale + ad0.y;
            s[nt][2] = s[nt][2]*scale + ad1.x;
            s[nt][3] = s[nt][3]*scale + ad1.y;
        }

        float mx0 = -1e30f, mx1 = -1e30f;
#pragma unroll
        for (int nt = 0; nt < 8; nt++) {
            mx0 = fmaxf(mx0, fmaxf(s[nt][0], s[nt][1]));
            mx1 = fmaxf(mx1, fmaxf(s[nt][2], s[nt][3]));
        }
        mx0 = fmaxf(mx0, __shfl_xor_sync(0xffffffffu, mx0, 1));
        mx0 = fmaxf(mx0, __shfl_xor_sync(0xffffffffu, mx0, 2));
        mx1 = fmaxf(mx1, __shfl_xor_sync(0xffffffffu, mx1, 1));
        mx1 = fmaxf(mx1, __shfl_xor_sync(0xffffffffu, mx1, 2));
        float mn0 = fmaxf(m0, mx0), mn1 = fmaxf(m1, mx1);
        float al0 = __expf(m0 - mn0), al1 = __expf(m1 - mn1);
        float rs0 = 0.f, rs1 = 0.f;
#pragma unroll
        for (int nt = 0; nt < 8; nt++) {
            s[nt][0] = __expf(s[nt][0] - mn0);
            s[nt][1] = __expf(s[nt][1] - mn0);
            s[nt][2] = __expf(s[nt][2] - mn1);
            s[nt][3] = __expf(s[nt][3] - mn1);
            rs0 += s[nt][0] + s[nt][1];
            rs1 += s[nt][2] + s[nt][3];
        }
        rs0 += __shfl_xor_sync(0xffffffffu, rs0, 1);
        rs0 += __shfl_xor_sync(0xffffffffu, rs0, 2);
        rs1 += __shfl_xor_sync(0xffffffffu, rs1, 1);
        rs1 += __shfl_xor_sync(0xffffffffu, rs1, 2);
        l0 = l0*al0 + rs0;  l1 = l1*al1 + rs1;
        m0 = mn0;           m1 = mn1;
#pragma unroll
        for (int nt = 0; nt < 8; nt++) {
            o[nt][0] *= al0; o[nt][1] *= al0;
            o[nt][2] *= al1; o[nt][3] *= al1;
        }

        const float* vs = Vbuf[buf];
#pragma unroll
        for (int k8 = 0; k8 < 8; k8++) {
            const int kb = k8*8;
            float t0 = __shfl_sync(0xffffffffu, s[k8][0], srcA);
            float t1 = __shfl_sync(0xffffffffu, s[k8][1], srcA);
            float t2 = __shfl_sync(0xffffffffu, s[k8][2], srcA);
            float t3 = __shfl_sync(0xffffffffu, s[k8][3], srcA);
            float u0 = __shfl_sync(0xffffffffu, s[k8][0], srcB);
            float u1 = __shfl_sync(0xffffffffu, s[k8][1], srcB);
            float u2 = __shfl_sync(0xffffffffu, s[k8][2], srcB);
            float u3 = __shfl_sync(0xffffffffu, s[k8][3], srcB);
            unsigned ap0 = __float_as_uint(oddc ? t1 : t0);
            unsigned ap1 = __float_as_uint(oddc ? t3 : t2);
            unsigned ap2 = __float_as_uint(oddc ? u1 : u0);
            unsigned ap3 = __float_as_uint(oddc ? u3 : u2);
#pragma unroll
            for (int nt = 0; nt < 8; nt++) {
                unsigned b0 = __float_as_uint(vs[(kb + c4    )*V_STR + nt*8 + r8]);
                unsigned b1 = __float_as_uint(vs[(kb + c4 + 4)*V_STR + nt*8 + r8]);
                MMA_TF32(o[nt], ap0, ap1, ap2, ap3, b0, b1);
            }
        }
        __syncthreads();
    }

    const int qg0 = q0 + qrow + r8;
    float i0 = 1.f / l0, i1 = 1.f / l1;
#pragma unroll
    for (int nt = 0; nt < 8; nt++) {
        int col = h*DHd + nt*8 + c4*2;
        *(float2*)&out[(size_t)(b*Nseq + qg0    )*Dmod + col] =
            make_float2(round_tf32(o[nt][0]*i0), round_tf32(o[nt][1]*i0));
        *(float2*)&out[(size_t)(b*Nseq + qg0 + 8)*Dmod + col] =
            make_float2(round_tf32(o[nt][2]*i1), round_tf32(o[nt][3]*i1));
    }
}

// ---------------- launcher ----------------
extern "C" void kernel_launch(void* const* d_in, const int* in_sizes, int n_in,
                              void* d_out, int out_size)
{
    const float* x      = (const float*)d_in[0];
    const float* adj    = (const float*)d_in[1];
    const float* ln1_g  = (const float*)d_in[2];
    const float* ln1_b  = (const float*)d_in[3];
    const float* qkv_w  = (const float*)d_in[4];
    const float* qkv_b  = (const float*)d_in[5];
    const float* proj_w = (const float*)d_in[6];
    const float* proj_b = (const float*)d_in[7];
    const float* ln2_g  = (const float*)d_in[8];
    const float* ln2_b  = (const float*)d_in[9];
    const float* fc1_w  = (const float*)d_in[10];
    const float* fc1_b  = (const float*)d_in[11];
    const float* fc2_w  = (const float*)d_in[12];
    const float* fc2_b  = (const float*)d_in[13];
    float* out = (float*)d_out;

    float *h, *qkv, *attn, *x1, *h2, *act, *part;
    float *wqkvT, *wprojT, *wfc1T, *wfc2T;
    cudaGetSymbolAddress((void**)&h,     g_h);
    cudaGetSymbolAddress((void**)&qkv,   g_qkv);
    cudaGetSymbolAddress((void**)&attn,  g_attn);
    cudaGetSymbolAddress((void**)&x1,    g_x1);
    cudaGetSymbolAddress((void**)&h2,    g_h2);
    cudaGetSymbolAddress((void**)&act,   g_act);
    cudaGetSymbolAddress((void**)&part,  g_part);
    cudaGetSymbolAddress((void**)&wqkvT, g_wqkvT);
    cudaGetSymbolAddress((void**)&wprojT,g_wprojT);
    cudaGetSymbolAddress((void**)&wfc1T, g_wfc1T);
    cudaGetSymbolAddress((void**)&wfc2T, g_wfc2T);

    const int attn_smem = (128*QP_STR + 2*64*QP_STR + 2*64*V_STR)
                          * sizeof(float);   // 106496 B
    static cudaStream_t s2 = nullptr;
    static cudaEvent_t evA = nullptr, evQ = nullptr, evW = nullptr;
    if (!s2) {
        cudaFuncSetAttribute(gemm_tc<false,false,false,false>,
            cudaFuncAttributeMaxDynamicSharedMemorySize, GEMM_SMEM);
        cudaFuncSetAttribute(gemm_tc<true,false,true,false>,
            cudaFuncAttributeMaxDynamicSharedMemorySize, GEMM_SMEM);
        cudaFuncSetAttribute(gemm_tc<false,false,false,true>,
            cudaFuncAttributeMaxDynamicSharedMemorySize, GEMM_SMEM);
        cudaFuncSetAttribute(attn_tc,
            cudaFuncAttributeMaxDynamicSharedMemorySize, attn_smem);
        cudaStreamCreateWithFlags(&s2, cudaStreamNonBlocking);
        cudaEventCreateWithFlags(&evA, cudaEventDisableTiming);
        cudaEventCreateWithFlags(&evQ, cudaEventDisableTiming);
        cudaEventCreateWithFlags(&evW, cudaEventDisableTiming);
    }

    dim3 tb(32, 8);

    // ---- fork: side stream does all weight transposes ----
    cudaEventRecord(evA, 0);
    cudaStreamWaitEvent(s2, evA, 0);
    transpose32<<<dim3(3*Dmod/32, Dmod/32), tb, 0, s2>>>(qkv_w, wqkvT, Dmod, 3*Dmod);
    cudaEventRecord(evQ, s2);
    transpose32<<<dim3(Dmod/32, Dmod/32), tb, 0, s2>>>(proj_w, wprojT, Dmod, Dmod);
    transpose32<<<dim3(HID/32,  Dmod/32), tb, 0, s2>>>(fc1_w,  wfc1T, Dmod, HID);
    transpose32<<<dim3(Dmod/32, HID/32),  tb, 0, s2>>>(fc2_w,  wfc2T, HID, Dmod);
    cudaEventRecord(evW, s2);

    // ---- main stream: LN1 overlaps the qkv-weight transpose ----
    ln_warp<<<ROWS/8, 256>>>(x, ln1_g, ln1_b, h);
    cudaStreamWaitEvent(0, evQ, 0);
    // qkv = h @ qkv_w + qkv_b
    gemm_tc<false,false,false,false><<<dim3(18, 32, 1), 256, GEMM_SMEM>>>(
        h, wqkvT, qkv_b, nullptr, qkv, ROWS, Dmod, 3*Dmod, Dmod);
    // attention (remaining transposes hide under this)
    attn_tc<<<dim3(Nseq/128, Bsz*Hh), 256, attn_smem>>>(qkv, adj, attn);
    cudaStreamWaitEvent(0, evW, 0);
    // proj (split-K=3) then fused reduce+residual+LN2
    gemm_tc<false,false,false,true><<<dim3(6, 32, 3), 256, GEMM_SMEM>>>(
        attn, wprojT, proj_b, nullptr, part, ROWS, Dmod, Dmod, Dmod/3);
    reduce3_ln<<<ROWS/8, 256>>>(part, proj_b, x, x1, ln2_g, ln2_b, h2);
    // act = gelu(h2 @ fc1_w + fc1_b)
    gemm_tc<true,false,true,false><<<dim3(24, 32, 1), 256, GEMM_SMEM>>>(
        h2, wfc1T, fc1_b, nullptr, act, ROWS, Dmod, HID, Dmod);
    // out = x1 + act @ fc2_w + fc2_b  (split-K=3)
    gemm_tc<false,false,false,true><<<dim3(6, 32, 3), 256, GEMM_SMEM>>>(
        act, wfc2T, fc2_b, nullptr, part, ROWS, HID, Dmod, HID/3);
    reduce3_kernel<<<ROWS*Dmod/4/256, 256>>>(part, fc2_b, x1, out, Dmod);
}

// round 12
// speedup vs baseline: 3.8143x; 1.0001x over previous
#include <cuda_runtime.h>
#include <math.h>
#include <stdint.h>

#define Bsz  4
#define Nseq 1024
#define Dmod 768
#define Hh   12
#define DHd  64
#define HID  3072
#define ROWS (Bsz*Nseq)   // 4096

// ---- scratch (no cudaMalloc allowed) ----
__device__ float g_h   [ROWS*Dmod];
__device__ float g_qkv [ROWS*3*Dmod];
__device__ float g_attn[ROWS*Dmod];
__device__ float g_x1  [ROWS*Dmod];
__device__ float g_h2  [ROWS*Dmod];
__device__ float g_act [ROWS*HID];
__device__ float g_part[3*ROWS*Dmod];   // split-K partials
// transposed weights [N][K]
__device__ float g_wqkvT[3*Dmod*Dmod];
__device__ float g_wprojT[Dmod*Dmod];
__device__ float g_wfc1T[HID*Dmod];
__device__ float g_wfc2T[Dmod*HID];

__device__ __forceinline__ float round_tf32(float x) {
    unsigned r;
    asm("cvt.rna.tf32.f32 %0, %1;" : "=r"(r) : "f"(x));
    return __uint_as_float(r);
}

#define MMA_TF32(acc, a0,a1,a2,a3, b0,b1)                                   \
    asm volatile(                                                           \
        "mma.sync.aligned.m16n8k8.row.col.f32.tf32.tf32.f32 "               \
        "{%0,%1,%2,%3}, {%4,%5,%6,%7}, {%8,%9}, {%0,%1,%2,%3};"             \
        : "+f"(acc[0]), "+f"(acc[1]), "+f"(acc[2]), "+f"(acc[3])            \
        : "r"(a0), "r"(a1), "r"(a2), "r"(a3), "r"(b0), "r"(b1))

#define LDSM_X4(r, addr)                                                    \
    asm volatile("ldmatrix.sync.aligned.m8n8.x4.shared.b16 {%0,%1,%2,%3}, [%4];" \
        : "=r"((r)[0]), "=r"((r)[1]), "=r"((r)[2]), "=r"((r)[3]) : "r"(addr))

__device__ __forceinline__ void cp16(unsigned dst, const void* src) {
    asm volatile("cp.async.cg.shared.global [%0], [%1], 16;" :: "r"(dst), "l"(src));
}

// ---------------- weight transpose: [K][N] -> [N][K] ----------------
__global__ __launch_bounds__(256) void transpose32(
    const float* __restrict__ in, float* __restrict__ out, int K, int N)
{
    __shared__ float t[32][33];
    int n0 = blockIdx.x*32, k0 = blockIdx.y*32;
    int tx = threadIdx.x, ty = threadIdx.y;
#pragma unroll
    for (int i = 0; i < 4; i++)
        t[ty + i*8][tx] = in[(size_t)(k0 + ty + i*8)*N + n0 + tx];
    __syncthreads();
#pragma unroll
    for (int i = 0; i < 4; i++)
        out[(size_t)(n0 + ty + i*8)*K + k0 + tx] = t[tx][ty + i*8];
}

// ---------------- warp-per-row LayerNorm (tf32-rounded output) -------------
__global__ __launch_bounds__(256) void ln_warp(
    const float* __restrict__ x, const float* __restrict__ g,
    const float* __restrict__ b, float* __restrict__ out)
{
    const int warp = threadIdx.x >> 5, lane = threadIdx.x & 31;
    const int row  = blockIdx.x * 8 + warp;
    const float4* xr = (const float4*)(x + (size_t)row * Dmod);
    float4 v[6];
    float s = 0.f, s2 = 0.f;
#pragma unroll
    for (int i = 0; i < 6; i++) {
        v[i] = xr[lane + i*32];
        s  += v[i].x + v[i].y + v[i].z + v[i].w;
        s2 += v[i].x*v[i].x + v[i].y*v[i].y + v[i].z*v[i].z + v[i].w*v[i].w;
    }
#pragma unroll
    for (int off = 16; off; off >>= 1) {
        s  += __shfl_xor_sync(0xffffffffu, s,  off);
        s2 += __shfl_xor_sync(0xffffffffu, s2, off);
    }
    const float mu = s * (1.f/Dmod);
    const float rs = rsqrtf(s2 * (1.f/Dmod) - mu*mu + 1e-6f);
    float4* orow = (float4*)(out + (size_t)row * Dmod);
#pragma unroll
    for (int i = 0; i < 6; i++) {
        int c = lane + i*32;
        float4 gg = __ldg(&((const float4*)g)[c]);
        float4 bb = __ldg(&((const float4*)b)[c]);
        float4 o;
        o.x = round_tf32((v[i].x - mu)*rs*gg.x + bb.x);
        o.y = round_tf32((v[i].y - mu)*rs*gg.y + bb.y);
        o.z = round_tf32((v[i].z - mu)*rs*gg.z + bb.z);
        o.w = round_tf32((v[i].w - mu)*rs*gg.w + bb.w);
        orow[c] = o;
    }
}

// ------- fused split-K reduce + residual + LN: x1 and h2 in one pass -------
__global__ __launch_bounds__(256) void reduce3_ln(
    const float* __restrict__ p, const float* __restrict__ bias,
    const float* __restrict__ res, float* __restrict__ x1,
    const float* __restrict__ g, const float* __restrict__ bv,
    float* __restrict__ h2)
{
    const int warp = threadIdx.x >> 5, lane = threadIdx.x & 31;
    const int row  = blockIdx.x * 8 + warp;
    const size_t tot4 = (size_t)ROWS * Dmod / 4;
    const size_t base4 = (size_t)row * (Dmod/4);
    float4 v[6];
    float s = 0.f, s2 = 0.f;
#pragma unroll
    for (int i = 0; i < 6; i++) {
        int c = lane + i*32;
        size_t idx = base4 + c;
        float4 a  = ((const float4*)p)[idx];
        float4 b2 = ((const float4*)p)[idx + tot4];
        float4 c2 = ((const float4*)p)[idx + 2*tot4];
        float4 r  = ((const float4*)res)[idx];
        float4 bi = __ldg(&((const float4*)bias)[c]);
        float4 o;
        o.x = a.x + b2.x + c2.x + bi.x + r.x;
        o.y = a.y + b2.y + c2.y + bi.y + r.y;
        o.z = a.z + b2.z + c2.z + bi.z + r.z;
        o.w = a.w + b2.w + c2.w + bi.w + r.w;
        ((float4*)x1)[idx] = o;
        v[i] = o;
        s  += o.x + o.y + o.z + o.w;
        s2 += o.x*o.x + o.y*o.y + o.z*o.z + o.w*o.w;
    }
#pragma unroll
    for (int off = 16; off; off >>= 1) {
        s  += __shfl_xor_sync(0xffffffffu, s,  off);
        s2 += __shfl_xor_sync(0xffffffffu, s2, off);
    }
    const float mu = s * (1.f/Dmod);
    const float rs = rsqrtf(s2 * (1.f/Dmod) - mu*mu + 1e-6f);
#pragma unroll
    for (int i = 0; i < 6; i++) {
        int c = lane + i*32;
        float4 gg = __ldg(&((const float4*)g)[c]);
        float4 bb = __ldg(&((const float4*)bv)[c]);
        float4 o;
        o.x = round_tf32((v[i].x - mu)*rs*gg.x + bb.x);
        o.y = round_tf32((v[i].y - mu)*rs*gg.y + bb.y);
        o.z = round_tf32((v[i].z - mu)*rs*gg.z + bb.z);
        o.w = round_tf32((v[i].w - mu)*rs*gg.w + bb.w);
        ((float4*)h2)[base4 + c] = o;
    }
}

// ---------------- split-K reduction: out = p0+p1+p2 + bias + res ----------
__global__ __launch_bounds__(256) void reduce3_kernel(
    const float* __restrict__ p, const float* __restrict__ bias,
    const float* __restrict__ res, float* __restrict__ out, int Nc)
{
    int i = blockIdx.x * 256 + threadIdx.x;
    const size_t tot = (size_t)ROWS * Nc;
    float4 a = ((const float4*)p)[i];
    float4 b = ((const float4*)(p + tot))[i];
    float4 c = ((const float4*)(p + 2*tot))[i];
    float4 r = ((const float4*)res)[i];
    int col = (i*4) % Nc;
    const float4 bi = *(const float4*)&bias[col];
    float4 o;
    o.x = a.x + b.x + c.x + bi.x + r.x;
    o.y = a.y + b.y + c.y + bi.y + r.y;
    o.z = a.z + b.z + c.z + bi.z + r.z;
    o.w = a.w + b.w + c.w + bi.w + r.w;
    ((float4*)out)[i] = o;
}

// --------- tf32 GEMM 128x128, 3-stage smem + B-fragment reg prefetch -------
#define TS 36
#define STAGE_FLOATS (2*128*TS)
#define GEMM_SMEM (3*STAGE_FLOATS*4)

template<bool GELU, bool RES, bool ROUND, bool PARTIAL>
__global__ __launch_bounds__(256, 2) void gemm_tc(
    const float* __restrict__ A, const float* __restrict__ WT,
    const float* __restrict__ bias, const float* __restrict__ res,
    float* __restrict__ C, int M, int Kfull, int Nc, int Ks)
{
    extern __shared__ float sm[];

    const int tid  = threadIdx.x;
    const int lane = tid & 31;
    const int warp = tid >> 5;
    const int wm   = warp & 1;
    const int wn   = warp >> 1;
    const int bm   = blockIdx.y * 128;
    const int bn   = blockIdx.x * 128;
    const int z    = blockIdx.z;

    const float* Ab = A  + (size_t)z * Ks;
    const float* Wb = WT + (size_t)z * Ks;
    float* Cb = PARTIAL ? (C + (size_t)z * M * Nc) : C;

    float acc[4][4][4];
#pragma unroll
    for (int i = 0; i < 4; i++)
#pragma unroll
        for (int j = 0; j < 4; j++)
#pragma unroll
            for (int r = 0; r < 4; r++) acc[i][j][r] = 0.f;

    const int kTiles = Ks >> 5;

    auto load_stage = [&](int kt, int buf) {
        const int k0 = kt * 32;
        float* As = sm + buf*STAGE_FLOATS;
        float* Bs = As + 128*TS;
#pragma unroll
        for (int i = 0; i < 4; i++) {
            int idx = tid + i*256;
            int r = idx >> 3, kk = (idx & 7) * 4;
            cp16((unsigned)__cvta_generic_to_shared(&As[r*TS + kk]),
                 Ab + (size_t)(bm + r) * Kfull + k0 + kk);
        }
#pragma unroll
        for (int i = 0; i < 4; i++) {
            int idx = tid + i*256;
            int r = idx >> 3, kk = (idx & 7) * 4;
            cp16((unsigned)__cvta_generic_to_shared(&Bs[r*TS + kk]),
                 Wb + (size_t)(bn + r) * Kfull + k0 + kk);
        }
        asm volatile("cp.async.commit_group;");
    };

    load_stage(0, 0);
    load_stage(1, 1);

    const int r8 = lane >> 2;
    const int c4 = lane & 3;
    const int lrow = ((lane >> 3) & 1) * 8 + (lane & 7);
    const int lcol = (lane >> 4) * 4;
    const int kprow = ((lane >> 4) & 1) * 8 + (lane & 7);
    const int kpcol = ((lane >> 3) & 1) * 4;

    const uint32_t a_base = ((wm*64 + lrow)*TS + lcol) * 4u;
    const uint32_t b_base = ((wn*32 + kprow)*TS + kpcol) * 4u;

    for (int kt = 0; kt < kTiles; kt++) {
        if (kt + 1 < kTiles) asm volatile("cp.async.wait_group 1;");
        else                 asm volatile("cp.async.wait_group 0;");
        __syncthreads();
        if (kt + 2 < kTiles) load_stage(kt + 2, (kt + 2) % 3);

        const int buf = kt % 3;
        const uint32_t as_u32 = (uint32_t)__cvta_generic_to_shared(sm)
                                + buf*STAGE_FLOATS*4u;
        const uint32_t bs_u32 = as_u32 + 128*TS*4u;

        // B-fragment register double-buffer: preload k8=0, then prefetch k8+1
        unsigned bfr[2][2][4];
        LDSM_X4(bfr[0][0], bs_u32 + b_base);
        LDSM_X4(bfr[0][1], bs_u32 + b_base + 16u*TS*4u);
#pragma unroll
        for (int k8 = 0; k8 < 4; k8++) {
            const int cur = k8 & 1, nxt = cur ^ 1;
            unsigned af[4][4];
#pragma unroll
            for (int mt = 0; mt < 4; mt++)
                LDSM_X4(af[mt], as_u32 + a_base + mt*(16u*TS*4u) + k8*32u);
            if (k8 < 3) {
                LDSM_X4(bfr[nxt][0], bs_u32 + b_base + (k8+1)*32u);
                LDSM_X4(bfr[nxt][1], bs_u32 + b_base + 16u*TS*4u + (k8+1)*32u);
            }
#pragma unroll
            for (int mt = 0; mt < 4; mt++) {
                MMA_TF32(acc[mt][0], af[mt][0], af[mt][1], af[mt][2], af[mt][3],
                         bfr[cur][0][0], bfr[cur][0][1]);
                MMA_TF32(acc[mt][1], af[mt][0], af[mt][1], af[mt][2], af[mt][3],
                         bfr[cur][0][2], bfr[cur][0][3]);
                MMA_TF32(acc[mt][2], af[mt][0], af[mt][1], af[mt][2], af[mt][3],
                         bfr[cur][1][0], bfr[cur][1][1]);
                MMA_TF32(acc[mt][3], af[mt][0], af[mt][1], af[mt][2], af[mt][3],
                         bfr[cur][1][2], bfr[cur][1][3]);
            }
        }
    }

#pragma unroll
    for (int mt = 0; mt < 4; mt++) {
        int row0 = bm + wm*64 + mt*16 + r8;
#pragma unroll
        for (int nt = 0; nt < 4; nt++) {
            int col0 = bn + wn*32 + nt*8 + c4*2;
            float b0 = 0.f, b1 = 0.f;
            if (!PARTIAL) { b0 = __ldg(&bias[col0]); b1 = __ldg(&bias[col0 + 1]); }
#pragma unroll
            for (int half = 0; half < 2; half++) {
                int row = row0 + half*8;
                float v0 = acc[mt][nt][half*2 + 0] + b0;
                float v1 = acc[mt][nt][half*2 + 1] + b1;
                if (GELU) { v0 = v0 * normcdff(v0); v1 = v1 * normcdff(v1); }
                if (RES) {
                    const float2 rr = *(const float2*)&res[(size_t)row*Nc + col0];
                    v0 += rr.x; v1 += rr.y;
                }
                if (ROUND) { v0 = round_tf32(v0); v1 = round_tf32(v1); }
                *(float2*)&Cb[(size_t)row*Nc + col0] = make_float2(v0, v1);
            }
        }
    }
}

// ------- Tensor-core flash attention: cp.async double-buffer, no P smem ----
#define QP_STR 68
#define V_STR  72

__global__ __launch_bounds__(256) void attn_tc(
    const float* __restrict__ qkv, const float* __restrict__ adj,
    float* __restrict__ out)
{
    extern __shared__ float sma[];
    float* Qs  = sma;
    float* Kb0 = Qs + 128*QP_STR;
    float* Vb0 = Kb0 + 2*64*QP_STR;

    const int tid  = threadIdx.x;
    const int lane = tid & 31;
    const int warp = tid >> 5;
    const int r8   = lane >> 2;
    const int c4   = lane & 3;
    const int bh   = blockIdx.y;
    const int b    = bh / Hh, h = bh % Hh;
    const int q0   = blockIdx.x * 128;
    const int qrow = (warp >> 2)*64 + (warp & 3)*16;
    const float scale = 0.125f;

    const int lrow  = ((lane >> 3) & 1) * 8 + (lane & 7);
    const int lcol  = (lane >> 4) * 4;
    const int kprow = ((lane >> 4) & 1) * 8 + (lane & 7);
    const int kpcol = ((lane >> 3) & 1) * 4;

    const uint32_t qs_u32 = (uint32_t)__cvta_generic_to_shared(Qs);
    uint32_t ks_u32[2] = {
        (uint32_t)__cvta_generic_to_shared(Kb0),
        (uint32_t)__cvta_generic_to_shared(Kb0 + 64*QP_STR) };
    float* Vbuf[2] = { Vb0, Vb0 + 64*V_STR };
    const uint32_t q_off  = ((qrow + lrow)*QP_STR + lcol) * 4u;
    const uint32_t kp_off = (kprow*QP_STR + kpcol) * 4u;

#pragma unroll
    for (int it = 0; it < 32; it++) {
        int idx = tid + it*256;
        int r = idx >> 6, d = idx & 63;
        Qs[r*QP_STR + d] = qkv[(size_t)(b*Nseq + q0 + r)*(3*Dmod) + h*DHd + d];
    }

    auto load_kv = [&](int kt, int buf) {
        const int k0 = kt*64;
        float* kd = Kb0 + buf*64*QP_STR;
        float* vd = Vbuf[buf];
#pragma unroll
        for (int i = 0; i < 4; i++) {
            int idx = tid + i*256;
            int r = idx >> 4, d4 = (idx & 15) * 4;
            size_t base = (size_t)(b*Nseq + k0 + r)*(3*Dmod) + h*DHd + d4;
            cp16((unsigned)__cvta_generic_to_shared(&kd[r*QP_STR + d4]),
                 qkv + base + Dmod);
            cp16((unsigned)__cvta_generic_to_shared(&vd[r*V_STR + d4]),
                 qkv + base + 2*Dmod);
        }
        asm volatile("cp.async.commit_group;");
    };

    load_kv(0, 0);

    float m0 = -1e30f, m1 = -1e30f, l0 = 0.f, l1 = 0.f;
    float o[8][4];
#pragma unroll
    for (int nt = 0; nt < 8; nt++)
#pragma unroll
        for (int r = 0; r < 4; r++) o[nt][r] = 0.f;

    const int srcA = (lane & ~3) | (c4 >> 1);
    const int srcB = srcA + 2;
    const bool oddc = c4 & 1;

    for (int kt = 0; kt < Nseq/64; kt++) {
        const int buf = kt & 1;
        asm volatile("cp.async.wait_group 0;");
        __syncthreads();
        if (kt + 1 < Nseq/64) load_kv(kt + 1, buf ^ 1);

        float s[8][4];
#pragma unroll
        for (int nt = 0; nt < 8; nt++)
#pragma unroll
            for (int r = 0; r < 4; r++) s[nt][r] = 0.f;

#pragma unroll
        for (int k8 = 0; k8 < 8; k8++) {
            unsigned aq[4];
            LDSM_X4(aq, qs_u32 + q_off + k8*32u);
#pragma unroll
            for (int ntp = 0; ntp < 4; ntp++) {
                unsigned kb4[4];
                LDSM_X4(kb4, ks_u32[buf] + kp_off + ntp*(16u*QP_STR*4u) + k8*32u);
                MMA_TF32(s[2*ntp    ], aq[0], aq[1], aq[2], aq[3], kb4[0], kb4[1]);
                MMA_TF32(s[2*ntp + 1], aq[0], aq[1], aq[2], aq[3], kb4[2], kb4[3]);
            }
        }

        const int k0 = kt*64;
        const int qg0 = q0 + qrow + r8;
#pragma unroll
        for (int nt = 0; nt < 8; nt++) {
            int col = k0 + nt*8 + c4*2;
            float2 ad0 = *(const float2*)&adj[(size_t) qg0     *Nseq + col];
            float2 ad1 = *(const float2*)&adj[(size_t)(qg0 + 8)*Nseq + col];
            s[nt][0] = s[nt][0]*scale + ad0.x;
            s[nt][1] = s[nt][1]*scale + ad0.y;
            s[nt][2] = s[nt][2]*scale + ad1.x;
            s[nt][3] = s[nt][3]*scale + ad1.y;
        }

        float mx0 = -1e30f, mx1 = -1e30f;
#pragma unroll
        for (int nt = 0; nt < 8; nt++) {
            mx0 = fmaxf(mx0, fmaxf(s[nt][0], s[nt][1]));
            mx1 = fmaxf(mx1, fmaxf(s[nt][2], s[nt][3]));
        }
        mx0 = fmaxf(mx0, __shfl_xor_sync(0xffffffffu, mx0, 1));
        mx0 = fmaxf(mx0, __shfl_xor_sync(0xffffffffu, mx0, 2));
        mx1 = fmaxf(mx1, __shfl_xor_sync(0xffffffffu, mx1, 1));
        mx1 = fmaxf(mx1, __shfl_xor_sync(0xffffffffu, mx1, 2));
        float mn0 = fmaxf(m0, mx0), mn1 = fmaxf(m1, mx1);
        float al0 = __expf(m0 - mn0), al1 = __expf(m1 - mn1);
        float rs0 = 0.f, rs1 = 0.f;
#pragma unroll
        for (int nt = 0; nt < 8; nt++) {
            s[nt][0] = __expf(s[nt][0] - mn0);
            s[nt][1] = __expf(s[nt][1] - mn0);
            s[nt][2] = __expf(s[nt][2] - mn1);
            s[nt][3] = __expf(s[nt][3] - mn1);
            rs0 += s[nt][0] + s[nt][1];
            rs1 += s[nt][2] + s[nt][3];
        }
        rs0 += __shfl_xor_sync(0xffffffffu, rs0, 1);
        rs0 += __shfl_xor_sync(0xffffffffu, rs0, 2);
        rs1 += __shfl_xor_sync(0xffffffffu, rs1, 1);
        rs1 += __shfl_xor_sync(0xffffffffu, rs1, 2);
        l0 = l0*al0 + rs0;  l1 = l1*al1 + rs1;
        m0 = mn0;           m1 = mn1;
#pragma unroll
        for (int nt = 0; nt < 8; nt++) {
            o[nt][0] *= al0; o[nt][1] *= al0;
            o[nt][2] *= al1; o[nt][3] *= al1;
        }

        const float* vs = Vbuf[buf];
#pragma unroll
        for (int k8 = 0; k8 < 8; k8++) {
            const int kb = k8*8;
            float t0 = __shfl_sync(0xffffffffu, s[k8][0], srcA);
            float t1 = __shfl_sync(0xffffffffu, s[k8][1], srcA);
            float t2 = __shfl_sync(0xffffffffu, s[k8][2], srcA);
            float t3 = __shfl_sync(0xffffffffu, s[k8][3], srcA);
            float u0 = __shfl_sync(0xffffffffu, s[k8][0], srcB);
            float u1 = __shfl_sync(0xffffffffu, s[k8][1], srcB);
            float u2 = __shfl_sync(0xffffffffu, s[k8][2], srcB);
            float u3 = __shfl_sync(0xffffffffu, s[k8][3], srcB);
            unsigned ap0 = __float_as_uint(oddc ? t1 : t0);
            unsigned ap1 = __float_as_uint(oddc ? t3 : t2);
            unsigned ap2 = __float_as_uint(oddc ? u1 : u0);
            unsigned ap3 = __float_as_uint(oddc ? u3 : u2);
#pragma unroll
            for (int nt = 0; nt < 8; nt++) {
                unsigned b0 = __float_as_uint(vs[(kb + c4    )*V_STR + nt*8 + r8]);
                unsigned b1 = __float_as_uint(vs[(kb + c4 + 4)*V_STR + nt*8 + r8]);
                MMA_TF32(o[nt], ap0, ap1, ap2, ap3, b0, b1);
            }
        }
        __syncthreads();
    }

    const int qg0 = q0 + qrow + r8;
    float i0 = 1.f / l0, i1 = 1.f / l1;
#pragma unroll
    for (int nt = 0; nt < 8; nt++) {
        int col = h*DHd + nt*8 + c4*2;
        *(float2*)&out[(size_t)(b*Nseq + qg0    )*Dmod + col] =
            make_float2(round_tf32(o[nt][0]*i0), round_tf32(o[nt][1]*i0));
        *(float2*)&out[(size_t)(b*Nseq + qg0 + 8)*Dmod + col] =
            make_float2(round_tf32(o[nt][2]*i1), round_tf32(o[nt][3]*i1));
    }
}

// ---------------- launcher ----------------
extern "C" void kernel_launch(void* const* d_in, const int* in_sizes, int n_in,
                              void* d_out, int out_size)
{
    const float* x      = (const float*)d_in[0];
    const float* adj    = (const float*)d_in[1];
    const float* ln1_g  = (const float*)d_in[2];
    const float* ln1_b  = (const float*)d_in[3];
    const float* qkv_w  = (const float*)d_in[4];
    const float* qkv_b  = (const float*)d_in[5];
    const float* proj_w = (const float*)d_in[6];
    const float* proj_b = (const float*)d_in[7];
    const float* ln2_g  = (const float*)d_in[8];
    const float* ln2_b  = (const float*)d_in[9];
    const float* fc1_w  = (const float*)d_in[10];
    const float* fc1_b  = (const float*)d_in[11];
    const float* fc2_w  = (const float*)d_in[12];
    const float* fc2_b  = (const float*)d_in[13];
    float* out = (float*)d_out;

    float *h, *qkv, *attn, *x1, *h2, *act, *part;
    float *wqkvT, *wprojT, *wfc1T, *wfc2T;
    cudaGetSymbolAddress((void**)&h,     g_h);
    cudaGetSymbolAddress((void**)&qkv,   g_qkv);
    cudaGetSymbolAddress((void**)&attn,  g_attn);
    cudaGetSymbolAddress((void**)&x1,    g_x1);
    cudaGetSymbolAddress((void**)&h2,    g_h2);
    cudaGetSymbolAddress((void**)&act,   g_act);
    cudaGetSymbolAddress((void**)&part,  g_part);
    cudaGetSymbolAddress((void**)&wqkvT, g_wqkvT);
    cudaGetSymbolAddress((void**)&wprojT,g_wprojT);
    cudaGetSymbolAddress((void**)&wfc1T, g_wfc1T);
    cudaGetSymbolAddress((void**)&wfc2T, g_wfc2T);

    const int attn_smem = (128*QP_STR + 2*64*QP_STR + 2*64*V_STR)
                          * sizeof(float);   // 106496 B
    static cudaStream_t s2 = nullptr;
    static cudaEvent_t evA = nullptr, evQ = nullptr, evW = nullptr;
    if (!s2) {
        cudaFuncSetAttribute(gemm_tc<false,false,false,false>,
            cudaFuncAttributeMaxDynamicSharedMemorySize, GEMM_SMEM);
        cudaFuncSetAttribute(gemm_tc<true,false,true,false>,
            cudaFuncAttributeMaxDynamicSharedMemorySize, GEMM_SMEM);
        cudaFuncSetAttribute(gemm_tc<false,false,false,true>,
            cudaFuncAttributeMaxDynamicSharedMemorySize, GEMM_SMEM);
        cudaFuncSetAttribute(attn_tc,
            cudaFuncAttributeMaxDynamicSharedMemorySize, attn_smem);
        cudaStreamCreateWithFlags(&s2, cudaStreamNonBlocking);
        cudaEventCreateWithFlags(&evA, cudaEventDisableTiming);
        cudaEventCreateWithFlags(&evQ, cudaEventDisableTiming);
        cudaEventCreateWithFlags(&evW, cudaEventDisableTiming);
    }

    dim3 tb(32, 8);

    // ---- fork: side stream does all weight transposes ----
    cudaEventRecord(evA, 0);
    cudaStreamWaitEvent(s2, evA, 0);
    transpose32<<<dim3(3*Dmod/32, Dmod/32), tb, 0, s2>>>(qkv_w, wqkvT, Dmod, 3*Dmod);
    cudaEventRecord(evQ, s2);
    transpose32<<<dim3(Dmod/32, Dmod/32), tb, 0, s2>>>(proj_w, wprojT, Dmod, Dmod);
    transpose32<<<dim3(HID/32,  Dmod/32), tb, 0, s2>>>(fc1_w,  wfc1T, Dmod, HID);
    transpose32<<<dim3(Dmod/32, HID/32),  tb, 0, s2>>>(fc2_w,  wfc2T, HID, Dmod);
    cudaEventRecord(evW, s2);

    // ---- main stream: LN1 overlaps the qkv-weight transpose ----
    ln_warp<<<ROWS/8, 256>>>(x, ln1_g, ln1_b, h);
    cudaStreamWaitEvent(0, evQ, 0);
    // qkv = h @ qkv_w + qkv_b
    gemm_tc<false,false,false,false><<<dim3(18, 32, 1), 256, GEMM_SMEM>>>(
        h, wqkvT, qkv_b, nullptr, qkv, ROWS, Dmod, 3*Dmod, Dmod);
    // attention (remaining transposes hide under this)
    attn_tc<<<dim3(Nseq/128, Bsz*Hh), 256, attn_smem>>>(qkv, adj, attn);
    cudaStreamWaitEvent(0, evW, 0);
    // proj (split-K=3) then fused reduce+residual+LN2
    gemm_tc<false,false,false,true><<<dim3(6, 32, 3), 256, GEMM_SMEM>>>(
        attn, wprojT, proj_b, nullptr, part, ROWS, Dmod, Dmod, Dmod/3);
    reduce3_ln<<<ROWS/8, 256>>>(part, proj_b, x, x1, ln2_g, ln2_b, h2);
    // act = gelu(h2 @ fc1_w + fc1_b)
    gemm_tc<true,false,true,false><<<dim3(24, 32, 1), 256, GEMM_SMEM>>>(
        h2, wfc1T, fc1_b, nullptr, act, ROWS, Dmod, HID, Dmod);
    // out = x1 + act @ fc2_w + fc2_b  (split-K=3)
    gemm_tc<false,false,false,true><<<dim3(6, 32, 3), 256, GEMM_SMEM>>>(
        act, wfc2T, fc2_b, nullptr, part, ROWS, HID, Dmod, HID/3);
    reduce3_kernel<<<ROWS*Dmod/4/256, 256>>>(part, fc2_b, x1, out, Dmod);
}